// round 14
// baseline (speedup 1.0000x reference)
#include <cuda_runtime.h>
#include <cuda_bf16.h>
#include <math.h>
#include <stdint.h>

#define BATCH 4
#define CIN 256
#define COUT 128
#define HH 64
#define WW 64
#define HW 4096

typedef unsigned long long ull;

// ---------------- scratch (static device globals; no allocs) ----------------
__device__ float g_xa[BATCH * COUT * HW];
__device__ float g_S[(size_t)BATCH * HW * HW];
__device__ float g_avg[BATCH * CIN];
__device__ float g_mx[BATCH * CIN];
__device__ float g_s[BATCH * CIN];
__device__ float g_bp[BATCH * CIN];
// bf16 split operands
__device__ __nv_bfloat16 g_xth[BATCH * HW * CIN];   // xcT hi [b][hw][c]
__device__ __nv_bfloat16 g_xtl[BATCH * HW * CIN];
__device__ __nv_bfloat16 g_xTh[BATCH * HW * CIN];   // raw xT hi [b][hw][c]
__device__ __nv_bfloat16 g_xTl[BATCH * HW * CIN];
__device__ __nv_bfloat16 g_cth[(size_t)BATCH * HW * 5 * CIN];
__device__ __nv_bfloat16 g_ctl[(size_t)BATCH * HW * 5 * CIN];
__device__ __nv_bfloat16 g_pth[BATCH * HW * CIN];   // projT hi [b][hw][c]
__device__ __nv_bfloat16 g_ptl[BATCH * HW * CIN];
__device__ __nv_bfloat16 g_w3h[3 * 9 * CIN * CIN];
__device__ __nv_bfloat16 g_w3l[3 * 9 * CIN * CIN];
__device__ __nv_bfloat16 g_a0h[CIN * CIN];
__device__ __nv_bfloat16 g_a0l[CIN * CIN];
__device__ __nv_bfloat16 g_pjh[CIN * 5 * CIN];
__device__ __nv_bfloat16 g_pjl[CIN * 5 * CIN];
__device__ __nv_bfloat16 g_c2h[CIN * COUT];
__device__ __nv_bfloat16 g_c2l[CIN * COUT];
__device__ __nv_bfloat16 g_c1h[COUT * CIN];
__device__ __nv_bfloat16 g_c1l[COUT * CIN];
// attention operands
__device__ __nv_bfloat16 g_x1th[BATCH * HW * COUT];
__device__ __nv_bfloat16 g_x1tl[BATCH * HW * COUT];
__device__ __nv_bfloat16 g_xath[BATCH * HW * COUT];
__device__ __nv_bfloat16 g_xatl[BATCH * HW * COUT];
__device__ __nv_bfloat16 g_x1h[BATCH * COUT * HW];
__device__ __nv_bfloat16 g_x1l[BATCH * COUT * HW];
__device__ __nv_bfloat16 g_Ah[(size_t)BATCH * HW * HW];
__device__ __nv_bfloat16 g_Al[(size_t)BATCH * HW * HW];
__device__ __nv_bfloat16 g_oth[BATCH * HW * COUT];
__device__ __nv_bfloat16 g_otl[BATCH * HW * COUT];

__device__ __forceinline__ float gelu_f(float x) {
    return 0.5f * x * (1.0f + erff(x * 0.70710678118654752440f));
}
__device__ __forceinline__ void splitf(float v, __nv_bfloat16& h, __nv_bfloat16& l) {
    h = __float2bfloat16(v);
    l = __float2bfloat16(v - __bfloat162float(h));
}

// ---------------- HMMA m16n8k16 bf16 ----------------
__device__ __forceinline__ void mma16816(float* d, const uint32_t* a, const uint32_t* b) {
    asm volatile(
        "mma.sync.aligned.m16n8k16.row.col.f32.bf16.bf16.f32 "
        "{%0,%1,%2,%3}, {%4,%5,%6,%7}, {%8,%9}, {%0,%1,%2,%3};"
        : "+f"(d[0]), "+f"(d[1]), "+f"(d[2]), "+f"(d[3])
        : "r"(a[0]), "r"(a[1]), "r"(a[2]), "r"(a[3]), "r"(b[0]), "r"(b[1]));
}
__device__ __forceinline__ void ldsm_x4(uint32_t* r, uint32_t addr) {
    asm volatile("ldmatrix.sync.aligned.m8n8.x4.shared.b16 {%0,%1,%2,%3}, [%4];"
                 : "=r"(r[0]), "=r"(r[1]), "=r"(r[2]), "=r"(r[3]) : "r"(addr));
}
__device__ __forceinline__ void ldsm_x4t(uint32_t* r, uint32_t addr) {
    asm volatile("ldmatrix.sync.aligned.m8n8.x4.trans.shared.b16 {%0,%1,%2,%3}, [%4];"
                 : "=r"(r[0]), "=r"(r[1]), "=r"(r[2]), "=r"(r[3]) : "r"(addr));
}

// ---------------- cp.async helpers ----------------
__device__ __forceinline__ void cp16(uint32_t d, const void* s, int ssz) {
    asm volatile("cp.async.ca.shared.global [%0], [%1], 16, %2;"
                 :: "r"(d), "l"(s), "r"(ssz) : "memory");
}
#define CP_COMMIT() asm volatile("cp.async.commit_group;" ::: "memory")
#define CP_WAIT1()  asm volatile("cp.async.wait_group 1;" ::: "memory")
#define CP_WAIT0()  asm volatile("cp.async.wait_group 0;" ::: "memory")

// ---------------- prep: weight splits + per-(b,c) stats ----------------
__global__ void k_prep(const float* __restrict__ w1, const float* __restrict__ w2,
                       const float* __restrict__ w3, const float* __restrict__ a0,
                       const float* __restrict__ pj, const float* __restrict__ c2,
                       const float* __restrict__ c1, const float* __restrict__ x) {
    if (blockIdx.x < 2560) {
        int e = blockIdx.x * 256 + threadIdx.x;
        if (e < 196608) {
            const float* srcs[3] = { w1, w2, w3 };
            int conv = e >> 16, mc = e & 65535, m = mc >> 8, c = mc & 255;
            const float* src = srcs[conv] + (size_t)m * 2304 + (size_t)c * 9;
            size_t dbase = (size_t)conv * 9 * 65536 + (size_t)m * 256 + c;
#pragma unroll
            for (int tap = 0; tap < 9; tap++) {
                __nv_bfloat16 h, l; splitf(src[tap], h, l);
                g_w3h[dbase + (size_t)tap * 65536] = h;
                g_w3l[dbase + (size_t)tap * 65536] = l;
            }
        } else if (e < 262144) {
            int i = e - 196608;
            __nv_bfloat16 h, l; splitf(a0[i], h, l);
            g_a0h[i] = h; g_a0l[i] = l;
        } else if (e < 589824) {
            int i = e - 262144;
            __nv_bfloat16 h, l; splitf(pj[i], h, l);
            g_pjh[i] = h; g_pjl[i] = l;
        } else if (e < 622592) {
            int i = e - 589824;
            __nv_bfloat16 h, l; splitf(c2[i], h, l);
            g_c2h[i] = h; g_c2l[i] = l;
        } else if (e < 655360) {
            int i = e - 622592;
            __nv_bfloat16 h, l; splitf(c1[i], h, l);
            g_c1h[i] = h; g_c1l[i] = l;
        }
    } else {
        int bc = blockIdx.x - 2560;
        const float* p = x + (size_t)bc * HW;
        int t = threadIdx.x;
        float s = 0.f, m = -1e30f;
        for (int i = t; i < HW; i += 256) { float v = p[i]; s += v; m = fmaxf(m, v); }
        __shared__ float ss[256], sm[256];
        ss[t] = s; sm[t] = m; __syncthreads();
        for (int o = 128; o > 0; o >>= 1) {
            if (t < o) { ss[t] += ss[t + o]; sm[t] = fmaxf(sm[t], sm[t + o]); }
            __syncthreads();
        }
        if (t == 0) { g_avg[bc] = ss[0] * (1.f / HW); g_mx[bc] = sm[0]; }
    }
}

// ---------------- channel weighting MLP + global-pool ASPP branch ----------------
__global__ void k_cw(const float* __restrict__ w1, const float* __restrict__ bb1,
                     const float* __restrict__ lg, const float* __restrict__ lb,
                     const float* __restrict__ w2, const float* __restrict__ bb2,
                     const float* __restrict__ apw, const float* __restrict__ apg,
                     const float* __restrict__ apb) {
    int b = blockIdx.x, t = threadIdx.x;
    __shared__ float o[CIN];
    __shared__ float h[COUT];
    __shared__ float red[256];
    __shared__ float gp[CIN];
    float avg = g_avg[b * CIN + t], mx = g_mx[b * CIN + t];
    o[t] = fabsf(avg - mx) * avg;
    __syncthreads();
    float hv = 0.f;
    if (t < COUT) {
        hv = bb1[t];
        const float* wr = w1 + t * CIN;
        for (int i = 0; i < CIN; i++) hv = fmaf(o[i], wr[i], hv);
    }
    red[t] = (t < COUT) ? hv : 0.f; __syncthreads();
    for (int s = 128; s > 0; s >>= 1) { if (t < s) red[t] += red[t + s]; __syncthreads(); }
    float mu = red[0] * (1.f / COUT); __syncthreads();
    float dv = (t < COUT) ? (hv - mu) : 0.f;
    red[t] = dv * dv; __syncthreads();
    for (int s = 128; s > 0; s >>= 1) { if (t < s) red[t] += red[t + s]; __syncthreads(); }
    float var = red[0] * (1.f / COUT); __syncthreads();
    if (t < COUT) h[t] = lg[t] * ((hv - mu) * rsqrtf(var + 1e-5f)) + lb[t];
    __syncthreads();
    float sv = bb2[t];
    const float* wr2 = w2 + t * COUT;
    for (int j = 0; j < COUT; j++) sv = fmaf(h[j], wr2[j], sv);
    float sig = 1.f / (1.f + expf(-sv));
    g_s[b * CIN + t] = sig;
    gp[t] = (1.f + sig) * avg;
    __syncthreads();
    float v = 0.f;
    const float* ar = apw + t * CIN;
    for (int i = 0; i < CIN; i++) v = fmaf(ar[i], gp[i], v);
    red[t] = v; __syncthreads();
    for (int s = 128; s > 0; s >>= 1) { if (t < s) red[t] += red[t + s]; __syncthreads(); }
    float mu2 = red[0] * (1.f / CIN); __syncthreads();
    float d2 = v - mu2; red[t] = d2 * d2; __syncthreads();
    for (int s = 128; s > 0; s >>= 1) { if (t < s) red[t] += red[t + s]; __syncthreads(); }
    float var2 = red[0] * (1.f / CIN); __syncthreads();
    float z = apg[t] * ((v - mu2) * rsqrtf(var2 + 1e-6f)) + apb[t];
    g_bp[b * CIN + t] = gelu_f(z);
}

// ---------------- xT / xcT split ----------------
__global__ void k_xcsplit(const float* __restrict__ x) {
    __shared__ float tile[32][33];
    int b = blockIdx.z, c0 = blockIdx.y * 32, h0 = blockIdx.x * 32;
    int t = threadIdx.x;
    const float* xb = x + ((size_t)b * CIN + c0) * HW + h0;
#pragma unroll
    for (int i = 0; i < 4; i++) {
        int r = (t >> 5) + 8 * i;
        tile[r][t & 31] = xb[(size_t)r * HW + (t & 31)];
    }
    __syncthreads();
#pragma unroll
    for (int i = 0; i < 4; i++) {
        int hr = (t >> 5) + 8 * i, cc = t & 31;
        float vr = tile[cc][hr];
        size_t idx = ((size_t)b * HW + h0 + hr) * CIN + c0 + cc;
        __nv_bfloat16 h, l;
        splitf(vr, h, l);
        g_xTh[idx] = h; g_xTl[idx] = l;
        float v = vr * (1.f + g_s[b * CIN + c0 + cc]);
        splitf(v, h, l);
        g_xth[idx] = h; g_xtl[idx] = l;
    }
}

// ---------------- bp broadcast into catT channels [1024,1280) ----------------
__global__ void k_bp_cat() {
    int b = blockIdx.y, h0 = blockIdx.x * 32;
    int c = threadIdx.x;
    __nv_bfloat16 h, l; splitf(g_bp[b * CIN + c], h, l);
    for (int r = 0; r < 32; r++) {
        size_t idx = ((size_t)b * HW + h0 + r) * 1280 + 1024 + c;
        g_cth[idx] = h; g_ctl[idx] = l;
    }
}

struct AsppArgs {
    const __nv_bfloat16* wh[4];
    const __nv_bfloat16* wl[4];
    const float* g[4];
    const float* bt[4];
    int dil[4];
    int coff[4];
};

// ---------------- merged ASPP HMMA kernel v2: 256x64 tile, 256 thr, 2 CTA/SM -------
// Double-buffered; WAR-safe via second __syncthreads before refilling the
// just-consumed buffer (the second barrier's cost is hidden by 2 CTAs/SM).
__global__ void __launch_bounds__(256, 2) k_aspp(
    AsppArgs A_, const __nv_bfloat16* __restrict__ Ihi, const __nv_bfloat16* __restrict__ Ilo,
    __nv_bfloat16* __restrict__ cth, __nv_bfloat16* __restrict__ ctl) {
    extern __shared__ __align__(16) char dsm[];
    __shared__ int s_tapn, s_tp[9], s_dy[9], s_dx[9];
    __shared__ float sgam[256], sbet[256], smean[64], srstd[64];
    __shared__ float red4[4][64];

    const int br = blockIdx.z, b = blockIdx.y, y = blockIdx.x;  // y = image row
    const int t = threadIdx.x, wid = t >> 5, lane = t & 31;
    const int mw = wid >> 1, nw = wid & 1;
    const uint32_t sbase = (uint32_t)__cvta_generic_to_shared(dsm);
    const __nv_bfloat16* Whi = A_.wh[br];
    const __nv_bfloat16* Wlo = A_.wl[br];
    const int dil = A_.dil[br], coff = A_.coff[br];

    if (t == 0) {
        if (dil == 0) {
            s_tapn = 1; s_tp[0] = 0; s_dy[0] = 0; s_dx[0] = 0;
        } else {
            int n = 0;
            for (int tap = 0; tap < 9; tap++) {
                int dy = (tap / 3 - 1) * dil;
                if ((unsigned)(y + dy) < 64u) {
                    s_tp[n] = tap; s_dy[n] = dy; s_dx[n] = (tap % 3 - 1) * dil; n++;
                }
            }
            s_tapn = n;
        }
    }
    sgam[t] = A_.g[br][t]; sbet[t] = A_.bt[br][t];
    __syncthreads();

    const int T = s_tapn * 8;
    const __nv_bfloat16* Ib_hi = Ihi + (size_t)b * HW * CIN;
    const __nv_bfloat16* Ib_lo = Ilo + (size_t)b * HW * CIN;

    float acc[4][4][4];
#pragma unroll
    for (int i = 0; i < 4; i++)
#pragma unroll
        for (int j = 0; j < 4; j++)
#pragma unroll
            for (int r = 0; r < 4; r++) acc[i][j][r] = 0.f;

    auto loadG = [&](int it, int buf) {
        int tap_i = it >> 3;
        int kc = (it & 7) * 32;
        uint32_t base = sbase + buf * 51200;
        int grow = s_tp[tap_i] * 256 + t;
        const __nv_bfloat16* ah = Whi + (size_t)grow * CIN + kc;
        const __nv_bfloat16* al = Wlo + (size_t)grow * CIN + kc;
        uint32_t da = base + t * 80;
#pragma unroll
        for (int q = 0; q < 4; q++) {
            cp16(da + q * 16, ah + q * 8, 16);
            cp16(da + 20480 + q * 16, al + q * 8, 16);
        }
        int n = t >> 2, q = t & 3;
        int hw; int ok = 16;
        int xx = n + s_dx[tap_i];
        int yy = y + s_dy[tap_i];
        if ((unsigned)xx < 64u) hw = yy * 64 + xx;
        else { hw = 0; ok = (dil == 0) ? 16 : 0; }
        if (dil == 0) hw = y * 64 + n;
        uint32_t db = base + 40960 + n * 80 + q * 16;
        cp16(db, Ib_hi + (size_t)hw * CIN + kc + q * 8, ok);
        cp16(db + 5120, Ib_lo + (size_t)hw * CIN + kc + q * 8, ok);
        CP_COMMIT();
    };

    loadG(0, 0);
    if (T > 1) loadG(1, 1);

    const int lr = lane >> 2, lc = 2 * (lane & 3);
    const uint32_t a_loff = (uint32_t)(((lane & 7) + ((lane >> 3) & 1) * 8) * 80
                                       + (lane >> 4) * 16);
    const uint32_t b_loff4 = (uint32_t)(((lane & 7) + ((lane >> 4) & 1) * 8) * 80
                                        + ((lane >> 3) & 1) * 16);
    const uint32_t a_wbase = (uint32_t)(mw * 64 * 80) + a_loff;
    const uint32_t b_wbase = 40960u + (uint32_t)(nw * 32 * 80) + b_loff4;

    int cur = 0;
    for (int it = 0; it < T; ++it) {
        if (it + 1 < T) CP_WAIT1(); else CP_WAIT0();
        __syncthreads();
        uint32_t sb = sbase + cur * 51200;
#pragma unroll
        for (int ks = 0; ks < 2; ks++) {
            uint32_t kboff = ks * 32;
            uint32_t bh[4][2], bl[4][2];
#pragma unroll
            for (int jp = 0; jp < 2; jp++) {
                uint32_t ba = sb + b_wbase + jp * (16 * 80) + kboff;
                uint32_t r[4];
                ldsm_x4(r, ba);
                bh[2 * jp][0] = r[0]; bh[2 * jp][1] = r[1];
                bh[2 * jp + 1][0] = r[2]; bh[2 * jp + 1][1] = r[3];
                ldsm_x4(r, ba + 5120);
                bl[2 * jp][0] = r[0]; bl[2 * jp][1] = r[1];
                bl[2 * jp + 1][0] = r[2]; bl[2 * jp + 1][1] = r[3];
            }
#pragma unroll
            for (int i = 0; i < 4; i++) {
                uint32_t aa = sb + a_wbase + i * (16 * 80) + kboff;
                uint32_t ah[4], al[4];
                ldsm_x4(ah, aa);
                ldsm_x4(al, aa + 20480);
#pragma unroll
                for (int j = 0; j < 4; j++) {
                    mma16816(acc[i][j], ah, bh[j]);
                    mma16816(acc[i][j], ah, bl[j]);
                    mma16816(acc[i][j], al, bh[j]);
                }
            }
        }
        if (it + 2 < T) {
            __syncthreads();           // WAR guard: all reads of buf `cur` done
            loadG(it + 2, cur);
        }
        cur ^= 1;
    }
    __syncthreads();

    // ---- stage D (256x64, pitch 65)
    float* Ds = reinterpret_cast<float*>(dsm);
#pragma unroll
    for (int i = 0; i < 4; i++) {
        int r0 = mw * 64 + i * 16 + lr;
#pragma unroll
        for (int j = 0; j < 4; j++) {
            int c = nw * 32 + j * 8 + lc;
            Ds[r0 * 65 + c] = acc[i][j][0];
            Ds[r0 * 65 + c + 1] = acc[i][j][1];
            Ds[(r0 + 8) * 65 + c] = acc[i][j][2];
            Ds[(r0 + 8) * 65 + c + 1] = acc[i][j][3];
        }
    }
    __syncthreads();
    {
        int n = t & 63, p = t >> 6;
        float s = 0.f;
        for (int mm = p * 64; mm < p * 64 + 64; mm++) s += Ds[mm * 65 + n];
        red4[p][n] = s;
        __syncthreads();
        if (t < 64)
            smean[t] = (red4[0][t] + red4[1][t] + red4[2][t] + red4[3][t]) * (1.f / 256.f);
        __syncthreads();
        float mu = smean[n];
        s = 0.f;
        for (int mm = p * 64; mm < p * 64 + 64; mm++) {
            float d = Ds[mm * 65 + n] - mu; s += d * d;
        }
        red4[p][n] = s;
        __syncthreads();
        if (t < 64)
            srstd[t] = rsqrtf((red4[0][t] + red4[1][t] + red4[2][t] + red4[3][t]) * (1.f / 256.f) + 1e-6f);
        __syncthreads();
    }
    {
        int n2 = t >> 2, m0q = (t & 3) * 64;
        float mu = smean[n2], rs = srstd[n2];
        size_t rowb = ((size_t)b * HW + y * 64 + n2) * 1280 + coff + m0q;
#pragma unroll
        for (int blk = 0; blk < 64; blk += 8) {
            __align__(16) unsigned short h8[8], l8[8];
#pragma unroll
            for (int j = 0; j < 8; j++) {
                int m = m0q + blk + j;
                float vv = gelu_f((Ds[m * 65 + n2] - mu) * rs * sgam[m] + sbet[m]);
                __nv_bfloat16 h, l; splitf(vv, h, l);
                h8[j] = *reinterpret_cast<unsigned short*>(&h);
                l8[j] = *reinterpret_cast<unsigned short*>(&l);
            }
            *reinterpret_cast<uint4*>(cth + rowb + blk) = *reinterpret_cast<uint4*>(h8);
            *reinterpret_cast<uint4*>(ctl + rowb + blk) = *reinterpret_cast<uint4*>(l8);
        }
    }
}

// ---------------- HMMA GEMM M=256 (proj EPI1 -> bf16T split / conv2 EPI2 -> f32) ----
template <int EPI>
__global__ void __launch_bounds__(512, 1) k_hgemm(
    const __nv_bfloat16* __restrict__ Whi, const __nv_bfloat16* __restrict__ Wlo,
    const __nv_bfloat16* __restrict__ Ihi, const __nv_bfloat16* __restrict__ Ilo,
    const float* __restrict__ gam, const float* __restrict__ bet,
    float* __restrict__ outF, __nv_bfloat16* __restrict__ bth, __nv_bfloat16* __restrict__ btl,
    int ostride, int Kc) {
    extern __shared__ __align__(16) char dsm[];
    __shared__ float sgam[256], sbet[256], smean[128], srstd[128];
    __shared__ float red4[4][128];

    const int b = blockIdx.y, y = blockIdx.x;
    const int t = threadIdx.x, wid = t >> 5, lane = t & 31;
    const int mw = wid >> 2, nw = wid & 3;
    const uint32_t sbase = (uint32_t)__cvta_generic_to_shared(dsm);

    if (t < 256) { sgam[t] = gam[t]; sbet[t] = bet[t]; }
    __syncthreads();

    const int T = Kc / 32;
    const __nv_bfloat16* Ib_hi = Ihi + (size_t)b * HW * Kc;
    const __nv_bfloat16* Ib_lo = Ilo + (size_t)b * HW * Kc;

    float acc[4][4][4];
#pragma unroll
    for (int i = 0; i < 4; i++)
#pragma unroll
        for (int j = 0; j < 4; j++)
#pragma unroll
            for (int r = 0; r < 4; r++) acc[i][j][r] = 0.f;

    auto loadG = [&](int it, int buf) {
        int kc = it * 32;
        uint32_t base = sbase + buf * 61440;
        int arow = t >> 1, ak = (t & 1) * 16;
        const __nv_bfloat16* ah = Whi + (size_t)arow * Kc + kc + ak;
        const __nv_bfloat16* al = Wlo + (size_t)arow * Kc + kc + ak;
        uint32_t da = base + arow * 80 + ak * 2;
        cp16(da, ah, 16);
        cp16(da + 16, ah + 8, 16);
        cp16(da + 20480, al, 16);
        cp16(da + 20480 + 16, al + 8, 16);
        int n = t >> 2, q = t & 3;
        int hw = y * 128 + n;
        uint32_t db = base + 40960 + n * 80 + q * 16;
        cp16(db, Ib_hi + (size_t)hw * Kc + kc + q * 8, 16);
        cp16(db + 10240, Ib_lo + (size_t)hw * Kc + kc + q * 8, 16);
        CP_COMMIT();
    };

    loadG(0, 0);
    if (T > 1) loadG(1, 1);

    const int lr = lane >> 2, lc = 2 * (lane & 3);
    const uint32_t a_loff = (uint32_t)(((lane & 7) + ((lane >> 3) & 1) * 8) * 80
                                       + (lane >> 4) * 16);
    const uint32_t b_loff4 = (uint32_t)(((lane & 7) + ((lane >> 4) & 1) * 8) * 80
                                        + ((lane >> 3) & 1) * 16);
    const uint32_t a_wbase = (uint32_t)(mw * 64 * 80) + a_loff;
    const uint32_t b_wbase = 40960u + (uint32_t)(nw * 32 * 80) + b_loff4;

    int cur = 0;
    for (int it = 0; it < T; ++it) {
        if (it + 1 < T) CP_WAIT1(); else CP_WAIT0();
        __syncthreads();
        uint32_t sb = sbase + cur * 61440;
#pragma unroll
        for (int ks = 0; ks < 2; ks++) {
            uint32_t kboff = ks * 32;
            uint32_t bh[4][2], bl[4][2];
#pragma unroll
            for (int jp = 0; jp < 2; jp++) {
                uint32_t ba = sb + b_wbase + jp * (16 * 80) + kboff;
                uint32_t r[4];
                ldsm_x4(r, ba);
                bh[2 * jp][0] = r[0]; bh[2 * jp][1] = r[1];
                bh[2 * jp + 1][0] = r[2]; bh[2 * jp + 1][1] = r[3];
                ldsm_x4(r, ba + 10240);
                bl[2 * jp][0] = r[0]; bl[2 * jp][1] = r[1];
                bl[2 * jp + 1][0] = r[2]; bl[2 * jp + 1][1] = r[3];
            }
#pragma unroll
            for (int i = 0; i < 4; i++) {
                uint32_t aa = sb + a_wbase + i * (16 * 80) + kboff;
                uint32_t ah[4], al[4];
                ldsm_x4(ah, aa);
                ldsm_x4(al, aa + 20480);
#pragma unroll
                for (int j = 0; j < 4; j++) {
                    mma16816(acc[i][j], ah, bh[j]);
                    mma16816(acc[i][j], ah, bl[j]);
                    mma16816(acc[i][j], al, bh[j]);
                }
            }
        }
        if (it + 2 < T) loadG(it + 2, (cur + 2 >= 3) ? cur - 1 : cur + 2);
        cur = (cur + 1 == 3) ? 0 : cur + 1;
    }
    __syncthreads();

    float* Ds = reinterpret_cast<float*>(dsm);
#pragma unroll
    for (int i = 0; i < 4; i++) {
        int r0 = mw * 64 + i * 16 + lr;
#pragma unroll
        for (int j = 0; j < 4; j++) {
            int c = nw * 32 + j * 8 + lc;
            Ds[r0 * 129 + c] = acc[i][j][0];
            Ds[r0 * 129 + c + 1] = acc[i][j][1];
            Ds[(r0 + 8) * 129 + c] = acc[i][j][2];
            Ds[(r0 + 8) * 129 + c + 1] = acc[i][j][3];
        }
    }
    __syncthreads();
    if (EPI == 1) {
        int n = t & 127, p = t >> 7;
        float s = 0.f;
        for (int mm = p * 64; mm < p * 64 + 64; mm++) s += Ds[mm * 129 + n];
        red4[p][n] = s;
        __syncthreads();
        if (t < 128)
            smean[t] = (red4[0][t] + red4[1][t] + red4[2][t] + red4[3][t]) * (1.f / 256.f);
        __syncthreads();
        float mu = smean[n];
        s = 0.f;
        for (int mm = p * 64; mm < p * 64 + 64; mm++) {
            float d = Ds[mm * 129 + n] - mu; s += d * d;
        }
        red4[p][n] = s;
        __syncthreads();
        if (t < 128)
            srstd[t] = rsqrtf((red4[0][t] + red4[1][t] + red4[2][t] + red4[3][t]) * (1.f / 256.f) + 1e-6f);
        __syncthreads();
        int n2 = t >> 2, m0q = (t & 3) * 64;
        float mu2 = smean[n2], rs = srstd[n2];
        size_t rowb = ((size_t)b * HW + y * 128 + n2) * ostride + m0q;
#pragma unroll
        for (int blk = 0; blk < 64; blk += 8) {
            __align__(16) unsigned short h8[8], l8[8];
#pragma unroll
            for (int j = 0; j < 8; j++) {
                int m = m0q + blk + j;
                float vv = gelu_f((Ds[m * 129 + n2] - mu2) * rs * sgam[m] + sbet[m]);
                __nv_bfloat16 h, l; splitf(vv, h, l);
                h8[j] = *reinterpret_cast<unsigned short*>(&h);
                l8[j] = *reinterpret_cast<unsigned short*>(&l);
            }
            *reinterpret_cast<uint4*>(bth + rowb + blk) = *reinterpret_cast<uint4*>(h8);
            *reinterpret_cast<uint4*>(btl + rowb + blk) = *reinterpret_cast<uint4*>(l8);
        }
    } else {
        int m = t >> 1, nh = (t & 1) * 64;
        float bias = sgam[m];
        size_t ob = ((size_t)b * CIN + m) * HW + y * 128 + nh;
#pragma unroll
        for (int blk = 0; blk < 64; blk += 4) {
            float4 v4;
            float* vp = &v4.x;
#pragma unroll
            for (int j = 0; j < 4; j++) vp[j] = Ds[m * 129 + nh + blk + j] + bias;
            *reinterpret_cast<float4*>(outF + ob + blk) = v4;
        }
    }
}

// ---------------- HMMA conv1: 128x128 tile, K=256; fused dual-layout epilogue -------
template <bool XA>
__global__ void __launch_bounds__(512, 1) k_conv1(
    const __nv_bfloat16* __restrict__ Whi, const __nv_bfloat16* __restrict__ Wlo,
    const __nv_bfloat16* __restrict__ Ihi, const __nv_bfloat16* __restrict__ Ilo,
    const float* __restrict__ bias,
    __nv_bfloat16* __restrict__ th, __nv_bfloat16* __restrict__ tl,
    __nv_bfloat16* __restrict__ sh, __nv_bfloat16* __restrict__ sl,
    float* __restrict__ sf) {
    extern __shared__ __align__(16) char dsm[];
    __shared__ float sb2[128];
    const int b = blockIdx.y, y = blockIdx.x;
    const int t = threadIdx.x, wid = t >> 5, lane = t & 31;
    const int mw = wid >> 2, nw = wid & 3;
    const uint32_t sbase = (uint32_t)__cvta_generic_to_shared(dsm);

    if (t < 128) sb2[t] = bias[t];
    __syncthreads();

    const __nv_bfloat16* Ib_hi = Ihi + (size_t)b * HW * CIN;
    const __nv_bfloat16* Ib_lo = Ilo + (size_t)b * HW * CIN;

    float acc[2][4][4];
#pragma unroll
    for (int i = 0; i < 2; i++)
#pragma unroll
        for (int j = 0; j < 4; j++)
#pragma unroll
            for (int r = 0; r < 4; r++) acc[i][j][r] = 0.f;

    auto loadG = [&](int it, int buf) {
        int kc = it * 32;
        uint32_t base = sbase + buf * 40960;
        int r = t >> 2, q = t & 3;
        cp16(base + r * 80 + q * 16, Whi + (size_t)r * CIN + kc + q * 8, 16);
        cp16(base + 10240 + r * 80 + q * 16, Wlo + (size_t)r * CIN + kc + q * 8, 16);
        int hw = y * 128 + r;
        cp16(base + 20480 + r * 80 + q * 16, Ib_hi + (size_t)hw * CIN + kc + q * 8, 16);
        cp16(base + 30720 + r * 80 + q * 16, Ib_lo + (size_t)hw * CIN + kc + q * 8, 16);
        CP_COMMIT();
    };

    loadG(0, 0);
    loadG(1, 1);

    const int lr = lane >> 2, lc = 2 * (lane & 3);
    const uint32_t a_loff = (uint32_t)(((lane & 7) + ((lane >> 3) & 1) * 8) * 80
                                       + (lane >> 4) * 16);
    const uint32_t b_loff4 = (uint32_t)(((lane & 7) + ((lane >> 4) & 1) * 8) * 80
                                        + ((lane >> 3) & 1) * 16);
    const uint32_t a_wbase = (uint32_t)(mw * 32 * 80) + a_loff;
    const uint32_t b_wbase = 20480u + (uint32_t)(nw * 32 * 80) + b_loff4;

    const int T = CIN / 32;
    int cur = 0;
    for (int it = 0; it < T; ++it) {
        if (it + 1 < T) CP_WAIT1(); else CP_WAIT0();
        __syncthreads();
        uint32_t sb = sbase + cur * 40960;
#pragma unroll
        for (int ks = 0; ks < 2; ks++) {
            uint32_t kboff = ks * 32;
            uint32_t bh[4][2], bl[4][2];
#pragma unroll
            for (int jp = 0; jp < 2; jp++) {
                uint32_t ba = sb + b_wbase + jp * (16 * 80) + kboff;
                uint32_t r[4];
                ldsm_x4(r, ba);
                bh[2 * jp][0] = r[0]; bh[2 * jp][1] = r[1];
                bh[2 * jp + 1][0] = r[2]; bh[2 * jp + 1][1] = r[3];
                ldsm_x4(r, ba + 10240);
                bl[2 * jp][0] = r[0]; bl[2 * jp][1] = r[1];
                bl[2 * jp + 1][0] = r[2]; bl[2 * jp + 1][1] = r[3];
            }
#pragma unroll
            for (int i = 0; i < 2; i++) {
                uint32_t aa = sb + a_wbase + i * (16 * 80) + kboff;
                uint32_t ah[4], al[4];
                ldsm_x4(ah, aa);
                ldsm_x4(al, aa + 10240);
#pragma unroll
                for (int j = 0; j < 4; j++) {
                    mma16816(acc[i][j], ah, bh[j]);
                    mma16816(acc[i][j], ah, bl[j]);
                    mma16816(acc[i][j], al, bh[j]);
                }
            }
        }
        if (it + 2 < T) loadG(it + 2, (cur + 2 >= 3) ? cur - 1 : cur + 2);
        cur = (cur + 1 == 3) ? 0 : cur + 1;
    }
    __syncthreads();

    float* Ds = reinterpret_cast<float*>(dsm);
#pragma unroll
    for (int i = 0; i < 2; i++) {
        int r0 = mw * 32 + i * 16 + lr;
#pragma unroll
        for (int j = 0; j < 4; j++) {
            int c = nw * 32 + j * 8 + lc;
            Ds[r0 * 129 + c] = acc[i][j][0] + sb2[r0];
            Ds[r0 * 129 + c + 1] = acc[i][j][1] + sb2[r0];
            Ds[(r0 + 8) * 129 + c] = acc[i][j][2] + sb2[r0 + 8];
            Ds[(r0 + 8) * 129 + c + 1] = acc[i][j][3] + sb2[r0 + 8];
        }
    }
    __syncthreads();
    {
        int n2 = t >> 2, m0 = (t & 3) * 32;
        size_t rowb = ((size_t)b * HW + y * 128 + n2) * COUT + m0;
#pragma unroll
        for (int blk = 0; blk < 32; blk += 8) {
            __align__(16) unsigned short h8[8], l8[8];
#pragma unroll
            for (int j = 0; j < 8; j++) {
                float vv = Ds[(m0 + blk + j) * 129 + n2];
                __nv_bfloat16 h, l; splitf(vv, h, l);
                h8[j] = *reinterpret_cast<unsigned short*>(&h);
                l8[j] = *reinterpret_cast<unsigned short*>(&l);
            }
            *reinterpret_cast<uint4*>(th + rowb + blk) = *reinterpret_cast<uint4*>(h8);
            *reinterpret_cast<uint4*>(tl + rowb + blk) = *reinterpret_cast<uint4*>(l8);
        }
    }
    {
        int m = t >> 2, nh = (t & 3) * 32;
        size_t ob = ((size_t)b * COUT + m) * HW + y * 128 + nh;
        if (XA) {
#pragma unroll
            for (int blk = 0; blk < 32; blk += 4) {
                float4 v4;
                float* vp = &v4.x;
#pragma unroll
                for (int j = 0; j < 4; j++) vp[j] = Ds[m * 129 + nh + blk + j];
                *reinterpret_cast<float4*>(sf + ob + blk) = v4;
            }
        } else {
#pragma unroll
            for (int blk = 0; blk < 32; blk += 8) {
                __align__(16) unsigned short h8[8], l8[8];
#pragma unroll
                for (int j = 0; j < 8; j++) {
                    float vv = Ds[m * 129 + nh + blk + j];
                    __nv_bfloat16 h, l; splitf(vv, h, l);
                    h8[j] = *reinterpret_cast<unsigned short*>(&h);
                    l8[j] = *reinterpret_cast<unsigned short*>(&l);
                }
                *reinterpret_cast<uint4*>(sh + ob + blk) = *reinterpret_cast<uint4*>(h8);
                *reinterpret_cast<uint4*>(sl + ob + blk) = *reinterpret_cast<uint4*>(l8);
            }
        }
    }
}

// ---------------- HMMA S-GEMM: 256(q)x128(p), tri-buffer, Bx4 ----------
__global__ void __launch_bounds__(512, 1) k_sgemm2() {
    extern __shared__ __align__(16) char dsm[];
    const int b = blockIdx.z, q0 = blockIdx.y * 256, p0 = blockIdx.x * 128;
    const int t = threadIdx.x, wid = t >> 5, lane = t & 31;
    const int mw = wid >> 2, nw = wid & 3;
    const uint32_t sbase = (uint32_t)__cvta_generic_to_shared(dsm);
    const __nv_bfloat16* Qh = g_xath + (size_t)b * HW * COUT;
    const __nv_bfloat16* Ql = g_xatl + (size_t)b * HW * COUT;
    const __nv_bfloat16* Ph = g_x1th + (size_t)b * HW * COUT;
    const __nv_bfloat16* Pl = g_x1tl + (size_t)b * HW * COUT;

    float acc[4][4][4];
#pragma unroll
    for (int i = 0; i < 4; i++)
#pragma unroll
        for (int j = 0; j < 4; j++)
#pragma unroll
            for (int r = 0; r < 4; r++) acc[i][j][r] = 0.f;

    auto loadG = [&](int it, int buf) {
        int kc = it * 32;
        uint32_t base = sbase + buf * 61440;
        int arow = t >> 1, ak = (t & 1) * 16;
        const __nv_bfloat16* ah = Qh + (size_t)(q0 + arow) * COUT + kc + ak;
        const __nv_bfloat16* al = Ql + (size_t)(q0 + arow) * COUT + kc + ak;
        uint32_t da = base + arow * 80 + ak * 2;
        cp16(da, ah, 16);
        cp16(da + 16, ah + 8, 16);
        cp16(da + 20480, al, 16);
        cp16(da + 20480 + 16, al + 8, 16);
        int n = t >> 2, q = t & 3;
        uint32_t db = base + 40960 + n * 80 + q * 16;
        cp16(db, Ph + (size_t)(p0 + n) * COUT + kc + q * 8, 16);
        cp16(db + 10240, Pl + (size_t)(p0 + n) * COUT + kc + q * 8, 16);
        CP_COMMIT();
    };

    loadG(0, 0);
    loadG(1, 1);

    const int lr = lane >> 2, lc = 2 * (lane & 3);
    const uint32_t a_loff = (uint32_t)(((lane & 7) + ((lane >> 3) & 1) * 8) * 80
                                       + (lane >> 4) * 16);
    const uint32_t b_loff4 = (uint32_t)(((lane & 7) + ((lane >> 4) & 1) * 8) * 80
                                        + ((lane >> 3) & 1) * 16);
    const uint32_t a_wbase = (uint32_t)(mw * 64 * 80) + a_loff;
    const uint32_t b_wbase = 40960u + (uint32_t)(nw * 32 * 80) + b_loff4;

    const int T = COUT / 32;
    int cur = 0;
    for (int it = 0; it < T; ++it) {
        if (it + 1 < T) CP_WAIT1(); else CP_WAIT0();
        __syncthreads();
        uint32_t sb = sbase + cur * 61440;
#pragma unroll
        for (int ks = 0; ks < 2; ks++) {
            uint32_t kboff = ks * 32;
            uint32_t bh[4][2], bl[4][2];
#pragma unroll
            for (int jp = 0; jp < 2; jp++) {
                uint32_t ba = sb + b_wbase + jp * (16 * 80) + kboff;
                uint32_t r[4];
                ldsm_x4(r, ba);
                bh[2 * jp][0] = r[0]; bh[2 * jp][1] = r[1];
                bh[2 * jp + 1][0] = r[2]; bh[2 * jp + 1][1] = r[3];
                ldsm_x4(r, ba + 10240);
                bl[2 * jp][0] = r[0]; bl[2 * jp][1] = r[1];
                bl[2 * jp + 1][0] = r[2]; bl[2 * jp + 1][1] = r[3];
            }
#pragma unroll
            for (int i = 0; i < 4; i++) {
                uint32_t aa = sb + a_wbase + i * (16 * 80) + kboff;
                uint32_t ah[4], al[4];
                ldsm_x4(ah, aa);
                ldsm_x4(al, aa + 20480);
#pragma unroll
                for (int j = 0; j < 4; j++) {
                    mma16816(acc[i][j], ah, bh[j]);
                    mma16816(acc[i][j], ah, bl[j]);
                    mma16816(acc[i][j], al, bh[j]);
                }
            }
        }
        if (it + 2 < T) loadG(it + 2, (cur + 2 >= 3) ? cur - 1 : cur + 2);
        cur = (cur + 1 == 3) ? 0 : cur + 1;
    }
    __syncthreads();

    float* Ds = reinterpret_cast<float*>(dsm);
#pragma unroll
    for (int i = 0; i < 4; i++) {
        int r0 = mw * 64 + i * 16 + lr;
#pragma unroll
        for (int j = 0; j < 4; j++) {
            int c = nw * 32 + j * 8 + lc;
            Ds[r0 * 129 + c] = acc[i][j][0];
            Ds[r0 * 129 + c + 1] = acc[i][j][1];
            Ds[(r0 + 8) * 129 + c] = acc[i][j][2];
            Ds[(r0 + 8) * 129 + c + 1] = acc[i][j][3];
        }
    }
    __syncthreads();
    {
        const float sc = 1.f / 64.f;
        int m = t >> 1, nh = (t & 1) * 64;
        float* So = g_S + (size_t)b * HW * HW + (size_t)(q0 + m) * HW + p0 + nh;
#pragma unroll
        for (int blk = 0; blk < 64; blk += 4) {
            float4 v4;
            float* vp = &v4.x;
#pragma unroll
            for (int j = 0; j < 4; j++) vp[j] = Ds[m * 129 + nh + blk + j] * sc;
            *reinterpret_cast<float4*>(So + blk) = v4;
        }
    }
}

// ---------------- row softmax; emits bf16 hi/lo probs ----------------
__global__ void __launch_bounds__(256) k_softmax() {
    const size_t row = blockIdx.x;
    const float* r = g_S + row * (size_t)HW;
    __nv_bfloat16* oh = g_Ah + row * (size_t)HW;
    __nv_bfloat16* ol = g_Al + row * (size_t)HW;
    __shared__ float buf[HW];
    __shared__ float red[256];
    int t = threadIdx.x;
    float m = -1e30f;
    for (int i = t; i < HW; i += 256) { float v = r[i]; buf[i] = v; m = fmaxf(m, v); }
    red[t] = m; __syncthreads();
    for (int s = 128; s > 0; s >>= 1) { if (t < s) red[t] = fmaxf(red[t], red[t + s]); __syncthreads(); }
    float mx = red[0]; __syncthreads();
    float s = 0.f;
    for (int i = t; i < HW; i += 256) { float e = expf(buf[i] - mx); buf[i] = e; s += e; }
    red[t] = s; __syncthreads();
    for (int o = 128; o > 0; o >>= 1) { if (t < o) red[t] += red[t + o]; __syncthreads(); }
    float inv = 1.f / red[0];
    for (int i = t; i < HW; i += 256) {
        float p = buf[i] * inv;
        __nv_bfloat16 h, l; splitf(p, h, l);
        oh[i] = h; ol[i] = l;
    }
}

// ---------------- HMMA L-GEMM: 128(c)x128(j), tri-buffer, trans-B x4 ----------
__global__ void __launch_bounds__(512, 1) k_lgemm2() {
    extern __shared__ __align__(16) char dsm[];
    const int b = blockIdx.y, j0g = blockIdx.x * 128;
    const int t = threadIdx.x, wid = t >> 5, lane = t & 31;
    const int mw = wid >> 2, nw = wid & 3;
    const uint32_t sbase = (uint32_t)__cvta_generic_to_shared(dsm);
    const __nv_bfloat16* Xh = g_x1h + (size_t)b * COUT * HW;
    const __nv_bfloat16* Xl = g_x1l + (size_t)b * COUT * HW;
    const __nv_bfloat16* Aph = g_Ah + (size_t)b * HW * HW;
    const __nv_bfloat16* Apl = g_Al + (size_t)b * HW * HW;

    float acc[2][4][4];
#pragma unroll
    for (int i = 0; i < 2; i++)
#pragma unroll
        for (int j = 0; j < 4; j++)
#pragma unroll
            for (int r = 0; r < 4; r++) acc[i][j][r] = 0.f;

    auto loadG = [&](int it, int buf) {
        int kc = it * 32;
        uint32_t base = sbase + buf * 37888;
        int c = t >> 2, cq = t & 3;
        const __nv_bfloat16* ah = Xh + (size_t)c * HW + kc + cq * 8;
        const __nv_bfloat16* al = Xl + (size_t)c * HW + kc + cq * 8;
        uint32_t da = base + c * 80 + cq * 16;
        cp16(da, ah, 16);
        cp16(da + 10240, al, 16);
        int k = t >> 4, jt = t & 15;
        const __nv_bfloat16* bh = Aph + (size_t)(kc + k) * HW + j0g + jt * 8;
        const __nv_bfloat16* bl = Apl + (size_t)(kc + k) * HW + j0g + jt * 8;
        uint32_t db = base + 20480 + k * 272 + jt * 16;
        cp16(db, bh, 16);
        cp16(db + 8704, bl, 16);
        CP_COMMIT();
    };

    loadG(0, 0);
    loadG(1, 1);

    const int lr = lane >> 2, lc = 2 * (lane & 3);
    const uint32_t a_loff = (uint32_t)(((lane & 7) + ((lane >> 3) & 1) * 8) * 80
                                       + (lane >> 4) * 16);
    const uint32_t a_wbase = (uint32_t)(mw * 32 * 80) + a_loff;
    const uint32_t bt_loff4 = (uint32_t)((lane & 15) * 272 + ((lane >> 4) & 1) * 16);

    const int T = HW / 32;
    int cur = 0;
    for (int it = 0; it < T; ++it) {
        if (it + 1 < T) CP_WAIT1(); else CP_WAIT0();
        __syncthreads();
        uint32_t sb = sbase + cur * 37888;
#pragma unroll
        for (int ks = 0; ks < 2; ks++) {
            uint32_t bh[4][2], bl[4][2];
#pragma unroll
            for (int jp = 0; jp < 2; jp++) {
                uint32_t ba = sb + 20480 + bt_loff4 + ks * (16 * 272)
                              + (nw * 32 + jp * 16) * 2;
                uint32_t r[4];
                ldsm_x4t(r, ba);
                bh[2 * jp][0] = r[0]; bh[2 * jp][1] = r[1];
                bh[2 * jp + 1][0] = r[2]; bh[2 * jp + 1][1] = r[3];
                ldsm_x4t(r, ba + 8704);
                bl[2 * jp][0] = r[0]; bl[2 * jp][1] = r[1];
                bl[2 * jp + 1][0] = r[2]; bl[2 * jp + 1][1] = r[3];
            }
#pragma unroll
            for (int i = 0; i < 2; i++) {
                uint32_t aa = sb + a_wbase + i * (16 * 80) + ks * 32;
                uint32_t ah[4], al[4];
                ldsm_x4(ah, aa);
                ldsm_x4(al, aa + 10240);
#pragma unroll
                for (int j = 0; j < 4; j++) {
                    mma16816(acc[i][j], ah, bh[j]);
                    mma16816(acc[i][j], ah, bl[j]);
                    mma16816(acc[i][j], al, bh[j]);
                }
            }
        }
        if (it + 2 < T) loadG(it + 2, (cur + 2 >= 3) ? cur - 1 : cur + 2);
        cur = (cur + 1 == 3) ? 0 : cur + 1;
    }
    __syncthreads();

    const float* xab = g_xa + (size_t)b * COUT * HW;
    float* Ds = reinterpret_cast<float*>(dsm);
#pragma unroll
    for (int i = 0; i < 2; i++) {
#pragma unroll
        for (int j = 0; j < 4; j++) {
            int c = mw * 32 + i * 16 + lr;
            int col = nw * 32 + j * 8 + lc;
            size_t i0 = (size_t)c * HW + j0g + col;
            size_t i8 = (size_t)(c + 8) * HW + j0g + col;
            float2 x0 = *reinterpret_cast<const float2*>(xab + i0);
            float2 x8 = *reinterpret_cast<const float2*>(xab + i8);
            Ds[col * 129 + c] = acc[i][j][0] + x0.x;
            Ds[(col + 1) * 129 + c] = acc[i][j][1] + x0.y;
            Ds[col * 129 + c + 8] = acc[i][j][2] + x8.x;
            Ds[(col + 1) * 129 + c + 8] = acc[i][j][3] + x8.y;
        }
    }
    __syncthreads();
    {
        int jj = t >> 2, c0q = (t & 3) * 32;
        size_t rowb = ((size_t)b * HW + j0g + jj) * COUT + c0q;
#pragma unroll
        for (int blk = 0; blk < 32; blk += 8) {
            __align__(16) unsigned short h8[8], l8[8];
#pragma unroll
            for (int j = 0; j < 8; j++) {
                float vv = Ds[jj * 129 + c0q + blk + j];
                __nv_bfloat16 h, l; splitf(vv, h, l);
                h8[j] = *reinterpret_cast<unsigned short*>(&h);
                l8[j] = *reinterpret_cast<unsigned short*>(&l);
            }
            *reinterpret_cast<uint4*>(g_oth + rowb + blk) = *reinterpret_cast<uint4*>(h8);
            *reinterpret_cast<uint4*>(g_otl + rowb + blk) = *reinterpret_cast<uint4*>(l8);
        }
    }
}

// ---------------- host launch ----------------
extern "C" void kernel_launch(void* const* d_in, const int* in_sizes, int n_in,
                              void* d_out, int out_size) {
    (void)in_sizes; (void)n_in; (void)out_size;
    const float* x       = (const float*)d_in[0];
    const float* conv1_w = (const float*)d_in[1];
    const float* conv1_b = (const float*)d_in[2];
    const float* conv2_w = (const float*)d_in[3];
    const float* conv2_b = (const float*)d_in[4];
    const float* cw_w1   = (const float*)d_in[5];
    const float* cw_b1   = (const float*)d_in[6];
    const float* cw_ln_g = (const float*)d_in[7];
    const float* cw_ln_b = (const float*)d_in[8];
    const float* cw_w2   = (const float*)d_in[9];
    const float* cw_b2   = (const float*)d_in[10];
    const float* aspp0_w = (const float*)d_in[11];
    const float* aspp0_g = (const float*)d_in[12];
    const float* aspp0_b = (const float*)d_in[13];
    const float* aspp1_w = (const float*)d_in[14];
    const float* aspp1_g = (const float*)d_in[15];
    const float* aspp1_b = (const float*)d_in[16];
    const float* aspp2_w = (const float*)d_in[17];
    const float* aspp2_g = (const float*)d_in[18];
    const float* aspp2_b = (const float*)d_in[19];
    const float* aspp3_w = (const float*)d_in[20];
    const float* aspp3_g = (const float*)d_in[21];
    const float* aspp3_b = (const float*)d_in[22];
    const float* asppp_w = (const float*)d_in[23];
    const float* asppp_g = (const float*)d_in[24];
    const float* asppp_b = (const float*)d_in[25];
    const float* proj_w  = (const float*)d_in[26];
    const float* proj_g  = (const float*)d_in[27];
    const float* proj_b  = (const float*)d_in[28];

    void* pv;
    float *p_xa;
    __nv_bfloat16 *p_xth, *p_xtl, *p_xTh, *p_xTl, *p_cth, *p_ctl, *p_pth, *p_ptl;
    __nv_bfloat16 *p_w3h, *p_w3l, *p_a0h, *p_a0l, *p_pjh, *p_pjl, *p_c2h, *p_c2l, *p_c1h, *p_c1l;
    __nv_bfloat16 *p_x1th, *p_x1tl, *p_xath, *p_xatl, *p_x1h, *p_x1l, *p_oth, *p_otl;
    cudaGetSymbolAddress(&pv, g_xa);   p_xa   = (float*)pv;
    cudaGetSymbolAddress(&pv, g_xth);  p_xth  = (__nv_bfloat16*)pv;
    cudaGetSymbolAddress(&pv, g_xtl);  p_xtl  = (__nv_bfloat16*)pv;
    cudaGetSymbolAddress(&pv, g_xTh);  p_xTh  = (__nv_bfloat16*)pv;
    cudaGetSymbolAddress(&pv, g_xTl);  p_xTl  = (__nv_bfloat16*)pv;
    cudaGetSymbolAddress(&pv, g_cth);  p_cth  = (__nv_bfloat16*)pv;
    cudaGetSymbolAddress(&pv, g_ctl);  p_ctl  = (__nv_bfloat16*)pv;
    cudaGetSymbolAddress(&pv, g_pth);  p_pth  = (__nv_bfloat16*)pv;
    cudaGetSymbolAddress(&pv, g_ptl);  p_ptl  = (__nv_bfloat16*)pv;
    cudaGetSymbolAddress(&pv, g_w3h);  p_w3h  = (__nv_bfloat16*)pv;
    cudaGetSymbolAddress(&pv, g_w3l);  p_w3l  = (__nv_bfloat16*)pv;
    cudaGetSymbolAddress(&pv, g_a0h);  p_a0h  = (__nv_bfloat16*)pv;
    cudaGetSymbolAddress(&pv, g_a0l);  p_a0l  = (__nv_bfloat16*)pv;
    cudaGetSymbolAddress(&pv, g_pjh);  p_pjh  = (__nv_bfloat16*)pv;
    cudaGetSymbolAddress(&pv, g_pjl);  p_pjl  = (__nv_bfloat16*)pv;
    cudaGetSymbolAddress(&pv, g_c2h);  p_c2h  = (__nv_bfloat16*)pv;
    cudaGetSymbolAddress(&pv, g_c2l);  p_c2l  = (__nv_bfloat16*)pv;
    cudaGetSymbolAddress(&pv, g_c1h);  p_c1h  = (__nv_bfloat16*)pv;
    cudaGetSymbolAddress(&pv, g_c1l);  p_c1l  = (__nv_bfloat16*)pv;
    cudaGetSymbolAddress(&pv, g_x1th); p_x1th = (__nv_bfloat16*)pv;
    cudaGetSymbolAddress(&pv, g_x1tl); p_x1tl = (__nv_bfloat16*)pv;
    cudaGetSymbolAddress(&pv, g_xath); p_xath = (__nv_bfloat16*)pv;
    cudaGetSymbolAddress(&pv, g_xatl); p_xatl = (__nv_bfloat16*)pv;
    cudaGetSymbolAddress(&pv, g_x1h);  p_x1h  = (__nv_bfloat16*)pv;
    cudaGetSymbolAddress(&pv, g_x1l);  p_x1l  = (__nv_bfloat16*)pv;
    cudaGetSymbolAddress(&pv, g_oth);  p_oth  = (__nv_bfloat16*)pv;
    cudaGetSymbolAddress(&pv, g_otl);  p_otl  = (__nv_bfloat16*)pv;

    const int TRI_SMEM = 184320;
    const int A2_SMEM = 102400;   // 2 x 51200 double buffer, 2 CTAs/SM
    const int C1_SMEM = 122880;
    cudaFuncSetAttribute(k_aspp, cudaFuncAttributeMaxDynamicSharedMemorySize, A2_SMEM);
    cudaFuncSetAttribute(k_hgemm<1>, cudaFuncAttributeMaxDynamicSharedMemorySize, TRI_SMEM);
    cudaFuncSetAttribute(k_hgemm<2>, cudaFuncAttributeMaxDynamicSharedMemorySize, TRI_SMEM);
    cudaFuncSetAttribute(k_conv1<false>, cudaFuncAttributeMaxDynamicSharedMemorySize, C1_SMEM);
    cudaFuncSetAttribute(k_conv1<true>, cudaFuncAttributeMaxDynamicSharedMemorySize, C1_SMEM);
    cudaFuncSetAttribute(k_sgemm2, cudaFuncAttributeMaxDynamicSharedMemorySize, TRI_SMEM);
    cudaFuncSetAttribute(k_lgemm2, cudaFuncAttributeMaxDynamicSharedMemorySize, 113664);

    dim3 gh(HW / 128, BATCH);

    AsppArgs aa;
    aa.wh[0] = p_a0h; aa.wl[0] = p_a0l; aa.g[0] = aspp0_g; aa.bt[0] = aspp0_b;
    aa.dil[0] = 0; aa.coff[0] = 0;
    aa.wh[1] = p_w3h; aa.wl[1] = p_w3l; aa.g[1] = aspp1_g; aa.bt[1] = aspp1_b;
    aa.dil[1] = 3; aa.coff[1] = 256;
    aa.wh[2] = p_w3h + 9 * 65536; aa.wl[2] = p_w3l + 9 * 65536;
    aa.g[2] = aspp2_g; aa.bt[2] = aspp2_b; aa.dil[2] = 6; aa.coff[2] = 512;
    aa.wh[3] = p_w3h + 18 * 65536; aa.wl[3] = p_w3l + 18 * 65536;
    aa.g[3] = aspp3_g; aa.bt[3] = aspp3_b; aa.dil[3] = 9; aa.coff[3] = 768;

    k_prep<<<3584, 256>>>(aspp1_w, aspp2_w, aspp3_w, aspp0_w, proj_w, conv2_w, conv1_w, x);
    k_cw<<<BATCH, 256>>>(cw_w1, cw_b1, cw_ln_g, cw_ln_b, cw_w2, cw_b2,
                         asppp_w, asppp_g, asppp_b);
    k_xcsplit<<<dim3(128, 8, BATCH), 256>>>(x);
    // merged ASPP branches (256-thread CTAs, 2/SM)
    k_aspp<<<dim3(HH, BATCH, 4), 256, A2_SMEM>>>(aa, p_xth, p_xtl, p_cth, p_ctl);
    k_bp_cat<<<dim3(128, BATCH), 256>>>();
    // proj (K=1280) -> projT bf16 split
    k_hgemm<1><<<gh, 512, TRI_SMEM>>>(p_pjh, p_pjl, p_cth, p_ctl,
                                      proj_g, proj_b, nullptr, p_pth, p_ptl, CIN, 5 * CIN);
    // conv1 x2 (HMMA, fused layout epilogues)
    k_conv1<false><<<gh, 512, C1_SMEM>>>(p_c1h, p_c1l, p_xTh, p_xTl, conv1_b,
                                         p_x1th, p_x1tl, p_x1h, p_x1l, nullptr);
    k_conv1<true><<<gh, 512, C1_SMEM>>>(p_c1h, p_c1l, p_pth, p_ptl, conv1_b,
                                        p_xath, p_xatl, nullptr, nullptr, p_xa);
    // attention
    k_sgemm2<<<dim3(HW / 128, HW / 256, BATCH), 512, TRI_SMEM>>>();
    k_softmax<<<BATCH * HW, 256>>>();
    k_lgemm2<<<dim3(HW / 128, BATCH), 512, 113664>>>();
    // conv2 (HMMA bias epilogue, K=128)
    k_hgemm<2><<<gh, 512, TRI_SMEM>>>(p_c2h, p_c2l, p_oth, p_otl,
                                      conv2_b, conv2_b, (float*)d_out, nullptr, nullptr,
                                      0, COUT);
}

// round 15
// speedup vs baseline: 1.3902x; 1.3902x over previous
#include <cuda_runtime.h>
#include <cuda_bf16.h>
#include <math.h>
#include <stdint.h>

#define BATCH 4
#define CIN 256
#define COUT 128
#define HH 64
#define WW 64
#define HW 4096

typedef unsigned long long ull;

// ---------------- scratch (static device globals; no allocs) ----------------
__device__ float g_xa[BATCH * COUT * HW];
__device__ float g_S[(size_t)BATCH * HW * HW];
__device__ float g_avg[BATCH * CIN];
__device__ float g_mx[BATCH * CIN];
__device__ float g_s[BATCH * CIN];
__device__ float g_bp[BATCH * CIN];
// bf16 split operands
__device__ __nv_bfloat16 g_xth[BATCH * HW * CIN];   // xcT hi [b][hw][c]
__device__ __nv_bfloat16 g_xtl[BATCH * HW * CIN];
__device__ __nv_bfloat16 g_xTh[BATCH * HW * CIN];   // raw xT hi [b][hw][c]
__device__ __nv_bfloat16 g_xTl[BATCH * HW * CIN];
__device__ __nv_bfloat16 g_cth[(size_t)BATCH * HW * 5 * CIN];
__device__ __nv_bfloat16 g_ctl[(size_t)BATCH * HW * 5 * CIN];
__device__ __nv_bfloat16 g_pth[BATCH * HW * CIN];   // projT hi [b][hw][c]
__device__ __nv_bfloat16 g_ptl[BATCH * HW * CIN];
__device__ __nv_bfloat16 g_w3h[3 * 9 * CIN * CIN];
__device__ __nv_bfloat16 g_w3l[3 * 9 * CIN * CIN];
__device__ __nv_bfloat16 g_a0h[CIN * CIN];
__device__ __nv_bfloat16 g_a0l[CIN * CIN];
__device__ __nv_bfloat16 g_pjh[CIN * 5 * CIN];
__device__ __nv_bfloat16 g_pjl[CIN * 5 * CIN];
__device__ __nv_bfloat16 g_c2h[CIN * COUT];
__device__ __nv_bfloat16 g_c2l[CIN * COUT];
__device__ __nv_bfloat16 g_c1h[COUT * CIN];
__device__ __nv_bfloat16 g_c1l[COUT * CIN];
// attention operands
__device__ __nv_bfloat16 g_x1th[BATCH * HW * COUT];
__device__ __nv_bfloat16 g_x1tl[BATCH * HW * COUT];
__device__ __nv_bfloat16 g_xath[BATCH * HW * COUT];
__device__ __nv_bfloat16 g_xatl[BATCH * HW * COUT];
__device__ __nv_bfloat16 g_x1h[BATCH * COUT * HW];
__device__ __nv_bfloat16 g_x1l[BATCH * COUT * HW];
__device__ __nv_bfloat16 g_Ah[(size_t)BATCH * HW * HW];
__device__ __nv_bfloat16 g_Al[(size_t)BATCH * HW * HW];
__device__ __nv_bfloat16 g_oth[BATCH * HW * COUT];
__device__ __nv_bfloat16 g_otl[BATCH * HW * COUT];

__device__ __forceinline__ float gelu_f(float x) {
    return 0.5f * x * (1.0f + erff(x * 0.70710678118654752440f));
}
__device__ __forceinline__ void splitf(float v, __nv_bfloat16& h, __nv_bfloat16& l) {
    h = __float2bfloat16(v);
    l = __float2bfloat16(v - __bfloat162float(h));
}

// ---------------- HMMA m16n8k16 bf16 ----------------
__device__ __forceinline__ void mma16816(float* d, const uint32_t* a, const uint32_t* b) {
    asm volatile(
        "mma.sync.aligned.m16n8k16.row.col.f32.bf16.bf16.f32 "
        "{%0,%1,%2,%3}, {%4,%5,%6,%7}, {%8,%9}, {%0,%1,%2,%3};"
        : "+f"(d[0]), "+f"(d[1]), "+f"(d[2]), "+f"(d[3])
        : "r"(a[0]), "r"(a[1]), "r"(a[2]), "r"(a[3]), "r"(b[0]), "r"(b[1]));
}
__device__ __forceinline__ void ldsm_x4(uint32_t* r, uint32_t addr) {
    asm volatile("ldmatrix.sync.aligned.m8n8.x4.shared.b16 {%0,%1,%2,%3}, [%4];"
                 : "=r"(r[0]), "=r"(r[1]), "=r"(r[2]), "=r"(r[3]) : "r"(addr));
}
__device__ __forceinline__ void ldsm_x4t(uint32_t* r, uint32_t addr) {
    asm volatile("ldmatrix.sync.aligned.m8n8.x4.trans.shared.b16 {%0,%1,%2,%3}, [%4];"
                 : "=r"(r[0]), "=r"(r[1]), "=r"(r[2]), "=r"(r[3]) : "r"(addr));
}

// ---------------- cp.async helpers ----------------
__device__ __forceinline__ void cp16(uint32_t d, const void* s, int ssz) {
    asm volatile("cp.async.ca.shared.global [%0], [%1], 16, %2;"
                 :: "r"(d), "l"(s), "r"(ssz) : "memory");
}
#define CP_COMMIT() asm volatile("cp.async.commit_group;" ::: "memory")
#define CP_WAIT1()  asm volatile("cp.async.wait_group 1;" ::: "memory")
#define CP_WAIT0()  asm volatile("cp.async.wait_group 0;" ::: "memory")

// ---------------- prep: weight splits + per-(b,c) stats ----------------
__global__ void k_prep(const float* __restrict__ w1, const float* __restrict__ w2,
                       const float* __restrict__ w3, const float* __restrict__ a0,
                       const float* __restrict__ pj, const float* __restrict__ c2,
                       const float* __restrict__ c1, const float* __restrict__ x) {
    if (blockIdx.x < 2560) {
        int e = blockIdx.x * 256 + threadIdx.x;
        if (e < 196608) {
            const float* srcs[3] = { w1, w2, w3 };
            int conv = e >> 16, mc = e & 65535, m = mc >> 8, c = mc & 255;
            const float* src = srcs[conv] + (size_t)m * 2304 + (size_t)c * 9;
            size_t dbase = (size_t)conv * 9 * 65536 + (size_t)m * 256 + c;
#pragma unroll
            for (int tap = 0; tap < 9; tap++) {
                __nv_bfloat16 h, l; splitf(src[tap], h, l);
                g_w3h[dbase + (size_t)tap * 65536] = h;
                g_w3l[dbase + (size_t)tap * 65536] = l;
            }
        } else if (e < 262144) {
            int i = e - 196608;
            __nv_bfloat16 h, l; splitf(a0[i], h, l);
            g_a0h[i] = h; g_a0l[i] = l;
        } else if (e < 589824) {
            int i = e - 262144;
            __nv_bfloat16 h, l; splitf(pj[i], h, l);
            g_pjh[i] = h; g_pjl[i] = l;
        } else if (e < 622592) {
            int i = e - 589824;
            __nv_bfloat16 h, l; splitf(c2[i], h, l);
            g_c2h[i] = h; g_c2l[i] = l;
        } else if (e < 655360) {
            int i = e - 622592;
            __nv_bfloat16 h, l; splitf(c1[i], h, l);
            g_c1h[i] = h; g_c1l[i] = l;
        }
    } else {
        int bc = blockIdx.x - 2560;
        const float* p = x + (size_t)bc * HW;
        int t = threadIdx.x;
        float s = 0.f, m = -1e30f;
        for (int i = t; i < HW; i += 256) { float v = p[i]; s += v; m = fmaxf(m, v); }
        __shared__ float ss[256], sm[256];
        ss[t] = s; sm[t] = m; __syncthreads();
        for (int o = 128; o > 0; o >>= 1) {
            if (t < o) { ss[t] += ss[t + o]; sm[t] = fmaxf(sm[t], sm[t + o]); }
            __syncthreads();
        }
        if (t == 0) { g_avg[bc] = ss[0] * (1.f / HW); g_mx[bc] = sm[0]; }
    }
}

// ---------------- channel weighting MLP + global-pool ASPP branch ----------------
__global__ void k_cw(const float* __restrict__ w1, const float* __restrict__ bb1,
                     const float* __restrict__ lg, const float* __restrict__ lb,
                     const float* __restrict__ w2, const float* __restrict__ bb2,
                     const float* __restrict__ apw, const float* __restrict__ apg,
                     const float* __restrict__ apb) {
    int b = blockIdx.x, t = threadIdx.x;
    __shared__ float o[CIN];
    __shared__ float h[COUT];
    __shared__ float red[256];
    __shared__ float gp[CIN];
    float avg = g_avg[b * CIN + t], mx = g_mx[b * CIN + t];
    o[t] = fabsf(avg - mx) * avg;
    __syncthreads();
    float hv = 0.f;
    if (t < COUT) {
        hv = bb1[t];
        const float* wr = w1 + t * CIN;
        for (int i = 0; i < CIN; i++) hv = fmaf(o[i], wr[i], hv);
    }
    red[t] = (t < COUT) ? hv : 0.f; __syncthreads();
    for (int s = 128; s > 0; s >>= 1) { if (t < s) red[t] += red[t + s]; __syncthreads(); }
    float mu = red[0] * (1.f / COUT); __syncthreads();
    float dv = (t < COUT) ? (hv - mu) : 0.f;
    red[t] = dv * dv; __syncthreads();
    for (int s = 128; s > 0; s >>= 1) { if (t < s) red[t] += red[t + s]; __syncthreads(); }
    float var = red[0] * (1.f / COUT); __syncthreads();
    if (t < COUT) h[t] = lg[t] * ((hv - mu) * rsqrtf(var + 1e-5f)) + lb[t];
    __syncthreads();
    float sv = bb2[t];
    const float* wr2 = w2 + t * COUT;
    for (int j = 0; j < COUT; j++) sv = fmaf(h[j], wr2[j], sv);
    float sig = 1.f / (1.f + expf(-sv));
    g_s[b * CIN + t] = sig;
    gp[t] = (1.f + sig) * avg;
    __syncthreads();
    float v = 0.f;
    const float* ar = apw + t * CIN;
    for (int i = 0; i < CIN; i++) v = fmaf(ar[i], gp[i], v);
    red[t] = v; __syncthreads();
    for (int s = 128; s > 0; s >>= 1) { if (t < s) red[t] += red[t + s]; __syncthreads(); }
    float mu2 = red[0] * (1.f / CIN); __syncthreads();
    float d2 = v - mu2; red[t] = d2 * d2; __syncthreads();
    for (int s = 128; s > 0; s >>= 1) { if (t < s) red[t] += red[t + s]; __syncthreads(); }
    float var2 = red[0] * (1.f / CIN); __syncthreads();
    float z = apg[t] * ((v - mu2) * rsqrtf(var2 + 1e-6f)) + apb[t];
    g_bp[b * CIN + t] = gelu_f(z);
}

// ---------------- xT / xcT split ----------------
__global__ void k_xcsplit(const float* __restrict__ x) {
    __shared__ float tile[32][33];
    int b = blockIdx.z, c0 = blockIdx.y * 32, h0 = blockIdx.x * 32;
    int t = threadIdx.x;
    const float* xb = x + ((size_t)b * CIN + c0) * HW + h0;
#pragma unroll
    for (int i = 0; i < 4; i++) {
        int r = (t >> 5) + 8 * i;
        tile[r][t & 31] = xb[(size_t)r * HW + (t & 31)];
    }
    __syncthreads();
#pragma unroll
    for (int i = 0; i < 4; i++) {
        int hr = (t >> 5) + 8 * i, cc = t & 31;
        float vr = tile[cc][hr];
        size_t idx = ((size_t)b * HW + h0 + hr) * CIN + c0 + cc;
        __nv_bfloat16 h, l;
        splitf(vr, h, l);
        g_xTh[idx] = h; g_xTl[idx] = l;
        float v = vr * (1.f + g_s[b * CIN + c0 + cc]);
        splitf(v, h, l);
        g_xth[idx] = h; g_xtl[idx] = l;
    }
}

// ---------------- bp broadcast into catT channels [1024,1280) ----------------
__global__ void k_bp_cat() {
    int b = blockIdx.y, h0 = blockIdx.x * 32;
    int c = threadIdx.x;
    __nv_bfloat16 h, l; splitf(g_bp[b * CIN + c], h, l);
    for (int r = 0; r < 32; r++) {
        size_t idx = ((size_t)b * HW + h0 + r) * 1280 + 1024 + c;
        g_cth[idx] = h; g_ctl[idx] = l;
    }
}

struct AsppArgs {
    const __nv_bfloat16* wh[4];
    const __nv_bfloat16* wl[4];
    const float* g[4];
    const float* bt[4];
    int dil[4];
    int coff[4];
};

// ---------------- merged ASPP HMMA kernel: 256x128 tile, 512 thr, tri-buffer, Bx4 ---
__global__ void __launch_bounds__(512, 1) k_aspp(
    AsppArgs A_, const __nv_bfloat16* __restrict__ Ihi, const __nv_bfloat16* __restrict__ Ilo,
    __nv_bfloat16* __restrict__ cth, __nv_bfloat16* __restrict__ ctl) {
    extern __shared__ __align__(16) char dsm[];
    __shared__ int s_tapn, s_tp[9], s_dy[9], s_dx[9];
    __shared__ float sgam[256], sbet[256], smean[128], srstd[128];
    __shared__ float red4[4][128];

    const int br = blockIdx.z, b = blockIdx.y, y = blockIdx.x;
    const int t = threadIdx.x, wid = t >> 5, lane = t & 31;
    const int mw = wid >> 2, nw = wid & 3;
    const uint32_t sbase = (uint32_t)__cvta_generic_to_shared(dsm);
    const __nv_bfloat16* Whi = A_.wh[br];
    const __nv_bfloat16* Wlo = A_.wl[br];
    const int dil = A_.dil[br], coff = A_.coff[br];

    if (t == 0) {
        if (dil == 0) {
            s_tapn = 1; s_tp[0] = 0; s_dy[0] = 0; s_dx[0] = 0;
        } else {
            int n = 0;
            for (int tap = 0; tap < 9; tap++) {
                int dy = (tap / 3 - 1) * dil;
                int y0 = y * 2 + dy, y1 = y * 2 + 1 + dy;
                if ((unsigned)y0 < 64u || (unsigned)y1 < 64u) {
                    s_tp[n] = tap; s_dy[n] = dy; s_dx[n] = (tap % 3 - 1) * dil; n++;
                }
            }
            s_tapn = n;
        }
    }
    if (t < 256) { sgam[t] = A_.g[br][t]; sbet[t] = A_.bt[br][t]; }
    __syncthreads();

    const int T = s_tapn * 8;
    const __nv_bfloat16* Ib_hi = Ihi + (size_t)b * HW * CIN;
    const __nv_bfloat16* Ib_lo = Ilo + (size_t)b * HW * CIN;

    float acc[4][4][4];
#pragma unroll
    for (int i = 0; i < 4; i++)
#pragma unroll
        for (int j = 0; j < 4; j++)
#pragma unroll
            for (int r = 0; r < 4; r++) acc[i][j][r] = 0.f;

    auto loadG = [&](int it, int buf) {
        int tap_i = it >> 3;
        int kc = (it & 7) * 32;
        uint32_t base = sbase + buf * 61440;
        int arow = t >> 1, ak = (t & 1) * 16;
        int grow = s_tp[tap_i] * 256 + arow;
        const __nv_bfloat16* ah = Whi + (size_t)grow * CIN + kc + ak;
        const __nv_bfloat16* al = Wlo + (size_t)grow * CIN + kc + ak;
        uint32_t da = base + arow * 80 + ak * 2;
        cp16(da, ah, 16);
        cp16(da + 16, ah + 8, 16);
        cp16(da + 20480, al, 16);
        cp16(da + 20480 + 16, al + 8, 16);
        int n = t >> 2, q = t & 3;
        int hw; int ok = 16;
        int yy = y * 2 + (n >> 6) + s_dy[tap_i];
        int xx = (n & 63) + s_dx[tap_i];
        if ((unsigned)yy < 64u && (unsigned)xx < 64u) hw = yy * 64 + xx;
        else { hw = 0; ok = (dil == 0) ? 16 : 0; }
        if (dil == 0) hw = y * 128 + n;
        uint32_t db = base + 40960 + n * 80 + q * 16;
        cp16(db, Ib_hi + (size_t)hw * CIN + kc + q * 8, ok);
        cp16(db + 10240, Ib_lo + (size_t)hw * CIN + kc + q * 8, ok);
        CP_COMMIT();
    };

    loadG(0, 0);
    if (T > 1) loadG(1, 1);

    const int lr = lane >> 2, lc = 2 * (lane & 3);
    const uint32_t a_loff = (uint32_t)(((lane & 7) + ((lane >> 3) & 1) * 8) * 80
                                       + (lane >> 4) * 16);
    const uint32_t b_loff4 = (uint32_t)(((lane & 7) + ((lane >> 4) & 1) * 8) * 80
                                        + ((lane >> 3) & 1) * 16);
    const uint32_t a_wbase = (uint32_t)(mw * 64 * 80) + a_loff;
    const uint32_t b_wbase = 40960u + (uint32_t)(nw * 32 * 80) + b_loff4;

    int cur = 0;
    for (int it = 0; it < T; ++it) {
        if (it + 1 < T) CP_WAIT1(); else CP_WAIT0();
        __syncthreads();
        uint32_t sb = sbase + cur * 61440;
#pragma unroll
        for (int ks = 0; ks < 2; ks++) {
            uint32_t kboff = ks * 32;
            uint32_t bh[4][2], bl[4][2];
#pragma unroll
            for (int jp = 0; jp < 2; jp++) {
                uint32_t ba = sb + b_wbase + jp * (16 * 80) + kboff;
                uint32_t r[4];
                ldsm_x4(r, ba);
                bh[2 * jp][0] = r[0]; bh[2 * jp][1] = r[1];
                bh[2 * jp + 1][0] = r[2]; bh[2 * jp + 1][1] = r[3];
                ldsm_x4(r, ba + 10240);
                bl[2 * jp][0] = r[0]; bl[2 * jp][1] = r[1];
                bl[2 * jp + 1][0] = r[2]; bl[2 * jp + 1][1] = r[3];
            }
#pragma unroll
            for (int i = 0; i < 4; i++) {
                uint32_t aa = sb + a_wbase + i * (16 * 80) + kboff;
                uint32_t ah[4], al[4];
                ldsm_x4(ah, aa);
                ldsm_x4(al, aa + 20480);
#pragma unroll
                for (int j = 0; j < 4; j++) {
                    mma16816(acc[i][j], ah, bh[j]);
                    mma16816(acc[i][j], ah, bl[j]);
                    mma16816(acc[i][j], al, bh[j]);
                }
            }
        }
        if (it + 2 < T) loadG(it + 2, (cur + 2 >= 3) ? cur - 1 : cur + 2);
        cur = (cur + 1 == 3) ? 0 : cur + 1;
    }
    __syncthreads();

    float* Ds = reinterpret_cast<float*>(dsm);
#pragma unroll
    for (int i = 0; i < 4; i++) {
        int r0 = mw * 64 + i * 16 + lr;
#pragma unroll
        for (int j = 0; j < 4; j++) {
            int c = nw * 32 + j * 8 + lc;
            Ds[r0 * 129 + c] = acc[i][j][0];
            Ds[r0 * 129 + c + 1] = acc[i][j][1];
            Ds[(r0 + 8) * 129 + c] = acc[i][j][2];
            Ds[(r0 + 8) * 129 + c + 1] = acc[i][j][3];
        }
    }
    __syncthreads();
    {
        int n = t & 127, p = t >> 7;
        float s = 0.f;
        for (int mm = p * 64; mm < p * 64 + 64; mm++) s += Ds[mm * 129 + n];
        red4[p][n] = s;
        __syncthreads();
        if (t < 128)
            smean[t] = (red4[0][t] + red4[1][t] + red4[2][t] + red4[3][t]) * (1.f / 256.f);
        __syncthreads();
        float mu = smean[n];
        s = 0.f;
        for (int mm = p * 64; mm < p * 64 + 64; mm++) {
            float d = Ds[mm * 129 + n] - mu; s += d * d;
        }
        red4[p][n] = s;
        __syncthreads();
        if (t < 128)
            srstd[t] = rsqrtf((red4[0][t] + red4[1][t] + red4[2][t] + red4[3][t]) * (1.f / 256.f) + 1e-6f);
        __syncthreads();
    }
    {
        int n2 = t >> 2, m0q = (t & 3) * 64;
        float mu = smean[n2], rs = srstd[n2];
        size_t rowb = ((size_t)b * HW + y * 128 + n2) * 1280 + coff + m0q;
#pragma unroll
        for (int blk = 0; blk < 64; blk += 8) {
            __align__(16) unsigned short h8[8], l8[8];
#pragma unroll
            for (int j = 0; j < 8; j++) {
                int m = m0q + blk + j;
                float vv = gelu_f((Ds[m * 129 + n2] - mu) * rs * sgam[m] + sbet[m]);
                __nv_bfloat16 h, l; splitf(vv, h, l);
                h8[j] = *reinterpret_cast<unsigned short*>(&h);
                l8[j] = *reinterpret_cast<unsigned short*>(&l);
            }
            *reinterpret_cast<uint4*>(cth + rowb + blk) = *reinterpret_cast<uint4*>(h8);
            *reinterpret_cast<uint4*>(ctl + rowb + blk) = *reinterpret_cast<uint4*>(l8);
        }
    }
}

// ---------------- HMMA GEMM M=256 (proj EPI1 -> bf16T split / conv2 EPI2 -> f32) ----
template <int EPI>
__global__ void __launch_bounds__(512, 1) k_hgemm(
    const __nv_bfloat16* __restrict__ Whi, const __nv_bfloat16* __restrict__ Wlo,
    const __nv_bfloat16* __restrict__ Ihi, const __nv_bfloat16* __restrict__ Ilo,
    const float* __restrict__ gam, const float* __restrict__ bet,
    float* __restrict__ outF, __nv_bfloat16* __restrict__ bth, __nv_bfloat16* __restrict__ btl,
    int ostride, int Kc) {
    extern __shared__ __align__(16) char dsm[];
    __shared__ float sgam[256], sbet[256], smean[128], srstd[128];
    __shared__ float red4[4][128];

    const int b = blockIdx.y, y = blockIdx.x;
    const int t = threadIdx.x, wid = t >> 5, lane = t & 31;
    const int mw = wid >> 2, nw = wid & 3;
    const uint32_t sbase = (uint32_t)__cvta_generic_to_shared(dsm);

    if (t < 256) { sgam[t] = gam[t]; sbet[t] = bet[t]; }
    __syncthreads();

    const int T = Kc / 32;
    const __nv_bfloat16* Ib_hi = Ihi + (size_t)b * HW * Kc;
    const __nv_bfloat16* Ib_lo = Ilo + (size_t)b * HW * Kc;

    float acc[4][4][4];
#pragma unroll
    for (int i = 0; i < 4; i++)
#pragma unroll
        for (int j = 0; j < 4; j++)
#pragma unroll
            for (int r = 0; r < 4; r++) acc[i][j][r] = 0.f;

    auto loadG = [&](int it, int buf) {
        int kc = it * 32;
        uint32_t base = sbase + buf * 61440;
        int arow = t >> 1, ak = (t & 1) * 16;
        const __nv_bfloat16* ah = Whi + (size_t)arow * Kc + kc + ak;
        const __nv_bfloat16* al = Wlo + (size_t)arow * Kc + kc + ak;
        uint32_t da = base + arow * 80 + ak * 2;
        cp16(da, ah, 16);
        cp16(da + 16, ah + 8, 16);
        cp16(da + 20480, al, 16);
        cp16(da + 20480 + 16, al + 8, 16);
        int n = t >> 2, q = t & 3;
        int hw = y * 128 + n;
        uint32_t db = base + 40960 + n * 80 + q * 16;
        cp16(db, Ib_hi + (size_t)hw * Kc + kc + q * 8, 16);
        cp16(db + 10240, Ib_lo + (size_t)hw * Kc + kc + q * 8, 16);
        CP_COMMIT();
    };

    loadG(0, 0);
    if (T > 1) loadG(1, 1);

    const int lr = lane >> 2, lc = 2 * (lane & 3);
    const uint32_t a_loff = (uint32_t)(((lane & 7) + ((lane >> 3) & 1) * 8) * 80
                                       + (lane >> 4) * 16);
    const uint32_t b_loff4 = (uint32_t)(((lane & 7) + ((lane >> 4) & 1) * 8) * 80
                                        + ((lane >> 3) & 1) * 16);
    const uint32_t a_wbase = (uint32_t)(mw * 64 * 80) + a_loff;
    const uint32_t b_wbase = 40960u + (uint32_t)(nw * 32 * 80) + b_loff4;

    int cur = 0;
    for (int it = 0; it < T; ++it) {
        if (it + 1 < T) CP_WAIT1(); else CP_WAIT0();
        __syncthreads();
        uint32_t sb = sbase + cur * 61440;
#pragma unroll
        for (int ks = 0; ks < 2; ks++) {
            uint32_t kboff = ks * 32;
            uint32_t bh[4][2], bl[4][2];
#pragma unroll
            for (int jp = 0; jp < 2; jp++) {
                uint32_t ba = sb + b_wbase + jp * (16 * 80) + kboff;
                uint32_t r[4];
                ldsm_x4(r, ba);
                bh[2 * jp][0] = r[0]; bh[2 * jp][1] = r[1];
                bh[2 * jp + 1][0] = r[2]; bh[2 * jp + 1][1] = r[3];
                ldsm_x4(r, ba + 10240);
                bl[2 * jp][0] = r[0]; bl[2 * jp][1] = r[1];
                bl[2 * jp + 1][0] = r[2]; bl[2 * jp + 1][1] = r[3];
            }
#pragma unroll
            for (int i = 0; i < 4; i++) {
                uint32_t aa = sb + a_wbase + i * (16 * 80) + kboff;
                uint32_t ah[4], al[4];
                ldsm_x4(ah, aa);
                ldsm_x4(al, aa + 20480);
#pragma unroll
                for (int j = 0; j < 4; j++) {
                    mma16816(acc[i][j], ah, bh[j]);
                    mma16816(acc[i][j], ah, bl[j]);
                    mma16816(acc[i][j], al, bh[j]);
                }
            }
        }
        if (it + 2 < T) loadG(it + 2, (cur + 2 >= 3) ? cur - 1 : cur + 2);
        cur = (cur + 1 == 3) ? 0 : cur + 1;
    }
    __syncthreads();

    float* Ds = reinterpret_cast<float*>(dsm);
#pragma unroll
    for (int i = 0; i < 4; i++) {
        int r0 = mw * 64 + i * 16 + lr;
#pragma unroll
        for (int j = 0; j < 4; j++) {
            int c = nw * 32 + j * 8 + lc;
            Ds[r0 * 129 + c] = acc[i][j][0];
            Ds[r0 * 129 + c + 1] = acc[i][j][1];
            Ds[(r0 + 8) * 129 + c] = acc[i][j][2];
            Ds[(r0 + 8) * 129 + c + 1] = acc[i][j][3];
        }
    }
    __syncthreads();
    if (EPI == 1) {
        int n = t & 127, p = t >> 7;
        float s = 0.f;
        for (int mm = p * 64; mm < p * 64 + 64; mm++) s += Ds[mm * 129 + n];
        red4[p][n] = s;
        __syncthreads();
        if (t < 128)
            smean[t] = (red4[0][t] + red4[1][t] + red4[2][t] + red4[3][t]) * (1.f / 256.f);
        __syncthreads();
        float mu = smean[n];
        s = 0.f;
        for (int mm = p * 64; mm < p * 64 + 64; mm++) {
            float d = Ds[mm * 129 + n] - mu; s += d * d;
        }
        red4[p][n] = s;
        __syncthreads();
        if (t < 128)
            srstd[t] = rsqrtf((red4[0][t] + red4[1][t] + red4[2][t] + red4[3][t]) * (1.f / 256.f) + 1e-6f);
        __syncthreads();
        int n2 = t >> 2, m0q = (t & 3) * 64;
        float mu2 = smean[n2], rs = srstd[n2];
        size_t rowb = ((size_t)b * HW + y * 128 + n2) * ostride + m0q;
#pragma unroll
        for (int blk = 0; blk < 64; blk += 8) {
            __align__(16) unsigned short h8[8], l8[8];
#pragma unroll
            for (int j = 0; j < 8; j++) {
                int m = m0q + blk + j;
                float vv = gelu_f((Ds[m * 129 + n2] - mu2) * rs * sgam[m] + sbet[m]);
                __nv_bfloat16 h, l; splitf(vv, h, l);
                h8[j] = *reinterpret_cast<unsigned short*>(&h);
                l8[j] = *reinterpret_cast<unsigned short*>(&l);
            }
            *reinterpret_cast<uint4*>(bth + rowb + blk) = *reinterpret_cast<uint4*>(h8);
            *reinterpret_cast<uint4*>(btl + rowb + blk) = *reinterpret_cast<uint4*>(l8);
        }
    } else {
        int m = t >> 1, nh = (t & 1) * 64;
        float bias = sgam[m];
        size_t ob = ((size_t)b * CIN + m) * HW + y * 128 + nh;
#pragma unroll
        for (int blk = 0; blk < 64; blk += 4) {
            float4 v4;
            float* vp = &v4.x;
#pragma unroll
            for (int j = 0; j < 4; j++) vp[j] = Ds[m * 129 + nh + blk + j] + bias;
            *reinterpret_cast<float4*>(outF + ob + blk) = v4;
        }
    }
}

// ---------------- HMMA conv1 merged: z=0 -> x1 (T split + straight split),
//                  z=1 -> xa (T split + straight fp32). 128x128 tile, K=256. ------
__global__ void __launch_bounds__(512, 1) k_conv1(
    const __nv_bfloat16* __restrict__ Whi, const __nv_bfloat16* __restrict__ Wlo,
    const __nv_bfloat16* __restrict__ I0h, const __nv_bfloat16* __restrict__ I0l,
    const __nv_bfloat16* __restrict__ I1h, const __nv_bfloat16* __restrict__ I1l,
    const float* __restrict__ bias) {
    extern __shared__ __align__(16) char dsm[];
    __shared__ float sb2[128];
    const int zb = blockIdx.z, b = blockIdx.y, y = blockIdx.x;
    const int t = threadIdx.x, wid = t >> 5, lane = t & 31;
    const int mw = wid >> 2, nw = wid & 3;
    const uint32_t sbase = (uint32_t)__cvta_generic_to_shared(dsm);

    if (t < 128) sb2[t] = bias[t];
    __syncthreads();

    const __nv_bfloat16* Ib_hi = (zb ? I1h : I0h) + (size_t)b * HW * CIN;
    const __nv_bfloat16* Ib_lo = (zb ? I1l : I0l) + (size_t)b * HW * CIN;

    float acc[2][4][4];
#pragma unroll
    for (int i = 0; i < 2; i++)
#pragma unroll
        for (int j = 0; j < 4; j++)
#pragma unroll
            for (int r = 0; r < 4; r++) acc[i][j][r] = 0.f;

    auto loadG = [&](int it, int buf) {
        int kc = it * 32;
        uint32_t base = sbase + buf * 40960;
        int r = t >> 2, q = t & 3;
        cp16(base + r * 80 + q * 16, Whi + (size_t)r * CIN + kc + q * 8, 16);
        cp16(base + 10240 + r * 80 + q * 16, Wlo + (size_t)r * CIN + kc + q * 8, 16);
        int hw = y * 128 + r;
        cp16(base + 20480 + r * 80 + q * 16, Ib_hi + (size_t)hw * CIN + kc + q * 8, 16);
        cp16(base + 30720 + r * 80 + q * 16, Ib_lo + (size_t)hw * CIN + kc + q * 8, 16);
        CP_COMMIT();
    };

    loadG(0, 0);
    loadG(1, 1);

    const int lr = lane >> 2, lc = 2 * (lane & 3);
    const uint32_t a_loff = (uint32_t)(((lane & 7) + ((lane >> 3) & 1) * 8) * 80
                                       + (lane >> 4) * 16);
    const uint32_t b_loff4 = (uint32_t)(((lane & 7) + ((lane >> 4) & 1) * 8) * 80
                                        + ((lane >> 3) & 1) * 16);
    const uint32_t a_wbase = (uint32_t)(mw * 32 * 80) + a_loff;
    const uint32_t b_wbase = 20480u + (uint32_t)(nw * 32 * 80) + b_loff4;

    const int T = CIN / 32;
    int cur = 0;
    for (int it = 0; it < T; ++it) {
        if (it + 1 < T) CP_WAIT1(); else CP_WAIT0();
        __syncthreads();
        uint32_t sb = sbase + cur * 40960;
#pragma unroll
        for (int ks = 0; ks < 2; ks++) {
            uint32_t kboff = ks * 32;
            uint32_t bh[4][2], bl[4][2];
#pragma unroll
            for (int jp = 0; jp < 2; jp++) {
                uint32_t ba = sb + b_wbase + jp * (16 * 80) + kboff;
                uint32_t r[4];
                ldsm_x4(r, ba);
                bh[2 * jp][0] = r[0]; bh[2 * jp][1] = r[1];
                bh[2 * jp + 1][0] = r[2]; bh[2 * jp + 1][1] = r[3];
                ldsm_x4(r, ba + 10240);
                bl[2 * jp][0] = r[0]; bl[2 * jp][1] = r[1];
                bl[2 * jp + 1][0] = r[2]; bl[2 * jp + 1][1] = r[3];
            }
#pragma unroll
            for (int i = 0; i < 2; i++) {
                uint32_t aa = sb + a_wbase + i * (16 * 80) + kboff;
                uint32_t ah[4], al[4];
                ldsm_x4(ah, aa);
                ldsm_x4(al, aa + 10240);
#pragma unroll
                for (int j = 0; j < 4; j++) {
                    mma16816(acc[i][j], ah, bh[j]);
                    mma16816(acc[i][j], ah, bl[j]);
                    mma16816(acc[i][j], al, bh[j]);
                }
            }
        }
        if (it + 2 < T) loadG(it + 2, (cur + 2 >= 3) ? cur - 1 : cur + 2);
        cur = (cur + 1 == 3) ? 0 : cur + 1;
    }
    __syncthreads();

    float* Ds = reinterpret_cast<float*>(dsm);
#pragma unroll
    for (int i = 0; i < 2; i++) {
        int r0 = mw * 32 + i * 16 + lr;
#pragma unroll
        for (int j = 0; j < 4; j++) {
            int c = nw * 32 + j * 8 + lc;
            Ds[r0 * 129 + c] = acc[i][j][0] + sb2[r0];
            Ds[r0 * 129 + c + 1] = acc[i][j][1] + sb2[r0];
            Ds[(r0 + 8) * 129 + c] = acc[i][j][2] + sb2[r0 + 8];
            Ds[(r0 + 8) * 129 + c + 1] = acc[i][j][3] + sb2[r0 + 8];
        }
    }
    __syncthreads();
    {
        int n2 = t >> 2, m0 = (t & 3) * 32;
        __nv_bfloat16* th = zb ? g_xath : g_x1th;
        __nv_bfloat16* tl = zb ? g_xatl : g_x1tl;
        size_t rowb = ((size_t)b * HW + y * 128 + n2) * COUT + m0;
#pragma unroll
        for (int blk = 0; blk < 32; blk += 8) {
            __align__(16) unsigned short h8[8], l8[8];
#pragma unroll
            for (int j = 0; j < 8; j++) {
                float vv = Ds[(m0 + blk + j) * 129 + n2];
                __nv_bfloat16 h, l; splitf(vv, h, l);
                h8[j] = *reinterpret_cast<unsigned short*>(&h);
                l8[j] = *reinterpret_cast<unsigned short*>(&l);
            }
            *reinterpret_cast<uint4*>(th + rowb + blk) = *reinterpret_cast<uint4*>(h8);
            *reinterpret_cast<uint4*>(tl + rowb + blk) = *reinterpret_cast<uint4*>(l8);
        }
    }
    {
        int m = t >> 2, nh = (t & 3) * 32;
        size_t ob = ((size_t)b * COUT + m) * HW + y * 128 + nh;
        if (zb) {
#pragma unroll
            for (int blk = 0; blk < 32; blk += 4) {
                float4 v4;
                float* vp = &v4.x;
#pragma unroll
                for (int j = 0; j < 4; j++) vp[j] = Ds[m * 129 + nh + blk + j];
                *reinterpret_cast<float4*>(g_xa + ob + blk) = v4;
            }
        } else {
#pragma unroll
            for (int blk = 0; blk < 32; blk += 8) {
                __align__(16) unsigned short h8[8], l8[8];
#pragma unroll
                for (int j = 0; j < 8; j++) {
                    float vv = Ds[m * 129 + nh + blk + j];
                    __nv_bfloat16 h, l; splitf(vv, h, l);
                    h8[j] = *reinterpret_cast<unsigned short*>(&h);
                    l8[j] = *reinterpret_cast<unsigned short*>(&l);
                }
                *reinterpret_cast<uint4*>(g_x1h + ob + blk) = *reinterpret_cast<uint4*>(h8);
                *reinterpret_cast<uint4*>(g_x1l + ob + blk) = *reinterpret_cast<uint4*>(l8);
            }
        }
    }
}

// ---------------- HMMA S-GEMM: 256(q)x128(p), tri-buffer, Bx4 ----------
__global__ void __launch_bounds__(512, 1) k_sgemm2() {
    extern __shared__ __align__(16) char dsm[];
    const int b = blockIdx.z, q0 = blockIdx.y * 256, p0 = blockIdx.x * 128;
    const int t = threadIdx.x, wid = t >> 5, lane = t & 31;
    const int mw = wid >> 2, nw = wid & 3;
    const uint32_t sbase = (uint32_t)__cvta_generic_to_shared(dsm);
    const __nv_bfloat16* Qh = g_xath + (size_t)b * HW * COUT;
    const __nv_bfloat16* Ql = g_xatl + (size_t)b * HW * COUT;
    const __nv_bfloat16* Ph = g_x1th + (size_t)b * HW * COUT;
    const __nv_bfloat16* Pl = g_x1tl + (size_t)b * HW * COUT;

    float acc[4][4][4];
#pragma unroll
    for (int i = 0; i < 4; i++)
#pragma unroll
        for (int j = 0; j < 4; j++)
#pragma unroll
            for (int r = 0; r < 4; r++) acc[i][j][r] = 0.f;

    auto loadG = [&](int it, int buf) {
        int kc = it * 32;
        uint32_t base = sbase + buf * 61440;
        int arow = t >> 1, ak = (t & 1) * 16;
        const __nv_bfloat16* ah = Qh + (size_t)(q0 + arow) * COUT + kc + ak;
        const __nv_bfloat16* al = Ql + (size_t)(q0 + arow) * COUT + kc + ak;
        uint32_t da = base + arow * 80 + ak * 2;
        cp16(da, ah, 16);
        cp16(da + 16, ah + 8, 16);
        cp16(da + 20480, al, 16);
        cp16(da + 20480 + 16, al + 8, 16);
        int n = t >> 2, q = t & 3;
        uint32_t db = base + 40960 + n * 80 + q * 16;
        cp16(db, Ph + (size_t)(p0 + n) * COUT + kc + q * 8, 16);
        cp16(db + 10240, Pl + (size_t)(p0 + n) * COUT + kc + q * 8, 16);
        CP_COMMIT();
    };

    loadG(0, 0);
    loadG(1, 1);

    const int lr = lane >> 2, lc = 2 * (lane & 3);
    const uint32_t a_loff = (uint32_t)(((lane & 7) + ((lane >> 3) & 1) * 8) * 80
                                       + (lane >> 4) * 16);
    const uint32_t b_loff4 = (uint32_t)(((lane & 7) + ((lane >> 4) & 1) * 8) * 80
                                        + ((lane >> 3) & 1) * 16);
    const uint32_t a_wbase = (uint32_t)(mw * 64 * 80) + a_loff;
    const uint32_t b_wbase = 40960u + (uint32_t)(nw * 32 * 80) + b_loff4;

    const int T = COUT / 32;
    int cur = 0;
    for (int it = 0; it < T; ++it) {
        if (it + 1 < T) CP_WAIT1(); else CP_WAIT0();
        __syncthreads();
        uint32_t sb = sbase + cur * 61440;
#pragma unroll
        for (int ks = 0; ks < 2; ks++) {
            uint32_t kboff = ks * 32;
            uint32_t bh[4][2], bl[4][2];
#pragma unroll
            for (int jp = 0; jp < 2; jp++) {
                uint32_t ba = sb + b_wbase + jp * (16 * 80) + kboff;
                uint32_t r[4];
                ldsm_x4(r, ba);
                bh[2 * jp][0] = r[0]; bh[2 * jp][1] = r[1];
                bh[2 * jp + 1][0] = r[2]; bh[2 * jp + 1][1] = r[3];
                ldsm_x4(r, ba + 10240);
                bl[2 * jp][0] = r[0]; bl[2 * jp][1] = r[1];
                bl[2 * jp + 1][0] = r[2]; bl[2 * jp + 1][1] = r[3];
            }
#pragma unroll
            for (int i = 0; i < 4; i++) {
                uint32_t aa = sb + a_wbase + i * (16 * 80) + kboff;
                uint32_t ah[4], al[4];
                ldsm_x4(ah, aa);
                ldsm_x4(al, aa + 20480);
#pragma unroll
                for (int j = 0; j < 4; j++) {
                    mma16816(acc[i][j], ah, bh[j]);
                    mma16816(acc[i][j], ah, bl[j]);
                    mma16816(acc[i][j], al, bh[j]);
                }
            }
        }
        if (it + 2 < T) loadG(it + 2, (cur + 2 >= 3) ? cur - 1 : cur + 2);
        cur = (cur + 1 == 3) ? 0 : cur + 1;
    }
    __syncthreads();

    float* Ds = reinterpret_cast<float*>(dsm);
#pragma unroll
    for (int i = 0; i < 4; i++) {
        int r0 = mw * 64 + i * 16 + lr;
#pragma unroll
        for (int j = 0; j < 4; j++) {
            int c = nw * 32 + j * 8 + lc;
            Ds[r0 * 129 + c] = acc[i][j][0];
            Ds[r0 * 129 + c + 1] = acc[i][j][1];
            Ds[(r0 + 8) * 129 + c] = acc[i][j][2];
            Ds[(r0 + 8) * 129 + c + 1] = acc[i][j][3];
        }
    }
    __syncthreads();
    {
        const float sc = 1.f / 64.f;
        int m = t >> 1, nh = (t & 1) * 64;
        float* So = g_S + (size_t)b * HW * HW + (size_t)(q0 + m) * HW + p0 + nh;
#pragma unroll
        for (int blk = 0; blk < 64; blk += 4) {
            float4 v4;
            float* vp = &v4.x;
#pragma unroll
            for (int j = 0; j < 4; j++) vp[j] = Ds[m * 129 + nh + blk + j] * sc;
            *reinterpret_cast<float4*>(So + blk) = v4;
        }
    }
}

// ---------------- row softmax; emits bf16 hi/lo probs ----------------
__global__ void __launch_bounds__(256) k_softmax() {
    const size_t row = blockIdx.x;
    const float* r = g_S + row * (size_t)HW;
    __nv_bfloat16* oh = g_Ah + row * (size_t)HW;
    __nv_bfloat16* ol = g_Al + row * (size_t)HW;
    __shared__ float buf[HW];
    __shared__ float red[256];
    int t = threadIdx.x;
    float m = -1e30f;
    for (int i = t; i < HW; i += 256) { float v = r[i]; buf[i] = v; m = fmaxf(m, v); }
    red[t] = m; __syncthreads();
    for (int s = 128; s > 0; s >>= 1) { if (t < s) red[t] = fmaxf(red[t], red[t + s]); __syncthreads(); }
    float mx = red[0]; __syncthreads();
    float s = 0.f;
    for (int i = t; i < HW; i += 256) { float e = expf(buf[i] - mx); buf[i] = e; s += e; }
    red[t] = s; __syncthreads();
    for (int o = 128; o > 0; o >>= 1) { if (t < o) red[t] += red[t + o]; __syncthreads(); }
    float inv = 1.f / red[0];
    for (int i = t; i < HW; i += 256) {
        float p = buf[i] * inv;
        __nv_bfloat16 h, l; splitf(p, h, l);
        oh[i] = h; ol[i] = l;
    }
}

// ---------------- HMMA L-GEMM: 128(c)x128(j), tri-buffer, trans-B x4 ----------
__global__ void __launch_bounds__(512, 1) k_lgemm2() {
    extern __shared__ __align__(16) char dsm[];
    const int b = blockIdx.y, j0g = blockIdx.x * 128;
    const int t = threadIdx.x, wid = t >> 5, lane = t & 31;
    const int mw = wid >> 2, nw = wid & 3;
    const uint32_t sbase = (uint32_t)__cvta_generic_to_shared(dsm);
    const __nv_bfloat16* Xh = g_x1h + (size_t)b * COUT * HW;
    const __nv_bfloat16* Xl = g_x1l + (size_t)b * COUT * HW;
    const __nv_bfloat16* Aph = g_Ah + (size_t)b * HW * HW;
    const __nv_bfloat16* Apl = g_Al + (size_t)b * HW * HW;

    float acc[2][4][4];
#pragma unroll
    for (int i = 0; i < 2; i++)
#pragma unroll
        for (int j = 0; j < 4; j++)
#pragma unroll
            for (int r = 0; r < 4; r++) acc[i][j][r] = 0.f;

    auto loadG = [&](int it, int buf) {
        int kc = it * 32;
        uint32_t base = sbase + buf * 37888;
        int c = t >> 2, cq = t & 3;
        const __nv_bfloat16* ah = Xh + (size_t)c * HW + kc + cq * 8;
        const __nv_bfloat16* al = Xl + (size_t)c * HW + kc + cq * 8;
        uint32_t da = base + c * 80 + cq * 16;
        cp16(da, ah, 16);
        cp16(da + 10240, al, 16);
        int k = t >> 4, jt = t & 15;
        const __nv_bfloat16* bh = Aph + (size_t)(kc + k) * HW + j0g + jt * 8;
        const __nv_bfloat16* bl = Apl + (size_t)(kc + k) * HW + j0g + jt * 8;
        uint32_t db = base + 20480 + k * 272 + jt * 16;
        cp16(db, bh, 16);
        cp16(db + 8704, bl, 16);
        CP_COMMIT();
    };

    loadG(0, 0);
    loadG(1, 1);

    const int lr = lane >> 2, lc = 2 * (lane & 3);
    const uint32_t a_loff = (uint32_t)(((lane & 7) + ((lane >> 3) & 1) * 8) * 80
                                       + (lane >> 4) * 16);
    const uint32_t a_wbase = (uint32_t)(mw * 32 * 80) + a_loff;
    const uint32_t bt_loff4 = (uint32_t)((lane & 15) * 272 + ((lane >> 4) & 1) * 16);

    const int T = HW / 32;
    int cur = 0;
    for (int it = 0; it < T; ++it) {
        if (it + 1 < T) CP_WAIT1(); else CP_WAIT0();
        __syncthreads();
        uint32_t sb = sbase + cur * 37888;
#pragma unroll
        for (int ks = 0; ks < 2; ks++) {
            uint32_t bh[4][2], bl[4][2];
#pragma unroll
            for (int jp = 0; jp < 2; jp++) {
                uint32_t ba = sb + 20480 + bt_loff4 + ks * (16 * 272)
                              + (nw * 32 + jp * 16) * 2;
                uint32_t r[4];
                ldsm_x4t(r, ba);
                bh[2 * jp][0] = r[0]; bh[2 * jp][1] = r[1];
                bh[2 * jp + 1][0] = r[2]; bh[2 * jp + 1][1] = r[3];
                ldsm_x4t(r, ba + 8704);
                bl[2 * jp][0] = r[0]; bl[2 * jp][1] = r[1];
                bl[2 * jp + 1][0] = r[2]; bl[2 * jp + 1][1] = r[3];
            }
#pragma unroll
            for (int i = 0; i < 2; i++) {
                uint32_t aa = sb + a_wbase + i * (16 * 80) + ks * 32;
                uint32_t ah[4], al[4];
                ldsm_x4(ah, aa);
                ldsm_x4(al, aa + 10240);
#pragma unroll
                for (int j = 0; j < 4; j++) {
                    mma16816(acc[i][j], ah, bh[j]);
                    mma16816(acc[i][j], ah, bl[j]);
                    mma16816(acc[i][j], al, bh[j]);
                }
            }
        }
        if (it + 2 < T) loadG(it + 2, (cur + 2 >= 3) ? cur - 1 : cur + 2);
        cur = (cur + 1 == 3) ? 0 : cur + 1;
    }
    __syncthreads();

    const float* xab = g_xa + (size_t)b * COUT * HW;
    float* Ds = reinterpret_cast<float*>(dsm);
#pragma unroll
    for (int i = 0; i < 2; i++) {
#pragma unroll
        for (int j = 0; j < 4; j++) {
            int c = mw * 32 + i * 16 + lr;
            int col = nw * 32 + j * 8 + lc;
            size_t i0 = (size_t)c * HW + j0g + col;
            size_t i8 = (size_t)(c + 8) * HW + j0g + col;
            float2 x0 = *reinterpret_cast<const float2*>(xab + i0);
            float2 x8 = *reinterpret_cast<const float2*>(xab + i8);
            Ds[col * 129 + c] = acc[i][j][0] + x0.x;
            Ds[(col + 1) * 129 + c] = acc[i][j][1] + x0.y;
            Ds[col * 129 + c + 8] = acc[i][j][2] + x8.x;
            Ds[(col + 1) * 129 + c + 8] = acc[i][j][3] + x8.y;
        }
    }
    __syncthreads();
    {
        int jj = t >> 2, c0q = (t & 3) * 32;
        size_t rowb = ((size_t)b * HW + j0g + jj) * COUT + c0q;
#pragma unroll
        for (int blk = 0; blk < 32; blk += 8) {
            __align__(16) unsigned short h8[8], l8[8];
#pragma unroll
            for (int j = 0; j < 8; j++) {
                float vv = Ds[jj * 129 + c0q + blk + j];
                __nv_bfloat16 h, l; splitf(vv, h, l);
                h8[j] = *reinterpret_cast<unsigned short*>(&h);
                l8[j] = *reinterpret_cast<unsigned short*>(&l);
            }
            *reinterpret_cast<uint4*>(g_oth + rowb + blk) = *reinterpret_cast<uint4*>(h8);
            *reinterpret_cast<uint4*>(g_otl + rowb + blk) = *reinterpret_cast<uint4*>(l8);
        }
    }
}

// ---------------- host launch ----------------
extern "C" void kernel_launch(void* const* d_in, const int* in_sizes, int n_in,
                              void* d_out, int out_size) {
    (void)in_sizes; (void)n_in; (void)out_size;
    const float* x       = (const float*)d_in[0];
    const float* conv1_w = (const float*)d_in[1];
    const float* conv1_b = (const float*)d_in[2];
    const float* conv2_w = (const float*)d_in[3];
    const float* conv2_b = (const float*)d_in[4];
    const float* cw_w1   = (const float*)d_in[5];
    const float* cw_b1   = (const float*)d_in[6];
    const float* cw_ln_g = (const float*)d_in[7];
    const float* cw_ln_b = (const float*)d_in[8];
    const float* cw_w2   = (const float*)d_in[9];
    const float* cw_b2   = (const float*)d_in[10];
    const float* aspp0_w = (const float*)d_in[11];
    const float* aspp0_g = (const float*)d_in[12];
    const float* aspp0_b = (const float*)d_in[13];
    const float* aspp1_w = (const float*)d_in[14];
    const float* aspp1_g = (const float*)d_in[15];
    const float* aspp1_b = (const float*)d_in[16];
    const float* aspp2_w = (const float*)d_in[17];
    const float* aspp2_g = (const float*)d_in[18];
    const float* aspp2_b = (const float*)d_in[19];
    const float* aspp3_w = (const float*)d_in[20];
    const float* aspp3_g = (const float*)d_in[21];
    const float* aspp3_b = (const float*)d_in[22];
    const float* asppp_w = (const float*)d_in[23];
    const float* asppp_g = (const float*)d_in[24];
    const float* asppp_b = (const float*)d_in[25];
    const float* proj_w  = (const float*)d_in[26];
    const float* proj_g  = (const float*)d_in[27];
    const float* proj_b  = (const float*)d_in[28];

    void* pv;
    __nv_bfloat16 *p_xth, *p_xtl, *p_xTh, *p_xTl, *p_cth, *p_ctl, *p_pth, *p_ptl;
    __nv_bfloat16 *p_w3h, *p_w3l, *p_a0h, *p_a0l, *p_pjh, *p_pjl, *p_c2h, *p_c2l, *p_c1h, *p_c1l;
    __nv_bfloat16 *p_oth, *p_otl;
    cudaGetSymbolAddress(&pv, g_xth);  p_xth  = (__nv_bfloat16*)pv;
    cudaGetSymbolAddress(&pv, g_xtl);  p_xtl  = (__nv_bfloat16*)pv;
    cudaGetSymbolAddress(&pv, g_xTh);  p_xTh  = (__nv_bfloat16*)pv;
    cudaGetSymbolAddress(&pv, g_xTl);  p_xTl  = (__nv_bfloat16*)pv;
    cudaGetSymbolAddress(&pv, g_cth);  p_cth  = (__nv_bfloat16*)pv;
    cudaGetSymbolAddress(&pv, g_ctl);  p_ctl  = (__nv_bfloat16*)pv;
    cudaGetSymbolAddress(&pv, g_pth);  p_pth  = (__nv_bfloat16*)pv;
    cudaGetSymbolAddress(&pv, g_ptl);  p_ptl  = (__nv_bfloat16*)pv;
    cudaGetSymbolAddress(&pv, g_w3h);  p_w3h  = (__nv_bfloat16*)pv;
    cudaGetSymbolAddress(&pv, g_w3l);  p_w3l  = (__nv_bfloat16*)pv;
    cudaGetSymbolAddress(&pv, g_a0h);  p_a0h  = (__nv_bfloat16*)pv;
    cudaGetSymbolAddress(&pv, g_a0l);  p_a0l  = (__nv_bfloat16*)pv;
    cudaGetSymbolAddress(&pv, g_pjh);  p_pjh  = (__nv_bfloat16*)pv;
    cudaGetSymbolAddress(&pv, g_pjl);  p_pjl  = (__nv_bfloat16*)pv;
    cudaGetSymbolAddress(&pv, g_c2h);  p_c2h  = (__nv_bfloat16*)pv;
    cudaGetSymbolAddress(&pv, g_c2l);  p_c2l  = (__nv_bfloat16*)pv;
    cudaGetSymbolAddress(&pv, g_c1h);  p_c1h  = (__nv_bfloat16*)pv;
    cudaGetSymbolAddress(&pv, g_c1l);  p_c1l  = (__nv_bfloat16*)pv;
    cudaGetSymbolAddress(&pv, g_oth);  p_oth  = (__nv_bfloat16*)pv;
    cudaGetSymbolAddress(&pv, g_otl);  p_otl  = (__nv_bfloat16*)pv;

    const int TRI_SMEM = 184320;
    const int C1_SMEM = 122880;
    cudaFuncSetAttribute(k_aspp, cudaFuncAttributeMaxDynamicSharedMemorySize, TRI_SMEM);
    cudaFuncSetAttribute(k_hgemm<1>, cudaFuncAttributeMaxDynamicSharedMemorySize, TRI_SMEM);
    cudaFuncSetAttribute(k_hgemm<2>, cudaFuncAttributeMaxDynamicSharedMemorySize, TRI_SMEM);
    cudaFuncSetAttribute(k_conv1, cudaFuncAttributeMaxDynamicSharedMemorySize, C1_SMEM);
    cudaFuncSetAttribute(k_sgemm2, cudaFuncAttributeMaxDynamicSharedMemorySize, TRI_SMEM);
    cudaFuncSetAttribute(k_lgemm2, cudaFuncAttributeMaxDynamicSharedMemorySize, 113664);

    dim3 gh(HW / 128, BATCH);

    AsppArgs aa;
    aa.wh[0] = p_a0h; aa.wl[0] = p_a0l; aa.g[0] = aspp0_g; aa.bt[0] = aspp0_b;
    aa.dil[0] = 0; aa.coff[0] = 0;
    aa.wh[1] = p_w3h; aa.wl[1] = p_w3l; aa.g[1] = aspp1_g; aa.bt[1] = aspp1_b;
    aa.dil[1] = 3; aa.coff[1] = 256;
    aa.wh[2] = p_w3h + 9 * 65536; aa.wl[2] = p_w3l + 9 * 65536;
    aa.g[2] = aspp2_g; aa.bt[2] = aspp2_b; aa.dil[2] = 6; aa.coff[2] = 512;
    aa.wh[3] = p_w3h + 18 * 65536; aa.wl[3] = p_w3l + 18 * 65536;
    aa.g[3] = aspp3_g; aa.bt[3] = aspp3_b; aa.dil[3] = 9; aa.coff[3] = 768;

    k_prep<<<3584, 256>>>(aspp1_w, aspp2_w, aspp3_w, aspp0_w, proj_w, conv2_w, conv1_w, x);
    k_cw<<<BATCH, 256>>>(cw_w1, cw_b1, cw_ln_g, cw_ln_b, cw_w2, cw_b2,
                         asppp_w, asppp_g, asppp_b);
    k_xcsplit<<<dim3(128, 8, BATCH), 256>>>(x);
    // merged ASPP branches (round-12 proven config)
    k_aspp<<<dim3(HW / 128, BATCH, 4), 512, TRI_SMEM>>>(aa, p_xth, p_xtl, p_cth, p_ctl);
    k_bp_cat<<<dim3(128, BATCH), 256>>>();
    // proj (K=1280) -> projT bf16 split
    k_hgemm<1><<<gh, 512, TRI_SMEM>>>(p_pjh, p_pjl, p_cth, p_ctl,
                                      proj_g, proj_b, nullptr, p_pth, p_ptl, CIN, 5 * CIN);
    // conv1 x2 merged in one launch (z: 0=x1 from xT, 1=xa from projT)
    k_conv1<<<dim3(HW / 128, BATCH, 2), 512, C1_SMEM>>>(p_c1h, p_c1l,
                                                        p_xTh, p_xTl, p_pth, p_ptl, conv1_b);
    // attention
    k_sgemm2<<<dim3(HW / 128, HW / 256, BATCH), 512, TRI_SMEM>>>();
    k_softmax<<<BATCH * HW, 256>>>();
    k_lgemm2<<<dim3(HW / 128, BATCH), 512, 113664>>>();
    // conv2 (HMMA bias epilogue, K=128)
    k_hgemm<2><<<gh, 512, TRI_SMEM>>>(p_c2h, p_c2l, p_oth, p_otl,
                                      conv2_b, conv2_b, (float*)d_out, nullptr, nullptr,
                                      0, COUT);
}

// round 16
// speedup vs baseline: 1.5228x; 1.0953x over previous
#include <cuda_runtime.h>
#include <cuda_bf16.h>
#include <cuda_fp16.h>
#include <math.h>
#include <stdint.h>

#define BATCH 4
#define CIN 256
#define COUT 128
#define HH 64
#define WW 64
#define HW 4096

typedef unsigned long long ull;

// ---------------- scratch (static device globals; no allocs) ----------------
__device__ float g_xa[BATCH * COUT * HW];
__device__ float g_S[(size_t)BATCH * HW * HW];
__device__ float g_avg[BATCH * CIN];
__device__ float g_mx[BATCH * CIN];
__device__ float g_s[BATCH * CIN];
__device__ float g_bp[BATCH * CIN];
// bf16 split operands (conv family)
__device__ __nv_bfloat16 g_xth[BATCH * HW * CIN];
__device__ __nv_bfloat16 g_xtl[BATCH * HW * CIN];
__device__ __nv_bfloat16 g_xTh[BATCH * HW * CIN];
__device__ __nv_bfloat16 g_xTl[BATCH * HW * CIN];
__device__ __nv_bfloat16 g_cth[(size_t)BATCH * HW * 5 * CIN];
__device__ __nv_bfloat16 g_ctl[(size_t)BATCH * HW * 5 * CIN];
__device__ __nv_bfloat16 g_pth[BATCH * HW * CIN];
__device__ __nv_bfloat16 g_ptl[BATCH * HW * CIN];
__device__ __nv_bfloat16 g_w3h[3 * 9 * CIN * CIN];
__device__ __nv_bfloat16 g_w3l[3 * 9 * CIN * CIN];
__device__ __nv_bfloat16 g_a0h[CIN * CIN];
__device__ __nv_bfloat16 g_a0l[CIN * CIN];
__device__ __nv_bfloat16 g_pjh[CIN * 5 * CIN];
__device__ __nv_bfloat16 g_pjl[CIN * 5 * CIN];
__device__ __nv_bfloat16 g_c2h[CIN * COUT];
__device__ __nv_bfloat16 g_c2l[CIN * COUT];
__device__ __nv_bfloat16 g_c1h[COUT * CIN];
__device__ __nv_bfloat16 g_c1l[COUT * CIN];
// attention operands (fp16)
__device__ __half g_x1tf[BATCH * HW * COUT];      // x1T fp16 [b][hw][c]
__device__ __half g_xatf[BATCH * HW * COUT];      // xaT fp16 [b][hw][c]
__device__ __half g_x1fh[BATCH * COUT * HW];      // x1 straight fp16 hi [b][c][hw]
__device__ __half g_x1fl[BATCH * COUT * HW];      // x1 straight fp16 lo
__device__ __half g_Af[(size_t)BATCH * HW * HW];  // softmax probs fp16 [b][q][p]
// conv2 input (bf16 split OT)
__device__ __nv_bfloat16 g_oth[BATCH * HW * COUT];
__device__ __nv_bfloat16 g_otl[BATCH * HW * COUT];

__device__ __forceinline__ float gelu_f(float x) {
    return 0.5f * x * (1.0f + erff(x * 0.70710678118654752440f));
}
__device__ __forceinline__ void splitf(float v, __nv_bfloat16& h, __nv_bfloat16& l) {
    h = __float2bfloat16(v);
    l = __float2bfloat16(v - __bfloat162float(h));
}
__device__ __forceinline__ void splitf16(float v, __half& h, __half& l) {
    h = __float2half(v);
    l = __float2half(v - __half2float(h));
}

// ---------------- HMMA m16n8k16 ----------------
__device__ __forceinline__ void mma16816(float* d, const uint32_t* a, const uint32_t* b) {
    asm volatile(
        "mma.sync.aligned.m16n8k16.row.col.f32.bf16.bf16.f32 "
        "{%0,%1,%2,%3}, {%4,%5,%6,%7}, {%8,%9}, {%0,%1,%2,%3};"
        : "+f"(d[0]), "+f"(d[1]), "+f"(d[2]), "+f"(d[3])
        : "r"(a[0]), "r"(a[1]), "r"(a[2]), "r"(a[3]), "r"(b[0]), "r"(b[1]));
}
__device__ __forceinline__ void mma16816f(float* d, const uint32_t* a, const uint32_t* b) {
    asm volatile(
        "mma.sync.aligned.m16n8k16.row.col.f32.f16.f16.f32 "
        "{%0,%1,%2,%3}, {%4,%5,%6,%7}, {%8,%9}, {%0,%1,%2,%3};"
        : "+f"(d[0]), "+f"(d[1]), "+f"(d[2]), "+f"(d[3])
        : "r"(a[0]), "r"(a[1]), "r"(a[2]), "r"(a[3]), "r"(b[0]), "r"(b[1]));
}
__device__ __forceinline__ void ldsm_x4(uint32_t* r, uint32_t addr) {
    asm volatile("ldmatrix.sync.aligned.m8n8.x4.shared.b16 {%0,%1,%2,%3}, [%4];"
                 : "=r"(r[0]), "=r"(r[1]), "=r"(r[2]), "=r"(r[3]) : "r"(addr));
}
__device__ __forceinline__ void ldsm_x4t(uint32_t* r, uint32_t addr) {
    asm volatile("ldmatrix.sync.aligned.m8n8.x4.trans.shared.b16 {%0,%1,%2,%3}, [%4];"
                 : "=r"(r[0]), "=r"(r[1]), "=r"(r[2]), "=r"(r[3]) : "r"(addr));
}

// ---------------- cp.async helpers ----------------
__device__ __forceinline__ void cp16(uint32_t d, const void* s, int ssz) {
    asm volatile("cp.async.ca.shared.global [%0], [%1], 16, %2;"
                 :: "r"(d), "l"(s), "r"(ssz) : "memory");
}
#define CP_COMMIT() asm volatile("cp.async.commit_group;" ::: "memory")
#define CP_WAIT1()  asm volatile("cp.async.wait_group 1;" ::: "memory")
#define CP_WAIT0()  asm volatile("cp.async.wait_group 0;" ::: "memory")

// ---------------- prep: weight splits + per-(b,c) stats ----------------
__global__ void k_prep(const float* __restrict__ w1, const float* __restrict__ w2,
                       const float* __restrict__ w3, const float* __restrict__ a0,
                       const float* __restrict__ pj, const float* __restrict__ c2,
                       const float* __restrict__ c1, const float* __restrict__ x) {
    if (blockIdx.x < 2560) {
        int e = blockIdx.x * 256 + threadIdx.x;
        if (e < 196608) {
            const float* srcs[3] = { w1, w2, w3 };
            int conv = e >> 16, mc = e & 65535, m = mc >> 8, c = mc & 255;
            const float* src = srcs[conv] + (size_t)m * 2304 + (size_t)c * 9;
            size_t dbase = (size_t)conv * 9 * 65536 + (size_t)m * 256 + c;
#pragma unroll
            for (int tap = 0; tap < 9; tap++) {
                __nv_bfloat16 h, l; splitf(src[tap], h, l);
                g_w3h[dbase + (size_t)tap * 65536] = h;
                g_w3l[dbase + (size_t)tap * 65536] = l;
            }
        } else if (e < 262144) {
            int i = e - 196608;
            __nv_bfloat16 h, l; splitf(a0[i], h, l);
            g_a0h[i] = h; g_a0l[i] = l;
        } else if (e < 589824) {
            int i = e - 262144;
            __nv_bfloat16 h, l; splitf(pj[i], h, l);
            g_pjh[i] = h; g_pjl[i] = l;
        } else if (e < 622592) {
            int i = e - 589824;
            __nv_bfloat16 h, l; splitf(c2[i], h, l);
            g_c2h[i] = h; g_c2l[i] = l;
        } else if (e < 655360) {
            int i = e - 622592;
            __nv_bfloat16 h, l; splitf(c1[i], h, l);
            g_c1h[i] = h; g_c1l[i] = l;
        }
    } else {
        int bc = blockIdx.x - 2560;
        const float* p = x + (size_t)bc * HW;
        int t = threadIdx.x;
        float s = 0.f, m = -1e30f;
        for (int i = t; i < HW; i += 256) { float v = p[i]; s += v; m = fmaxf(m, v); }
        __shared__ float ss[256], sm[256];
        ss[t] = s; sm[t] = m; __syncthreads();
        for (int o = 128; o > 0; o >>= 1) {
            if (t < o) { ss[t] += ss[t + o]; sm[t] = fmaxf(sm[t], sm[t + o]); }
            __syncthreads();
        }
        if (t == 0) { g_avg[bc] = ss[0] * (1.f / HW); g_mx[bc] = sm[0]; }
    }
}

// ---------------- channel weighting MLP + global-pool ASPP branch ----------------
__global__ void k_cw(const float* __restrict__ w1, const float* __restrict__ bb1,
                     const float* __restrict__ lg, const float* __restrict__ lb,
                     const float* __restrict__ w2, const float* __restrict__ bb2,
                     const float* __restrict__ apw, const float* __restrict__ apg,
                     const float* __restrict__ apb) {
    int b = blockIdx.x, t = threadIdx.x;
    __shared__ float o[CIN];
    __shared__ float h[COUT];
    __shared__ float red[256];
    __shared__ float gp[CIN];
    float avg = g_avg[b * CIN + t], mx = g_mx[b * CIN + t];
    o[t] = fabsf(avg - mx) * avg;
    __syncthreads();
    float hv = 0.f;
    if (t < COUT) {
        hv = bb1[t];
        const float* wr = w1 + t * CIN;
        for (int i = 0; i < CIN; i++) hv = fmaf(o[i], wr[i], hv);
    }
    red[t] = (t < COUT) ? hv : 0.f; __syncthreads();
    for (int s = 128; s > 0; s >>= 1) { if (t < s) red[t] += red[t + s]; __syncthreads(); }
    float mu = red[0] * (1.f / COUT); __syncthreads();
    float dv = (t < COUT) ? (hv - mu) : 0.f;
    red[t] = dv * dv; __syncthreads();
    for (int s = 128; s > 0; s >>= 1) { if (t < s) red[t] += red[t + s]; __syncthreads(); }
    float var = red[0] * (1.f / COUT); __syncthreads();
    if (t < COUT) h[t] = lg[t] * ((hv - mu) * rsqrtf(var + 1e-5f)) + lb[t];
    __syncthreads();
    float sv = bb2[t];
    const float* wr2 = w2 + t * COUT;
    for (int j = 0; j < COUT; j++) sv = fmaf(h[j], wr2[j], sv);
    float sig = 1.f / (1.f + expf(-sv));
    g_s[b * CIN + t] = sig;
    gp[t] = (1.f + sig) * avg;
    __syncthreads();
    float v = 0.f;
    const float* ar = apw + t * CIN;
    for (int i = 0; i < CIN; i++) v = fmaf(ar[i], gp[i], v);
    red[t] = v; __syncthreads();
    for (int s = 128; s > 0; s >>= 1) { if (t < s) red[t] += red[t + s]; __syncthreads(); }
    float mu2 = red[0] * (1.f / CIN); __syncthreads();
    float d2 = v - mu2; red[t] = d2 * d2; __syncthreads();
    for (int s = 128; s > 0; s >>= 1) { if (t < s) red[t] += red[t + s]; __syncthreads(); }
    float var2 = red[0] * (1.f / CIN); __syncthreads();
    float z = apg[t] * ((v - mu2) * rsqrtf(var2 + 1e-6f)) + apb[t];
    g_bp[b * CIN + t] = gelu_f(z);
}

// ---------------- xT / xcT split ----------------
__global__ void k_xcsplit(const float* __restrict__ x) {
    __shared__ float tile[32][33];
    int b = blockIdx.z, c0 = blockIdx.y * 32, h0 = blockIdx.x * 32;
    int t = threadIdx.x;
    const float* xb = x + ((size_t)b * CIN + c0) * HW + h0;
#pragma unroll
    for (int i = 0; i < 4; i++) {
        int r = (t >> 5) + 8 * i;
        tile[r][t & 31] = xb[(size_t)r * HW + (t & 31)];
    }
    __syncthreads();
#pragma unroll
    for (int i = 0; i < 4; i++) {
        int hr = (t >> 5) + 8 * i, cc = t & 31;
        float vr = tile[cc][hr];
        size_t idx = ((size_t)b * HW + h0 + hr) * CIN + c0 + cc;
        __nv_bfloat16 h, l;
        splitf(vr, h, l);
        g_xTh[idx] = h; g_xTl[idx] = l;
        float v = vr * (1.f + g_s[b * CIN + c0 + cc]);
        splitf(v, h, l);
        g_xth[idx] = h; g_xtl[idx] = l;
    }
}

// ---------------- bp broadcast into catT channels [1024,1280) ----------------
__global__ void k_bp_cat() {
    int b = blockIdx.y, h0 = blockIdx.x * 32;
    int c = threadIdx.x;
    __nv_bfloat16 h, l; splitf(g_bp[b * CIN + c], h, l);
    for (int r = 0; r < 32; r++) {
        size_t idx = ((size_t)b * HW + h0 + r) * 1280 + 1024 + c;
        g_cth[idx] = h; g_ctl[idx] = l;
    }
}

struct AsppArgs {
    const __nv_bfloat16* wh[4];
    const __nv_bfloat16* wl[4];
    const float* g[4];
    const float* bt[4];
    int dil[4];
    int coff[4];
};

// ---------------- merged ASPP HMMA kernel: 256x128 tile, 512 thr, tri-buffer, Bx4 ---
__global__ void __launch_bounds__(512, 1) k_aspp(
    AsppArgs A_, const __nv_bfloat16* __restrict__ Ihi, const __nv_bfloat16* __restrict__ Ilo,
    __nv_bfloat16* __restrict__ cth, __nv_bfloat16* __restrict__ ctl) {
    extern __shared__ __align__(16) char dsm[];
    __shared__ int s_tapn, s_tp[9], s_dy[9], s_dx[9];
    __shared__ float sgam[256], sbet[256], smean[128], srstd[128];
    __shared__ float red4[4][128];

    const int br = blockIdx.z, b = blockIdx.y, y = blockIdx.x;
    const int t = threadIdx.x, wid = t >> 5, lane = t & 31;
    const int mw = wid >> 2, nw = wid & 3;
    const uint32_t sbase = (uint32_t)__cvta_generic_to_shared(dsm);
    const __nv_bfloat16* Whi = A_.wh[br];
    const __nv_bfloat16* Wlo = A_.wl[br];
    const int dil = A_.dil[br], coff = A_.coff[br];

    if (t == 0) {
        if (dil == 0) {
            s_tapn = 1; s_tp[0] = 0; s_dy[0] = 0; s_dx[0] = 0;
        } else {
            int n = 0;
            for (int tap = 0; tap < 9; tap++) {
                int dy = (tap / 3 - 1) * dil;
                int y0 = y * 2 + dy, y1 = y * 2 + 1 + dy;
                if ((unsigned)y0 < 64u || (unsigned)y1 < 64u) {
                    s_tp[n] = tap; s_dy[n] = dy; s_dx[n] = (tap % 3 - 1) * dil; n++;
                }
            }
            s_tapn = n;
        }
    }
    if (t < 256) { sgam[t] = A_.g[br][t]; sbet[t] = A_.bt[br][t]; }
    __syncthreads();

    const int T = s_tapn * 8;
    const __nv_bfloat16* Ib_hi = Ihi + (size_t)b * HW * CIN;
    const __nv_bfloat16* Ib_lo = Ilo + (size_t)b * HW * CIN;

    float acc[4][4][4];
#pragma unroll
    for (int i = 0; i < 4; i++)
#pragma unroll
        for (int j = 0; j < 4; j++)
#pragma unroll
            for (int r = 0; r < 4; r++) acc[i][j][r] = 0.f;

    auto loadG = [&](int it, int buf) {
        int tap_i = it >> 3;
        int kc = (it & 7) * 32;
        uint32_t base = sbase + buf * 61440;
        int arow = t >> 1, ak = (t & 1) * 16;
        int grow = s_tp[tap_i] * 256 + arow;
        const __nv_bfloat16* ah = Whi + (size_t)grow * CIN + kc + ak;
        const __nv_bfloat16* al = Wlo + (size_t)grow * CIN + kc + ak;
        uint32_t da = base + arow * 80 + ak * 2;
        cp16(da, ah, 16);
        cp16(da + 16, ah + 8, 16);
        cp16(da + 20480, al, 16);
        cp16(da + 20480 + 16, al + 8, 16);
        int n = t >> 2, q = t & 3;
        int hw; int ok = 16;
        int yy = y * 2 + (n >> 6) + s_dy[tap_i];
        int xx = (n & 63) + s_dx[tap_i];
        if ((unsigned)yy < 64u && (unsigned)xx < 64u) hw = yy * 64 + xx;
        else { hw = 0; ok = (dil == 0) ? 16 : 0; }
        if (dil == 0) hw = y * 128 + n;
        uint32_t db = base + 40960 + n * 80 + q * 16;
        cp16(db, Ib_hi + (size_t)hw * CIN + kc + q * 8, ok);
        cp16(db + 10240, Ib_lo + (size_t)hw * CIN + kc + q * 8, ok);
        CP_COMMIT();
    };

    loadG(0, 0);
    if (T > 1) loadG(1, 1);

    const int lr = lane >> 2, lc = 2 * (lane & 3);
    const uint32_t a_loff = (uint32_t)(((lane & 7) + ((lane >> 3) & 1) * 8) * 80
                                       + (lane >> 4) * 16);
    const uint32_t b_loff4 = (uint32_t)(((lane & 7) + ((lane >> 4) & 1) * 8) * 80
                                        + ((lane >> 3) & 1) * 16);
    const uint32_t a_wbase = (uint32_t)(mw * 64 * 80) + a_loff;
    const uint32_t b_wbase = 40960u + (uint32_t)(nw * 32 * 80) + b_loff4;

    int cur = 0;
    for (int it = 0; it < T; ++it) {
        if (it + 1 < T) CP_WAIT1(); else CP_WAIT0();
        __syncthreads();
        uint32_t sb = sbase + cur * 61440;
#pragma unroll
        for (int ks = 0; ks < 2; ks++) {
            uint32_t kboff = ks * 32;
            uint32_t bh[4][2], bl[4][2];
#pragma unroll
            for (int jp = 0; jp < 2; jp++) {
                uint32_t ba = sb + b_wbase + jp * (16 * 80) + kboff;
                uint32_t r[4];
                ldsm_x4(r, ba);
                bh[2 * jp][0] = r[0]; bh[2 * jp][1] = r[1];
                bh[2 * jp + 1][0] = r[2]; bh[2 * jp + 1][1] = r[3];
                ldsm_x4(r, ba + 10240);
                bl[2 * jp][0] = r[0]; bl[2 * jp][1] = r[1];
                bl[2 * jp + 1][0] = r[2]; bl[2 * jp + 1][1] = r[3];
            }
#pragma unroll
            for (int i = 0; i < 4; i++) {
                uint32_t aa = sb + a_wbase + i * (16 * 80) + kboff;
                uint32_t ah[4], al[4];
                ldsm_x4(ah, aa);
                ldsm_x4(al, aa + 20480);
#pragma unroll
                for (int j = 0; j < 4; j++) {
                    mma16816(acc[i][j], ah, bh[j]);
                    mma16816(acc[i][j], ah, bl[j]);
                    mma16816(acc[i][j], al, bh[j]);
                }
            }
        }
        if (it + 2 < T) loadG(it + 2, (cur + 2 >= 3) ? cur - 1 : cur + 2);
        cur = (cur + 1 == 3) ? 0 : cur + 1;
    }
    __syncthreads();

    float* Ds = reinterpret_cast<float*>(dsm);
#pragma unroll
    for (int i = 0; i < 4; i++) {
        int r0 = mw * 64 + i * 16 + lr;
#pragma unroll
        for (int j = 0; j < 4; j++) {
            int c = nw * 32 + j * 8 + lc;
            Ds[r0 * 129 + c] = acc[i][j][0];
            Ds[r0 * 129 + c + 1] = acc[i][j][1];
            Ds[(r0 + 8) * 129 + c] = acc[i][j][2];
            Ds[(r0 + 8) * 129 + c + 1] = acc[i][j][3];
        }
    }
    __syncthreads();
    {
        int n = t & 127, p = t >> 7;
        float s = 0.f;
        for (int mm = p * 64; mm < p * 64 + 64; mm++) s += Ds[mm * 129 + n];
        red4[p][n] = s;
        __syncthreads();
        if (t < 128)
            smean[t] = (red4[0][t] + red4[1][t] + red4[2][t] + red4[3][t]) * (1.f / 256.f);
        __syncthreads();
        float mu = smean[n];
        s = 0.f;
        for (int mm = p * 64; mm < p * 64 + 64; mm++) {
            float d = Ds[mm * 129 + n] - mu; s += d * d;
        }
        red4[p][n] = s;
        __syncthreads();
        if (t < 128)
            srstd[t] = rsqrtf((red4[0][t] + red4[1][t] + red4[2][t] + red4[3][t]) * (1.f / 256.f) + 1e-6f);
        __syncthreads();
    }
    {
        int n2 = t >> 2, m0q = (t & 3) * 64;
        float mu = smean[n2], rs = srstd[n2];
        size_t rowb = ((size_t)b * HW + y * 128 + n2) * 1280 + coff + m0q;
#pragma unroll
        for (int blk = 0; blk < 64; blk += 8) {
            __align__(16) unsigned short h8[8], l8[8];
#pragma unroll
            for (int j = 0; j < 8; j++) {
                int m = m0q + blk + j;
                float vv = gelu_f((Ds[m * 129 + n2] - mu) * rs * sgam[m] + sbet[m]);
                __nv_bfloat16 h, l; splitf(vv, h, l);
                h8[j] = *reinterpret_cast<unsigned short*>(&h);
                l8[j] = *reinterpret_cast<unsigned short*>(&l);
            }
            *reinterpret_cast<uint4*>(cth + rowb + blk) = *reinterpret_cast<uint4*>(h8);
            *reinterpret_cast<uint4*>(ctl + rowb + blk) = *reinterpret_cast<uint4*>(l8);
        }
    }
}

// ---------------- HMMA GEMM M=256 (proj EPI1 -> bf16T split / conv2 EPI2 -> f32) ----
template <int EPI>
__global__ void __launch_bounds__(512, 1) k_hgemm(
    const __nv_bfloat16* __restrict__ Whi, const __nv_bfloat16* __restrict__ Wlo,
    const __nv_bfloat16* __restrict__ Ihi, const __nv_bfloat16* __restrict__ Ilo,
    const float* __restrict__ gam, const float* __restrict__ bet,
    float* __restrict__ outF, __nv_bfloat16* __restrict__ bth, __nv_bfloat16* __restrict__ btl,
    int ostride, int Kc) {
    extern __shared__ __align__(16) char dsm[];
    __shared__ float sgam[256], sbet[256], smean[128], srstd[128];
    __shared__ float red4[4][128];

    const int b = blockIdx.y, y = blockIdx.x;
    const int t = threadIdx.x, wid = t >> 5, lane = t & 31;
    const int mw = wid >> 2, nw = wid & 3;
    const uint32_t sbase = (uint32_t)__cvta_generic_to_shared(dsm);

    if (t < 256) { sgam[t] = gam[t]; sbet[t] = bet[t]; }
    __syncthreads();

    const int T = Kc / 32;
    const __nv_bfloat16* Ib_hi = Ihi + (size_t)b * HW * Kc;
    const __nv_bfloat16* Ib_lo = Ilo + (size_t)b * HW * Kc;

    float acc[4][4][4];
#pragma unroll
    for (int i = 0; i < 4; i++)
#pragma unroll
        for (int j = 0; j < 4; j++)
#pragma unroll
            for (int r = 0; r < 4; r++) acc[i][j][r] = 0.f;

    auto loadG = [&](int it, int buf) {
        int kc = it * 32;
        uint32_t base = sbase + buf * 61440;
        int arow = t >> 1, ak = (t & 1) * 16;
        const __nv_bfloat16* ah = Whi + (size_t)arow * Kc + kc + ak;
        const __nv_bfloat16* al = Wlo + (size_t)arow * Kc + kc + ak;
        uint32_t da = base + arow * 80 + ak * 2;
        cp16(da, ah, 16);
        cp16(da + 16, ah + 8, 16);
        cp16(da + 20480, al, 16);
        cp16(da + 20480 + 16, al + 8, 16);
        int n = t >> 2, q = t & 3;
        int hw = y * 128 + n;
        uint32_t db = base + 40960 + n * 80 + q * 16;
        cp16(db, Ib_hi + (size_t)hw * Kc + kc + q * 8, 16);
        cp16(db + 10240, Ib_lo + (size_t)hw * Kc + kc + q * 8, 16);
        CP_COMMIT();
    };

    loadG(0, 0);
    if (T > 1) loadG(1, 1);

    const int lr = lane >> 2, lc = 2 * (lane & 3);
    const uint32_t a_loff = (uint32_t)(((lane & 7) + ((lane >> 3) & 1) * 8) * 80
                                       + (lane >> 4) * 16);
    const uint32_t b_loff4 = (uint32_t)(((lane & 7) + ((lane >> 4) & 1) * 8) * 80
                                        + ((lane >> 3) & 1) * 16);
    const uint32_t a_wbase = (uint32_t)(mw * 64 * 80) + a_loff;
    const uint32_t b_wbase = 40960u + (uint32_t)(nw * 32 * 80) + b_loff4;

    int cur = 0;
    for (int it = 0; it < T; ++it) {
        if (it + 1 < T) CP_WAIT1(); else CP_WAIT0();
        __syncthreads();
        uint32_t sb = sbase + cur * 61440;
#pragma unroll
        for (int ks = 0; ks < 2; ks++) {
            uint32_t kboff = ks * 32;
            uint32_t bh[4][2], bl[4][2];
#pragma unroll
            for (int jp = 0; jp < 2; jp++) {
                uint32_t ba = sb + b_wbase + jp * (16 * 80) + kboff;
                uint32_t r[4];
                ldsm_x4(r, ba);
                bh[2 * jp][0] = r[0]; bh[2 * jp][1] = r[1];
                bh[2 * jp + 1][0] = r[2]; bh[2 * jp + 1][1] = r[3];
                ldsm_x4(r, ba + 10240);
                bl[2 * jp][0] = r[0]; bl[2 * jp][1] = r[1];
                bl[2 * jp + 1][0] = r[2]; bl[2 * jp + 1][1] = r[3];
            }
#pragma unroll
            for (int i = 0; i < 4; i++) {
                uint32_t aa = sb + a_wbase + i * (16 * 80) + kboff;
                uint32_t ah[4], al[4];
                ldsm_x4(ah, aa);
                ldsm_x4(al, aa + 20480);
#pragma unroll
                for (int j = 0; j < 4; j++) {
                    mma16816(acc[i][j], ah, bh[j]);
                    mma16816(acc[i][j], ah, bl[j]);
                    mma16816(acc[i][j], al, bh[j]);
                }
            }
        }
        if (it + 2 < T) loadG(it + 2, (cur + 2 >= 3) ? cur - 1 : cur + 2);
        cur = (cur + 1 == 3) ? 0 : cur + 1;
    }
    __syncthreads();

    float* Ds = reinterpret_cast<float*>(dsm);
#pragma unroll
    for (int i = 0; i < 4; i++) {
        int r0 = mw * 64 + i * 16 + lr;
#pragma unroll
        for (int j = 0; j < 4; j++) {
            int c = nw * 32 + j * 8 + lc;
            Ds[r0 * 129 + c] = acc[i][j][0];
            Ds[r0 * 129 + c + 1] = acc[i][j][1];
            Ds[(r0 + 8) * 129 + c] = acc[i][j][2];
            Ds[(r0 + 8) * 129 + c + 1] = acc[i][j][3];
        }
    }
    __syncthreads();
    if (EPI == 1) {
        int n = t & 127, p = t >> 7;
        float s = 0.f;
        for (int mm = p * 64; mm < p * 64 + 64; mm++) s += Ds[mm * 129 + n];
        red4[p][n] = s;
        __syncthreads();
        if (t < 128)
            smean[t] = (red4[0][t] + red4[1][t] + red4[2][t] + red4[3][t]) * (1.f / 256.f);
        __syncthreads();
        float mu = smean[n];
        s = 0.f;
        for (int mm = p * 64; mm < p * 64 + 64; mm++) {
            float d = Ds[mm * 129 + n] - mu; s += d * d;
        }
        red4[p][n] = s;
        __syncthreads();
        if (t < 128)
            srstd[t] = rsqrtf((red4[0][t] + red4[1][t] + red4[2][t] + red4[3][t]) * (1.f / 256.f) + 1e-6f);
        __syncthreads();
        int n2 = t >> 2, m0q = (t & 3) * 64;
        float mu2 = smean[n2], rs = srstd[n2];
        size_t rowb = ((size_t)b * HW + y * 128 + n2) * ostride + m0q;
#pragma unroll
        for (int blk = 0; blk < 64; blk += 8) {
            __align__(16) unsigned short h8[8], l8[8];
#pragma unroll
            for (int j = 0; j < 8; j++) {
                int m = m0q + blk + j;
                float vv = gelu_f((Ds[m * 129 + n2] - mu2) * rs * sgam[m] + sbet[m]);
                __nv_bfloat16 h, l; splitf(vv, h, l);
                h8[j] = *reinterpret_cast<unsigned short*>(&h);
                l8[j] = *reinterpret_cast<unsigned short*>(&l);
            }
            *reinterpret_cast<uint4*>(bth + rowb + blk) = *reinterpret_cast<uint4*>(h8);
            *reinterpret_cast<uint4*>(btl + rowb + blk) = *reinterpret_cast<uint4*>(l8);
        }
    } else {
        int m = t >> 1, nh = (t & 1) * 64;
        float bias = sgam[m];
        size_t ob = ((size_t)b * CIN + m) * HW + y * 128 + nh;
#pragma unroll
        for (int blk = 0; blk < 64; blk += 4) {
            float4 v4;
            float* vp = &v4.x;
#pragma unroll
            for (int j = 0; j < 4; j++) vp[j] = Ds[m * 129 + nh + blk + j] + bias;
            *reinterpret_cast<float4*>(outF + ob + blk) = v4;
        }
    }
}

// ---------------- HMMA conv1 merged: z=0 -> x1 (fp16 T + fp16 split straight),
//                  z=1 -> xa (fp16 T + straight fp32). 128x128 tile, K=256. ------
__global__ void __launch_bounds__(512, 1) k_conv1(
    const __nv_bfloat16* __restrict__ Whi, const __nv_bfloat16* __restrict__ Wlo,
    const __nv_bfloat16* __restrict__ I0h, const __nv_bfloat16* __restrict__ I0l,
    const __nv_bfloat16* __restrict__ I1h, const __nv_bfloat16* __restrict__ I1l,
    const float* __restrict__ bias) {
    extern __shared__ __align__(16) char dsm[];
    __shared__ float sb2[128];
    const int zb = blockIdx.z, b = blockIdx.y, y = blockIdx.x;
    const int t = threadIdx.x, wid = t >> 5, lane = t & 31;
    const int mw = wid >> 2, nw = wid & 3;
    const uint32_t sbase = (uint32_t)__cvta_generic_to_shared(dsm);

    if (t < 128) sb2[t] = bias[t];
    __syncthreads();

    const __nv_bfloat16* Ib_hi = (zb ? I1h : I0h) + (size_t)b * HW * CIN;
    const __nv_bfloat16* Ib_lo = (zb ? I1l : I0l) + (size_t)b * HW * CIN;

    float acc[2][4][4];
#pragma unroll
    for (int i = 0; i < 2; i++)
#pragma unroll
        for (int j = 0; j < 4; j++)
#pragma unroll
            for (int r = 0; r < 4; r++) acc[i][j][r] = 0.f;

    auto loadG = [&](int it, int buf) {
        int kc = it * 32;
        uint32_t base = sbase + buf * 40960;
        int r = t >> 2, q = t & 3;
        cp16(base + r * 80 + q * 16, Whi + (size_t)r * CIN + kc + q * 8, 16);
        cp16(base + 10240 + r * 80 + q * 16, Wlo + (size_t)r * CIN + kc + q * 8, 16);
        int hw = y * 128 + r;
        cp16(base + 20480 + r * 80 + q * 16, Ib_hi + (size_t)hw * CIN + kc + q * 8, 16);
        cp16(base + 30720 + r * 80 + q * 16, Ib_lo + (size_t)hw * CIN + kc + q * 8, 16);
        CP_COMMIT();
    };

    loadG(0, 0);
    loadG(1, 1);

    const int lr = lane >> 2, lc = 2 * (lane & 3);
    const uint32_t a_loff = (uint32_t)(((lane & 7) + ((lane >> 3) & 1) * 8) * 80
                                       + (lane >> 4) * 16);
    const uint32_t b_loff4 = (uint32_t)(((lane & 7) + ((lane >> 4) & 1) * 8) * 80
                                        + ((lane >> 3) & 1) * 16);
    const uint32_t a_wbase = (uint32_t)(mw * 32 * 80) + a_loff;
    const uint32_t b_wbase = 20480u + (uint32_t)(nw * 32 * 80) + b_loff4;

    const int T = CIN / 32;
    int cur = 0;
    for (int it = 0; it < T; ++it) {
        if (it + 1 < T) CP_WAIT1(); else CP_WAIT0();
        __syncthreads();
        uint32_t sb = sbase + cur * 40960;
#pragma unroll
        for (int ks = 0; ks < 2; ks++) {
            uint32_t kboff = ks * 32;
            uint32_t bh[4][2], bl[4][2];
#pragma unroll
            for (int jp = 0; jp < 2; jp++) {
                uint32_t ba = sb + b_wbase + jp * (16 * 80) + kboff;
                uint32_t r[4];
                ldsm_x4(r, ba);
                bh[2 * jp][0] = r[0]; bh[2 * jp][1] = r[1];
                bh[2 * jp + 1][0] = r[2]; bh[2 * jp + 1][1] = r[3];
                ldsm_x4(r, ba + 10240);
                bl[2 * jp][0] = r[0]; bl[2 * jp][1] = r[1];
                bl[2 * jp + 1][0] = r[2]; bl[2 * jp + 1][1] = r[3];
            }
#pragma unroll
            for (int i = 0; i < 2; i++) {
                uint32_t aa = sb + a_wbase + i * (16 * 80) + kboff;
                uint32_t ah[4], al[4];
                ldsm_x4(ah, aa);
                ldsm_x4(al, aa + 10240);
#pragma unroll
                for (int j = 0; j < 4; j++) {
                    mma16816(acc[i][j], ah, bh[j]);
                    mma16816(acc[i][j], ah, bl[j]);
                    mma16816(acc[i][j], al, bh[j]);
                }
            }
        }
        if (it + 2 < T) loadG(it + 2, (cur + 2 >= 3) ? cur - 1 : cur + 2);
        cur = (cur + 1 == 3) ? 0 : cur + 1;
    }
    __syncthreads();

    float* Ds = reinterpret_cast<float*>(dsm);
#pragma unroll
    for (int i = 0; i < 2; i++) {
        int r0 = mw * 32 + i * 16 + lr;
#pragma unroll
        for (int j = 0; j < 4; j++) {
            int c = nw * 32 + j * 8 + lc;
            Ds[r0 * 129 + c] = acc[i][j][0] + sb2[r0];
            Ds[r0 * 129 + c + 1] = acc[i][j][1] + sb2[r0];
            Ds[(r0 + 8) * 129 + c] = acc[i][j][2] + sb2[r0 + 8];
            Ds[(r0 + 8) * 129 + c + 1] = acc[i][j][3] + sb2[r0 + 8];
        }
    }
    __syncthreads();
    // transposed single fp16
    {
        int n2 = t >> 2, m0 = (t & 3) * 32;
        __half* th = zb ? g_xatf : g_x1tf;
        size_t rowb = ((size_t)b * HW + y * 128 + n2) * COUT + m0;
#pragma unroll
        for (int blk = 0; blk < 32; blk += 8) {
            __align__(16) unsigned short h8[8];
#pragma unroll
            for (int j = 0; j < 8; j++) {
                __half h = __float2half(Ds[(m0 + blk + j) * 129 + n2]);
                h8[j] = *reinterpret_cast<unsigned short*>(&h);
            }
            *reinterpret_cast<uint4*>(th + rowb + blk) = *reinterpret_cast<uint4*>(h8);
        }
    }
    // straight
    {
        int m = t >> 2, nh = (t & 3) * 32;
        size_t ob = ((size_t)b * COUT + m) * HW + y * 128 + nh;
        if (zb) {
#pragma unroll
            for (int blk = 0; blk < 32; blk += 4) {
                float4 v4;
                float* vp = &v4.x;
#pragma unroll
                for (int j = 0; j < 4; j++) vp[j] = Ds[m * 129 + nh + blk + j];
                *reinterpret_cast<float4*>(g_xa + ob + blk) = v4;
            }
        } else {
#pragma unroll
            for (int blk = 0; blk < 32; blk += 8) {
                __align__(16) unsigned short h8[8], l8[8];
#pragma unroll
                for (int j = 0; j < 8; j++) {
                    __half h, l; splitf16(Ds[m * 129 + nh + blk + j], h, l);
                    h8[j] = *reinterpret_cast<unsigned short*>(&h);
                    l8[j] = *reinterpret_cast<unsigned short*>(&l);
                }
                *reinterpret_cast<uint4*>(g_x1fh + ob + blk) = *reinterpret_cast<uint4*>(h8);
                *reinterpret_cast<uint4*>(g_x1fl + ob + blk) = *reinterpret_cast<uint4*>(l8);
            }
        }
    }
}

// ---------------- HMMA S-GEMM fp16 1-pass: 256(q)x128(p), tri-buffer, Bx4 ----------
__global__ void __launch_bounds__(512, 1) k_sgemm2() {
    extern __shared__ __align__(16) char dsm[];
    const int b = blockIdx.z, q0 = blockIdx.y * 256, p0 = blockIdx.x * 128;
    const int t = threadIdx.x, wid = t >> 5, lane = t & 31;
    const int mw = wid >> 2, nw = wid & 3;
    const uint32_t sbase = (uint32_t)__cvta_generic_to_shared(dsm);
    const __half* Q = g_xatf + (size_t)b * HW * COUT;
    const __half* P = g_x1tf + (size_t)b * HW * COUT;

    float acc[4][4][4];
#pragma unroll
    for (int i = 0; i < 4; i++)
#pragma unroll
        for (int j = 0; j < 4; j++)
#pragma unroll
            for (int r = 0; r < 4; r++) acc[i][j][r] = 0.f;

    // per buf (30720B): A 256x80 (20480), B 128x80 (10240)
    auto loadG = [&](int it, int buf) {
        int kc = it * 32;
        uint32_t base = sbase + buf * 30720;
        int arow = t >> 1, ak = (t & 1) * 16;
        const __half* ap = Q + (size_t)(q0 + arow) * COUT + kc + ak;
        uint32_t da = base + arow * 80 + ak * 2;
        cp16(da, ap, 16);
        cp16(da + 16, ap + 8, 16);
        int n = t >> 2, q = t & 3;
        cp16(base + 20480 + n * 80 + q * 16, P + (size_t)(p0 + n) * COUT + kc + q * 8, 16);
        CP_COMMIT();
    };

    loadG(0, 0);
    loadG(1, 1);

    const int lr = lane >> 2, lc = 2 * (lane & 3);
    const uint32_t a_loff = (uint32_t)(((lane & 7) + ((lane >> 3) & 1) * 8) * 80
                                       + (lane >> 4) * 16);
    const uint32_t b_loff4 = (uint32_t)(((lane & 7) + ((lane >> 4) & 1) * 8) * 80
                                        + ((lane >> 3) & 1) * 16);
    const uint32_t a_wbase = (uint32_t)(mw * 64 * 80) + a_loff;
    const uint32_t b_wbase = 20480u + (uint32_t)(nw * 32 * 80) + b_loff4;

    const int T = COUT / 32;
    int cur = 0;
    for (int it = 0; it < T; ++it) {
        if (it + 1 < T) CP_WAIT1(); else CP_WAIT0();
        __syncthreads();
        uint32_t sb = sbase + cur * 30720;
#pragma unroll
        for (int ks = 0; ks < 2; ks++) {
            uint32_t kboff = ks * 32;
            uint32_t bh[4][2];
#pragma unroll
            for (int jp = 0; jp < 2; jp++) {
                uint32_t ba = sb + b_wbase + jp * (16 * 80) + kboff;
                uint32_t r[4];
                ldsm_x4(r, ba);
                bh[2 * jp][0] = r[0]; bh[2 * jp][1] = r[1];
                bh[2 * jp + 1][0] = r[2]; bh[2 * jp + 1][1] = r[3];
            }
#pragma unroll
            for (int i = 0; i < 4; i++) {
                uint32_t aa = sb + a_wbase + i * (16 * 80) + kboff;
                uint32_t ah[4];
                ldsm_x4(ah, aa);
#pragma unroll
                for (int j = 0; j < 4; j++) mma16816f(acc[i][j], ah, bh[j]);
            }
        }
        if (it + 2 < T) loadG(it + 2, (cur + 2 >= 3) ? cur - 1 : cur + 2);
        cur = (cur + 1 == 3) ? 0 : cur + 1;
    }
    __syncthreads();

    float* Ds = reinterpret_cast<float*>(dsm);
#pragma unroll
    for (int i = 0; i < 4; i++) {
        int r0 = mw * 64 + i * 16 + lr;
#pragma unroll
        for (int j = 0; j < 4; j++) {
            int c = nw * 32 + j * 8 + lc;
            Ds[r0 * 129 + c] = acc[i][j][0];
            Ds[r0 * 129 + c + 1] = acc[i][j][1];
            Ds[(r0 + 8) * 129 + c] = acc[i][j][2];
            Ds[(r0 + 8) * 129 + c + 1] = acc[i][j][3];
        }
    }
    __syncthreads();
    {
        const float sc = 1.f / 64.f;
        int m = t >> 1, nh = (t & 1) * 64;
        float* So = g_S + (size_t)b * HW * HW + (size_t)(q0 + m) * HW + p0 + nh;
#pragma unroll
        for (int blk = 0; blk < 64; blk += 4) {
            float4 v4;
            float* vp = &v4.x;
#pragma unroll
            for (int j = 0; j < 4; j++) vp[j] = Ds[m * 129 + nh + blk + j] * sc;
            *reinterpret_cast<float4*>(So + blk) = v4;
        }
    }
}

// ---------------- row softmax; emits fp16 probs ----------------
__global__ void __launch_bounds__(256) k_softmax() {
    const size_t row = blockIdx.x;
    const float* r = g_S + row * (size_t)HW;
    __half* oa = g_Af + row * (size_t)HW;
    __shared__ float buf[HW];
    __shared__ float red[256];
    int t = threadIdx.x;
    float m = -1e30f;
    for (int i = t; i < HW; i += 256) { float v = r[i]; buf[i] = v; m = fmaxf(m, v); }
    red[t] = m; __syncthreads();
    for (int s = 128; s > 0; s >>= 1) { if (t < s) red[t] = fmaxf(red[t], red[t + s]); __syncthreads(); }
    float mx = red[0]; __syncthreads();
    float s = 0.f;
    for (int i = t; i < HW; i += 256) { float e = expf(buf[i] - mx); buf[i] = e; s += e; }
    red[t] = s; __syncthreads();
    for (int o = 128; o > 0; o >>= 1) { if (t < o) red[t] += red[t + o]; __syncthreads(); }
    float inv = 1.f / red[0];
    for (int i = t; i < HW; i += 256) oa[i] = __float2half(buf[i] * inv);
}

// ---------------- HMMA L-GEMM fp16 2-pass: 128(c)x128(j), tri-buffer, trans-B x4 ----
__global__ void __launch_bounds__(512, 1) k_lgemm2() {
    extern __shared__ __align__(16) char dsm[];
    const int b = blockIdx.y, j0g = blockIdx.x * 128;
    const int t = threadIdx.x, wid = t >> 5, lane = t & 31;
    const int mw = wid >> 2, nw = wid & 3;
    const uint32_t sbase = (uint32_t)__cvta_generic_to_shared(dsm);
    const __half* Xh = g_x1fh + (size_t)b * COUT * HW;
    const __half* Xl = g_x1fl + (size_t)b * COUT * HW;
    const __half* Ap = g_Af + (size_t)b * HW * HW;

    float acc[2][4][4];
#pragma unroll
    for (int i = 0; i < 2; i++)
#pragma unroll
        for (int j = 0; j < 4; j++)
#pragma unroll
            for (int r = 0; r < 4; r++) acc[i][j][r] = 0.f;

    // per buf (29184B): Ah 0 (128x80), Al 10240, B 20480 (32x272)
    auto loadG = [&](int it, int buf) {
        int kc = it * 32;
        uint32_t base = sbase + buf * 29184;
        int c = t >> 2, cq = t & 3;
        uint32_t da = base + c * 80 + cq * 16;
        cp16(da, Xh + (size_t)c * HW + kc + cq * 8, 16);
        cp16(da + 10240, Xl + (size_t)c * HW + kc + cq * 8, 16);
        int k = t >> 4, jt = t & 15;
        cp16(base + 20480 + k * 272 + jt * 16,
             Ap + (size_t)(kc + k) * HW + j0g + jt * 8, 16);
        CP_COMMIT();
    };

    loadG(0, 0);
    loadG(1, 1);

    const int lr = lane >> 2, lc = 2 * (lane & 3);
    const uint32_t a_loff = (uint32_t)(((lane & 7) + ((lane >> 3) & 1) * 8) * 80
                                       + (lane >> 4) * 16);
    const uint32_t a_wbase = (uint32_t)(mw * 32 * 80) + a_loff;
    const uint32_t bt_loff4 = (uint32_t)((lane & 15) * 272 + ((lane >> 4) & 1) * 16);

    const int T = HW / 32;
    int cur = 0;
    for (int it = 0; it < T; ++it) {
        if (it + 1 < T) CP_WAIT1(); else CP_WAIT0();
        __syncthreads();
        uint32_t sb = sbase + cur * 29184;
#pragma unroll
        for (int ks = 0; ks < 2; ks++) {
            uint32_t bh[4][2];
#pragma unroll
            for (int jp = 0; jp < 2; jp++) {
                uint32_t ba = sb + 20480 + bt_loff4 + ks * (16 * 272)
                              + (nw * 32 + jp * 16) * 2;
                uint32_t r[4];
                ldsm_x4t(r, ba);
                bh[2 * jp][0] = r[0]; bh[2 * jp][1] = r[1];
                bh[2 * jp + 1][0] = r[2]; bh[2 * jp + 1][1] = r[3];
            }
#pragma unroll
            for (int i = 0; i < 2; i++) {
                uint32_t aa = sb + a_wbase + i * (16 * 80) + ks * 32;
                uint32_t ah[4], al[4];
                ldsm_x4(ah, aa);
                ldsm_x4(al, aa + 10240);
#pragma unroll
                for (int j = 0; j < 4; j++) {
                    mma16816f(acc[i][j], ah, bh[j]);
                    mma16816f(acc[i][j], al, bh[j]);
                }
            }
        }
        if (it + 2 < T) loadG(it + 2, (cur + 2 >= 3) ? cur - 1 : cur + 2);
        cur = (cur + 1 == 3) ? 0 : cur + 1;
    }
    __syncthreads();

    const float* xab = g_xa + (size_t)b * COUT * HW;
    float* Ds = reinterpret_cast<float*>(dsm);
#pragma unroll
    for (int i = 0; i < 2; i++) {
#pragma unroll
        for (int j = 0; j < 4; j++) {
            int c = mw * 32 + i * 16 + lr;
            int col = nw * 32 + j * 8 + lc;
            size_t i0 = (size_t)c * HW + j0g + col;
            size_t i8 = (size_t)(c + 8) * HW + j0g + col;
            float2 x0 = *reinterpret_cast<const float2*>(xab + i0);
            float2 x8 = *reinterpret_cast<const float2*>(xab + i8);
            Ds[col * 129 + c] = acc[i][j][0] + x0.x;
            Ds[(col + 1) * 129 + c] = acc[i][j][1] + x0.y;
            Ds[col * 129 + c + 8] = acc[i][j][2] + x8.x;
            Ds[(col + 1) * 129 + c + 8] = acc[i][j][3] + x8.y;
        }
    }
    __syncthreads();
    {
        int jj = t >> 2, c0q = (t & 3) * 32;
        size_t rowb = ((size_t)b * HW + j0g + jj) * COUT + c0q;
#pragma unroll
        for (int blk = 0; blk < 32; blk += 8) {
            __align__(16) unsigned short h8[8], l8[8];
#pragma unroll
            for (int j = 0; j < 8; j++) {
                float vv = Ds[jj * 129 + c0q + blk + j];
                __nv_bfloat16 h, l; splitf(vv, h, l);
                h8[j] = *reinterpret_cast<unsigned short*>(&h);
                l8[j] = *reinterpret_cast<unsigned short*>(&l);
            }
            *reinterpret_cast<uint4*>(g_oth + rowb + blk) = *reinterpret_cast<uint4*>(h8);
            *reinterpret_cast<uint4*>(g_otl + rowb + blk) = *reinterpret_cast<uint4*>(l8);
        }
    }
}

// ---------------- host launch ----------------
extern "C" void kernel_launch(void* const* d_in, const int* in_sizes, int n_in,
                              void* d_out, int out_size) {
    (void)in_sizes; (void)n_in; (void)out_size;
    const float* x       = (const float*)d_in[0];
    const float* conv1_w = (const float*)d_in[1];
    const float* conv1_b = (const float*)d_in[2];
    const float* conv2_w = (const float*)d_in[3];
    const float* conv2_b = (const float*)d_in[4];
    const float* cw_w1   = (const float*)d_in[5];
    const float* cw_b1   = (const float*)d_in[6];
    const float* cw_ln_g = (const float*)d_in[7];
    const float* cw_ln_b = (const float*)d_in[8];
    const float* cw_w2   = (const float*)d_in[9];
    const float* cw_b2   = (const float*)d_in[10];
    const float* aspp0_w = (const float*)d_in[11];
    const float* aspp0_g = (const float*)d_in[12];
    const float* aspp0_b = (const float*)d_in[13];
    const float* aspp1_w = (const float*)d_in[14];
    const float* aspp1_g = (const float*)d_in[15];
    const float* aspp1_b = (const float*)d_in[16];
    const float* aspp2_w = (const float*)d_in[17];
    const float* aspp2_g = (const float*)d_in[18];
    const float* aspp2_b = (const float*)d_in[19];
    const float* aspp3_w = (const float*)d_in[20];
    const float* aspp3_g = (const float*)d_in[21];
    const float* aspp3_b = (const float*)d_in[22];
    const float* asppp_w = (const float*)d_in[23];
    const float* asppp_g = (const float*)d_in[24];
    const float* asppp_b = (const float*)d_in[25];
    const float* proj_w  = (const float*)d_in[26];
    const float* proj_g  = (const float*)d_in[27];
    const float* proj_b  = (const float*)d_in[28];

    void* pv;
    __nv_bfloat16 *p_xth, *p_xtl, *p_xTh, *p_xTl, *p_cth, *p_ctl, *p_pth, *p_ptl;
    __nv_bfloat16 *p_w3h, *p_w3l, *p_a0h, *p_a0l, *p_pjh, *p_pjl, *p_c2h, *p_c2l, *p_c1h, *p_c1l;
    __nv_bfloat16 *p_oth, *p_otl;
    cudaGetSymbolAddress(&pv, g_xth);  p_xth  = (__nv_bfloat16*)pv;
    cudaGetSymbolAddress(&pv, g_xtl);  p_xtl  = (__nv_bfloat16*)pv;
    cudaGetSymbolAddress(&pv, g_xTh);  p_xTh  = (__nv_bfloat16*)pv;
    cudaGetSymbolAddress(&pv, g_xTl);  p_xTl  = (__nv_bfloat16*)pv;
    cudaGetSymbolAddress(&pv, g_cth);  p_cth  = (__nv_bfloat16*)pv;
    cudaGetSymbolAddress(&pv, g_ctl);  p_ctl  = (__nv_bfloat16*)pv;
    cudaGetSymbolAddress(&pv, g_pth);  p_pth  = (__nv_bfloat16*)pv;
    cudaGetSymbolAddress(&pv, g_ptl);  p_ptl  = (__nv_bfloat16*)pv;
    cudaGetSymbolAddress(&pv, g_w3h);  p_w3h  = (__nv_bfloat16*)pv;
    cudaGetSymbolAddress(&pv, g_w3l);  p_w3l  = (__nv_bfloat16*)pv;
    cudaGetSymbolAddress(&pv, g_a0h);  p_a0h  = (__nv_bfloat16*)pv;
    cudaGetSymbolAddress(&pv, g_a0l);  p_a0l  = (__nv_bfloat16*)pv;
    cudaGetSymbolAddress(&pv, g_pjh);  p_pjh  = (__nv_bfloat16*)pv;
    cudaGetSymbolAddress(&pv, g_pjl);  p_pjl  = (__nv_bfloat16*)pv;
    cudaGetSymbolAddress(&pv, g_c2h);  p_c2h  = (__nv_bfloat16*)pv;
    cudaGetSymbolAddress(&pv, g_c2l);  p_c2l  = (__nv_bfloat16*)pv;
    cudaGetSymbolAddress(&pv, g_c1h);  p_c1h  = (__nv_bfloat16*)pv;
    cudaGetSymbolAddress(&pv, g_c1l);  p_c1l  = (__nv_bfloat16*)pv;
    cudaGetSymbolAddress(&pv, g_oth);  p_oth  = (__nv_bfloat16*)pv;
    cudaGetSymbolAddress(&pv, g_otl);  p_otl  = (__nv_bfloat16*)pv;

    const int TRI_SMEM = 184320;
    const int C1_SMEM = 122880;
    const int SG_SMEM = 132096;   // max(3x30720, Ds 256x129x4)
    const int LG_SMEM = 87552;    // 3x29184 (Ds 128x129x4 = 66048 aliases)
    cudaFuncSetAttribute(k_aspp, cudaFuncAttributeMaxDynamicSharedMemorySize, TRI_SMEM);
    cudaFuncSetAttribute(k_hgemm<1>, cudaFuncAttributeMaxDynamicSharedMemorySize, TRI_SMEM);
    cudaFuncSetAttribute(k_hgemm<2>, cudaFuncAttributeMaxDynamicSharedMemorySize, TRI_SMEM);
    cudaFuncSetAttribute(k_conv1, cudaFuncAttributeMaxDynamicSharedMemorySize, C1_SMEM);
    cudaFuncSetAttribute(k_sgemm2, cudaFuncAttributeMaxDynamicSharedMemorySize, SG_SMEM);
    cudaFuncSetAttribute(k_lgemm2, cudaFuncAttributeMaxDynamicSharedMemorySize, LG_SMEM);

    dim3 gh(HW / 128, BATCH);

    AsppArgs aa;
    aa.wh[0] = p_a0h; aa.wl[0] = p_a0l; aa.g[0] = aspp0_g; aa.bt[0] = aspp0_b;
    aa.dil[0] = 0; aa.coff[0] = 0;
    aa.wh[1] = p_w3h; aa.wl[1] = p_w3l; aa.g[1] = aspp1_g; aa.bt[1] = aspp1_b;
    aa.dil[1] = 3; aa.coff[1] = 256;
    aa.wh[2] = p_w3h + 9 * 65536; aa.wl[2] = p_w3l + 9 * 65536;
    aa.g[2] = aspp2_g; aa.bt[2] = aspp2_b; aa.dil[2] = 6; aa.coff[2] = 512;
    aa.wh[3] = p_w3h + 18 * 65536; aa.wl[3] = p_w3l + 18 * 65536;
    aa.g[3] = aspp3_g; aa.bt[3] = aspp3_b; aa.dil[3] = 9; aa.coff[3] = 768;

    k_prep<<<3584, 256>>>(aspp1_w, aspp2_w, aspp3_w, aspp0_w, proj_w, conv2_w, conv1_w, x);
    k_cw<<<BATCH, 256>>>(cw_w1, cw_b1, cw_ln_g, cw_ln_b, cw_w2, cw_b2,
                         asppp_w, asppp_g, asppp_b);
    k_xcsplit<<<dim3(128, 8, BATCH), 256>>>(x);
    // merged ASPP branches (proven config)
    k_aspp<<<dim3(HW / 128, BATCH, 4), 512, TRI_SMEM>>>(aa, p_xth, p_xtl, p_cth, p_ctl);
    k_bp_cat<<<dim3(128, BATCH), 256>>>();
    // proj (K=1280) -> projT bf16 split
    k_hgemm<1><<<gh, 512, TRI_SMEM>>>(p_pjh, p_pjl, p_cth, p_ctl,
                                      proj_g, proj_b, nullptr, p_pth, p_ptl, CIN, 5 * CIN);
    // conv1 x2 merged (z: 0=x1 from xT -> fp16 outs, 1=xa from projT)
    k_conv1<<<dim3(HW / 128, BATCH, 2), 512, C1_SMEM>>>(p_c1h, p_c1l,
                                                        p_xTh, p_xTl, p_pth, p_ptl, conv1_b);
    // attention (fp16 1-pass S, fp16 softmax, fp16 2-pass L)
    k_sgemm2<<<dim3(HW / 128, HW / 256, BATCH), 512, SG_SMEM>>>();
    k_softmax<<<BATCH * HW, 256>>>();
    k_lgemm2<<<dim3(HW / 128, BATCH), 512, LG_SMEM>>>();
    // conv2 (HMMA bias epilogue, K=128)
    k_hgemm<2><<<gh, 512, TRI_SMEM>>>(p_c2h, p_c2l, p_oth, p_otl,
                                      conv2_b, conv2_b, (float*)d_out, nullptr, nullptr,
                                      0, COUT);
}

// round 17
// speedup vs baseline: 1.7461x; 1.1466x over previous
#include <cuda_runtime.h>
#include <cuda_bf16.h>
#include <cuda_fp16.h>
#include <math.h>
#include <stdint.h>

#define BATCH 4
#define CIN 256
#define COUT 128
#define HH 64
#define WW 64
#define HW 4096

typedef unsigned long long ull;

// ---------------- scratch (static device globals; no allocs) ----------------
__device__ float g_xa[BATCH * COUT * HW];
__device__ float g_S[(size_t)BATCH * HW * HW];
__device__ float g_avg[BATCH * CIN];
__device__ float g_mx[BATCH * CIN];
__device__ float g_s[BATCH * CIN];
__device__ float g_bp[BATCH * CIN];
// fp16 activations (single) + fp16 hi/lo weights
__device__ __half g_xtf[BATCH * HW * CIN];            // xcT fp16 [b][hw][c]
__device__ __half g_xTf[BATCH * HW * CIN];            // raw xT fp16
__device__ __half g_ctf[(size_t)BATCH * HW * 5 * CIN];// catT fp16 [b][hw][1280]
__device__ __half g_ptf[BATCH * HW * CIN];            // projT fp16
__device__ __half g_w3h[3 * 9 * CIN * CIN];           // conv3 w fp16 hi [conv][tap][m][c]
__device__ __half g_w3l[3 * 9 * CIN * CIN];
__device__ __half g_a0h[CIN * CIN];
__device__ __half g_a0l[CIN * CIN];
__device__ __half g_pjh[CIN * 5 * CIN];
__device__ __half g_pjl[CIN * 5 * CIN];
__device__ __half g_c2h[CIN * COUT];
__device__ __half g_c2l[CIN * COUT];
__device__ __half g_c1h[COUT * CIN];
__device__ __half g_c1l[COUT * CIN];
// attention operands (fp16)
__device__ __half g_x1tf[BATCH * HW * COUT];      // x1T fp16 [b][hw][c]
__device__ __half g_xatf[BATCH * HW * COUT];      // xaT fp16
__device__ __half g_x1fh[BATCH * COUT * HW];      // x1 straight fp16 hi [b][c][hw]
__device__ __half g_x1fl[BATCH * COUT * HW];
__device__ __half g_Af[(size_t)BATCH * HW * HW];  // softmax probs fp16
__device__ __half g_otf[BATCH * HW * COUT];       // OT fp16 [b][hw][c]

__device__ __forceinline__ float gelu_f(float x) {
    return 0.5f * x * (1.0f + erff(x * 0.70710678118654752440f));
}
__device__ __forceinline__ void splitf16(float v, __half& h, __half& l) {
    h = __float2half(v);
    l = __float2half(v - __half2float(h));
}

// ---------------- HMMA m16n8k16 fp16 ----------------
__device__ __forceinline__ void mma16816f(float* d, const uint32_t* a, const uint32_t* b) {
    asm volatile(
        "mma.sync.aligned.m16n8k16.row.col.f32.f16.f16.f32 "
        "{%0,%1,%2,%3}, {%4,%5,%6,%7}, {%8,%9}, {%0,%1,%2,%3};"
        : "+f"(d[0]), "+f"(d[1]), "+f"(d[2]), "+f"(d[3])
        : "r"(a[0]), "r"(a[1]), "r"(a[2]), "r"(a[3]), "r"(b[0]), "r"(b[1]));
}
__device__ __forceinline__ void ldsm_x4(uint32_t* r, uint32_t addr) {
    asm volatile("ldmatrix.sync.aligned.m8n8.x4.shared.b16 {%0,%1,%2,%3}, [%4];"
                 : "=r"(r[0]), "=r"(r[1]), "=r"(r[2]), "=r"(r[3]) : "r"(addr));
}
__device__ __forceinline__ void ldsm_x4t(uint32_t* r, uint32_t addr) {
    asm volatile("ldmatrix.sync.aligned.m8n8.x4.trans.shared.b16 {%0,%1,%2,%3}, [%4];"
                 : "=r"(r[0]), "=r"(r[1]), "=r"(r[2]), "=r"(r[3]) : "r"(addr));
}

// ---------------- cp.async helpers ----------------
__device__ __forceinline__ void cp16(uint32_t d, const void* s, int ssz) {
    asm volatile("cp.async.ca.shared.global [%0], [%1], 16, %2;"
                 :: "r"(d), "l"(s), "r"(ssz) : "memory");
}
#define CP_COMMIT() asm volatile("cp.async.commit_group;" ::: "memory")
#define CP_WAIT1()  asm volatile("cp.async.wait_group 1;" ::: "memory")
#define CP_WAIT0()  asm volatile("cp.async.wait_group 0;" ::: "memory")

// ---------------- prep: fp16 weight splits + per-(b,c) stats ----------------
__global__ void k_prep(const float* __restrict__ w1, const float* __restrict__ w2,
                       const float* __restrict__ w3, const float* __restrict__ a0,
                       const float* __restrict__ pj, const float* __restrict__ c2,
                       const float* __restrict__ c1, const float* __restrict__ x) {
    if (blockIdx.x < 2560) {
        int e = blockIdx.x * 256 + threadIdx.x;
        if (e < 196608) {
            const float* srcs[3] = { w1, w2, w3 };
            int conv = e >> 16, mc = e & 65535, m = mc >> 8, c = mc & 255;
            const float* src = srcs[conv] + (size_t)m * 2304 + (size_t)c * 9;
            size_t dbase = (size_t)conv * 9 * 65536 + (size_t)m * 256 + c;
#pragma unroll
            for (int tap = 0; tap < 9; tap++) {
                __half h, l; splitf16(src[tap], h, l);
                g_w3h[dbase + (size_t)tap * 65536] = h;
                g_w3l[dbase + (size_t)tap * 65536] = l;
            }
        } else if (e < 262144) {
            int i = e - 196608;
            __half h, l; splitf16(a0[i], h, l);
            g_a0h[i] = h; g_a0l[i] = l;
        } else if (e < 589824) {
            int i = e - 262144;
            __half h, l; splitf16(pj[i], h, l);
            g_pjh[i] = h; g_pjl[i] = l;
        } else if (e < 622592) {
            int i = e - 589824;
            __half h, l; splitf16(c2[i], h, l);
            g_c2h[i] = h; g_c2l[i] = l;
        } else if (e < 655360) {
            int i = e - 622592;
            __half h, l; splitf16(c1[i], h, l);
            g_c1h[i] = h; g_c1l[i] = l;
        }
    } else {
        int bc = blockIdx.x - 2560;
        const float* p = x + (size_t)bc * HW;
        int t = threadIdx.x;
        float s = 0.f, m = -1e30f;
        for (int i = t; i < HW; i += 256) { float v = p[i]; s += v; m = fmaxf(m, v); }
        __shared__ float ss[256], sm[256];
        ss[t] = s; sm[t] = m; __syncthreads();
        for (int o = 128; o > 0; o >>= 1) {
            if (t < o) { ss[t] += ss[t + o]; sm[t] = fmaxf(sm[t], sm[t + o]); }
            __syncthreads();
        }
        if (t == 0) { g_avg[bc] = ss[0] * (1.f / HW); g_mx[bc] = sm[0]; }
    }
}

// ---------------- channel weighting MLP + global-pool ASPP branch ----------------
__global__ void k_cw(const float* __restrict__ w1, const float* __restrict__ bb1,
                     const float* __restrict__ lg, const float* __restrict__ lb,
                     const float* __restrict__ w2, const float* __restrict__ bb2,
                     const float* __restrict__ apw, const float* __restrict__ apg,
                     const float* __restrict__ apb) {
    int b = blockIdx.x, t = threadIdx.x;
    __shared__ float o[CIN];
    __shared__ float h[COUT];
    __shared__ float red[256];
    __shared__ float gp[CIN];
    float avg = g_avg[b * CIN + t], mx = g_mx[b * CIN + t];
    o[t] = fabsf(avg - mx) * avg;
    __syncthreads();
    float hv = 0.f;
    if (t < COUT) {
        hv = bb1[t];
        const float* wr = w1 + t * CIN;
        for (int i = 0; i < CIN; i++) hv = fmaf(o[i], wr[i], hv);
    }
    red[t] = (t < COUT) ? hv : 0.f; __syncthreads();
    for (int s = 128; s > 0; s >>= 1) { if (t < s) red[t] += red[t + s]; __syncthreads(); }
    float mu = red[0] * (1.f / COUT); __syncthreads();
    float dv = (t < COUT) ? (hv - mu) : 0.f;
    red[t] = dv * dv; __syncthreads();
    for (int s = 128; s > 0; s >>= 1) { if (t < s) red[t] += red[t + s]; __syncthreads(); }
    float var = red[0] * (1.f / COUT); __syncthreads();
    if (t < COUT) h[t] = lg[t] * ((hv - mu) * rsqrtf(var + 1e-5f)) + lb[t];
    __syncthreads();
    float sv = bb2[t];
    const float* wr2 = w2 + t * COUT;
    for (int j = 0; j < COUT; j++) sv = fmaf(h[j], wr2[j], sv);
    float sig = 1.f / (1.f + expf(-sv));
    g_s[b * CIN + t] = sig;
    gp[t] = (1.f + sig) * avg;
    __syncthreads();
    float v = 0.f;
    const float* ar = apw + t * CIN;
    for (int i = 0; i < CIN; i++) v = fmaf(ar[i], gp[i], v);
    red[t] = v; __syncthreads();
    for (int s = 128; s > 0; s >>= 1) { if (t < s) red[t] += red[t + s]; __syncthreads(); }
    float mu2 = red[0] * (1.f / CIN); __syncthreads();
    float d2 = v - mu2; red[t] = d2 * d2; __syncthreads();
    for (int s = 128; s > 0; s >>= 1) { if (t < s) red[t] += red[t + s]; __syncthreads(); }
    float var2 = red[0] * (1.f / CIN); __syncthreads();
    float z = apg[t] * ((v - mu2) * rsqrtf(var2 + 1e-6f)) + apb[t];
    g_bp[b * CIN + t] = gelu_f(z);
}

// ---------------- xT / xcT split -> single fp16 ----------------
__global__ void k_xcsplit(const float* __restrict__ x) {
    __shared__ float tile[32][33];
    int b = blockIdx.z, c0 = blockIdx.y * 32, h0 = blockIdx.x * 32;
    int t = threadIdx.x;
    const float* xb = x + ((size_t)b * CIN + c0) * HW + h0;
#pragma unroll
    for (int i = 0; i < 4; i++) {
        int r = (t >> 5) + 8 * i;
        tile[r][t & 31] = xb[(size_t)r * HW + (t & 31)];
    }
    __syncthreads();
#pragma unroll
    for (int i = 0; i < 4; i++) {
        int hr = (t >> 5) + 8 * i, cc = t & 31;
        float vr = tile[cc][hr];
        size_t idx = ((size_t)b * HW + h0 + hr) * CIN + c0 + cc;
        g_xTf[idx] = __float2half(vr);
        g_xtf[idx] = __float2half(vr * (1.f + g_s[b * CIN + c0 + cc]));
    }
}

// ---------------- bp broadcast into catT channels [1024,1280) ----------------
__global__ void k_bp_cat() {
    int b = blockIdx.y, h0 = blockIdx.x * 32;
    int c = threadIdx.x;
    __half v = __float2half(g_bp[b * CIN + c]);
    for (int r = 0; r < 32; r++) {
        size_t idx = ((size_t)b * HW + h0 + r) * 1280 + 1024 + c;
        g_ctf[idx] = v;
    }
}

struct AsppArgs {
    const __half* wh[4];
    const __half* wl[4];
    const float* g[4];
    const float* bt[4];
    int dil[4];
    int coff[4];
};

// ---------------- merged ASPP: 256x128 tile, 512 thr, tri-buffer, fp16 2-pass -------
// Per buf (51200B): Ah 0 (256x80), Al 20480, B 40960 (128x80).
__global__ void __launch_bounds__(512, 1) k_aspp(
    AsppArgs A_, const __half* __restrict__ I,
    __half* __restrict__ ctf) {
    extern __shared__ __align__(16) char dsm[];
    __shared__ int s_tapn, s_tp[9], s_dy[9], s_dx[9];
    __shared__ float sgam[256], sbet[256], smean[128], srstd[128];
    __shared__ float red4[4][128];

    const int br = blockIdx.z, b = blockIdx.y, y = blockIdx.x;
    const int t = threadIdx.x, wid = t >> 5, lane = t & 31;
    const int mw = wid >> 2, nw = wid & 3;
    const uint32_t sbase = (uint32_t)__cvta_generic_to_shared(dsm);
    const __half* Whi = A_.wh[br];
    const __half* Wlo = A_.wl[br];
    const int dil = A_.dil[br], coff = A_.coff[br];

    if (t == 0) {
        if (dil == 0) {
            s_tapn = 1; s_tp[0] = 0; s_dy[0] = 0; s_dx[0] = 0;
        } else {
            int n = 0;
            for (int tap = 0; tap < 9; tap++) {
                int dy = (tap / 3 - 1) * dil;
                int y0 = y * 2 + dy, y1 = y * 2 + 1 + dy;
                if ((unsigned)y0 < 64u || (unsigned)y1 < 64u) {
                    s_tp[n] = tap; s_dy[n] = dy; s_dx[n] = (tap % 3 - 1) * dil; n++;
                }
            }
            s_tapn = n;
        }
    }
    if (t < 256) { sgam[t] = A_.g[br][t]; sbet[t] = A_.bt[br][t]; }
    __syncthreads();

    const int T = s_tapn * 8;
    const __half* Ib = I + (size_t)b * HW * CIN;

    float acc[4][4][4];
#pragma unroll
    for (int i = 0; i < 4; i++)
#pragma unroll
        for (int j = 0; j < 4; j++)
#pragma unroll
            for (int r = 0; r < 4; r++) acc[i][j][r] = 0.f;

    auto loadG = [&](int it, int buf) {
        int tap_i = it >> 3;
        int kc = (it & 7) * 32;
        uint32_t base = sbase + buf * 51200;
        int arow = t >> 1, ak = (t & 1) * 16;
        int grow = s_tp[tap_i] * 256 + arow;
        const __half* ah = Whi + (size_t)grow * CIN + kc + ak;
        const __half* al = Wlo + (size_t)grow * CIN + kc + ak;
        uint32_t da = base + arow * 80 + ak * 2;
        cp16(da, ah, 16);
        cp16(da + 16, ah + 8, 16);
        cp16(da + 20480, al, 16);
        cp16(da + 20480 + 16, al + 8, 16);
        int n = t >> 2, q = t & 3;
        int hw; int ok = 16;
        int yy = y * 2 + (n >> 6) + s_dy[tap_i];
        int xx = (n & 63) + s_dx[tap_i];
        if ((unsigned)yy < 64u && (unsigned)xx < 64u) hw = yy * 64 + xx;
        else { hw = 0; ok = (dil == 0) ? 16 : 0; }
        if (dil == 0) hw = y * 128 + n;
        cp16(base + 40960 + n * 80 + q * 16, Ib + (size_t)hw * CIN + kc + q * 8, ok);
        CP_COMMIT();
    };

    loadG(0, 0);
    if (T > 1) loadG(1, 1);

    const int lr = lane >> 2, lc = 2 * (lane & 3);
    const uint32_t a_loff = (uint32_t)(((lane & 7) + ((lane >> 3) & 1) * 8) * 80
                                       + (lane >> 4) * 16);
    const uint32_t b_loff4 = (uint32_t)(((lane & 7) + ((lane >> 4) & 1) * 8) * 80
                                        + ((lane >> 3) & 1) * 16);
    const uint32_t a_wbase = (uint32_t)(mw * 64 * 80) + a_loff;
    const uint32_t b_wbase = 40960u + (uint32_t)(nw * 32 * 80) + b_loff4;

    int cur = 0;
    for (int it = 0; it < T; ++it) {
        if (it + 1 < T) CP_WAIT1(); else CP_WAIT0();
        __syncthreads();
        uint32_t sb = sbase + cur * 51200;
#pragma unroll
        for (int ks = 0; ks < 2; ks++) {
            uint32_t kboff = ks * 32;
            uint32_t bh[4][2];
#pragma unroll
            for (int jp = 0; jp < 2; jp++) {
                uint32_t ba = sb + b_wbase + jp * (16 * 80) + kboff;
                uint32_t r[4];
                ldsm_x4(r, ba);
                bh[2 * jp][0] = r[0]; bh[2 * jp][1] = r[1];
                bh[2 * jp + 1][0] = r[2]; bh[2 * jp + 1][1] = r[3];
            }
#pragma unroll
            for (int i = 0; i < 4; i++) {
                uint32_t aa = sb + a_wbase + i * (16 * 80) + kboff;
                uint32_t ah[4], al[4];
                ldsm_x4(ah, aa);
                ldsm_x4(al, aa + 20480);
#pragma unroll
                for (int j = 0; j < 4; j++) {
                    mma16816f(acc[i][j], ah, bh[j]);
                    mma16816f(acc[i][j], al, bh[j]);
                }
            }
        }
        if (it + 2 < T) loadG(it + 2, (cur + 2 >= 3) ? cur - 1 : cur + 2);
        cur = (cur + 1 == 3) ? 0 : cur + 1;
    }
    __syncthreads();

    float* Ds = reinterpret_cast<float*>(dsm);
#pragma unroll
    for (int i = 0; i < 4; i++) {
        int r0 = mw * 64 + i * 16 + lr;
#pragma unroll
        for (int j = 0; j < 4; j++) {
            int c = nw * 32 + j * 8 + lc;
            Ds[r0 * 129 + c] = acc[i][j][0];
            Ds[r0 * 129 + c + 1] = acc[i][j][1];
            Ds[(r0 + 8) * 129 + c] = acc[i][j][2];
            Ds[(r0 + 8) * 129 + c + 1] = acc[i][j][3];
        }
    }
    __syncthreads();
    {
        int n = t & 127, p = t >> 7;
        float s = 0.f;
        for (int mm = p * 64; mm < p * 64 + 64; mm++) s += Ds[mm * 129 + n];
        red4[p][n] = s;
        __syncthreads();
        if (t < 128)
            smean[t] = (red4[0][t] + red4[1][t] + red4[2][t] + red4[3][t]) * (1.f / 256.f);
        __syncthreads();
        float mu = smean[n];
        s = 0.f;
        for (int mm = p * 64; mm < p * 64 + 64; mm++) {
            float d = Ds[mm * 129 + n] - mu; s += d * d;
        }
        red4[p][n] = s;
        __syncthreads();
        if (t < 128)
            srstd[t] = rsqrtf((red4[0][t] + red4[1][t] + red4[2][t] + red4[3][t]) * (1.f / 256.f) + 1e-6f);
        __syncthreads();
    }
    {
        int n2 = t >> 2, m0q = (t & 3) * 64;
        float mu = smean[n2], rs = srstd[n2];
        size_t rowb = ((size_t)b * HW + y * 128 + n2) * 1280 + coff + m0q;
#pragma unroll
        for (int blk = 0; blk < 64; blk += 8) {
            __align__(16) unsigned short h8[8];
#pragma unroll
            for (int j = 0; j < 8; j++) {
                int m = m0q + blk + j;
                __half h = __float2half(
                    gelu_f((Ds[m * 129 + n2] - mu) * rs * sgam[m] + sbet[m]));
                h8[j] = *reinterpret_cast<unsigned short*>(&h);
            }
            *reinterpret_cast<uint4*>(ctf + rowb + blk) = *reinterpret_cast<uint4*>(h8);
        }
    }
}

// ---------------- HMMA GEMM M=256, fp16 2-pass (proj EPI1 / conv2 EPI2) ----------
template <int EPI>
__global__ void __launch_bounds__(512, 1) k_hgemm(
    const __half* __restrict__ Whi, const __half* __restrict__ Wlo,
    const __half* __restrict__ I,
    const float* __restrict__ gam, const float* __restrict__ bet,
    float* __restrict__ outF, __half* __restrict__ btf,
    int ostride, int Kc) {
    extern __shared__ __align__(16) char dsm[];
    __shared__ float sgam[256], sbet[256], smean[128], srstd[128];
    __shared__ float red4[4][128];

    const int b = blockIdx.y, y = blockIdx.x;
    const int t = threadIdx.x, wid = t >> 5, lane = t & 31;
    const int mw = wid >> 2, nw = wid & 3;
    const uint32_t sbase = (uint32_t)__cvta_generic_to_shared(dsm);

    if (t < 256) { sgam[t] = gam[t]; sbet[t] = bet[t]; }
    __syncthreads();

    const int T = Kc / 32;
    const __half* Ib = I + (size_t)b * HW * Kc;

    float acc[4][4][4];
#pragma unroll
    for (int i = 0; i < 4; i++)
#pragma unroll
        for (int j = 0; j < 4; j++)
#pragma unroll
            for (int r = 0; r < 4; r++) acc[i][j][r] = 0.f;

    auto loadG = [&](int it, int buf) {
        int kc = it * 32;
        uint32_t base = sbase + buf * 51200;
        int arow = t >> 1, ak = (t & 1) * 16;
        const __half* ah = Whi + (size_t)arow * Kc + kc + ak;
        const __half* al = Wlo + (size_t)arow * Kc + kc + ak;
        uint32_t da = base + arow * 80 + ak * 2;
        cp16(da, ah, 16);
        cp16(da + 16, ah + 8, 16);
        cp16(da + 20480, al, 16);
        cp16(da + 20480 + 16, al + 8, 16);
        int n = t >> 2, q = t & 3;
        int hw = y * 128 + n;
        cp16(base + 40960 + n * 80 + q * 16, Ib + (size_t)hw * Kc + kc + q * 8, 16);
        CP_COMMIT();
    };

    loadG(0, 0);
    if (T > 1) loadG(1, 1);

    const int lr = lane >> 2, lc = 2 * (lane & 3);
    const uint32_t a_loff = (uint32_t)(((lane & 7) + ((lane >> 3) & 1) * 8) * 80
                                       + (lane >> 4) * 16);
    const uint32_t b_loff4 = (uint32_t)(((lane & 7) + ((lane >> 4) & 1) * 8) * 80
                                        + ((lane >> 3) & 1) * 16);
    const uint32_t a_wbase = (uint32_t)(mw * 64 * 80) + a_loff;
    const uint32_t b_wbase = 40960u + (uint32_t)(nw * 32 * 80) + b_loff4;

    int cur = 0;
    for (int it = 0; it < T; ++it) {
        if (it + 1 < T) CP_WAIT1(); else CP_WAIT0();
        __syncthreads();
        uint32_t sb = sbase + cur * 51200;
#pragma unroll
        for (int ks = 0; ks < 2; ks++) {
            uint32_t kboff = ks * 32;
            uint32_t bh[4][2];
#pragma unroll
            for (int jp = 0; jp < 2; jp++) {
                uint32_t ba = sb + b_wbase + jp * (16 * 80) + kboff;
                uint32_t r[4];
                ldsm_x4(r, ba);
                bh[2 * jp][0] = r[0]; bh[2 * jp][1] = r[1];
                bh[2 * jp + 1][0] = r[2]; bh[2 * jp + 1][1] = r[3];
            }
#pragma unroll
            for (int i = 0; i < 4; i++) {
                uint32_t aa = sb + a_wbase + i * (16 * 80) + kboff;
                uint32_t ah[4], al[4];
                ldsm_x4(ah, aa);
                ldsm_x4(al, aa + 20480);
#pragma unroll
                for (int j = 0; j < 4; j++) {
                    mma16816f(acc[i][j], ah, bh[j]);
                    mma16816f(acc[i][j], al, bh[j]);
                }
            }
        }
        if (it + 2 < T) loadG(it + 2, (cur + 2 >= 3) ? cur - 1 : cur + 2);
        cur = (cur + 1 == 3) ? 0 : cur + 1;
    }
    __syncthreads();

    float* Ds = reinterpret_cast<float*>(dsm);
#pragma unroll
    for (int i = 0; i < 4; i++) {
        int r0 = mw * 64 + i * 16 + lr;
#pragma unroll
        for (int j = 0; j < 4; j++) {
            int c = nw * 32 + j * 8 + lc;
            Ds[r0 * 129 + c] = acc[i][j][0];
            Ds[r0 * 129 + c + 1] = acc[i][j][1];
            Ds[(r0 + 8) * 129 + c] = acc[i][j][2];
            Ds[(r0 + 8) * 129 + c + 1] = acc[i][j][3];
        }
    }
    __syncthreads();
    if (EPI == 1) {
        int n = t & 127, p = t >> 7;
        float s = 0.f;
        for (int mm = p * 64; mm < p * 64 + 64; mm++) s += Ds[mm * 129 + n];
        red4[p][n] = s;
        __syncthreads();
        if (t < 128)
            smean[t] = (red4[0][t] + red4[1][t] + red4[2][t] + red4[3][t]) * (1.f / 256.f);
        __syncthreads();
        float mu = smean[n];
        s = 0.f;
        for (int mm = p * 64; mm < p * 64 + 64; mm++) {
            float d = Ds[mm * 129 + n] - mu; s += d * d;
        }
        red4[p][n] = s;
        __syncthreads();
        if (t < 128)
            srstd[t] = rsqrtf((red4[0][t] + red4[1][t] + red4[2][t] + red4[3][t]) * (1.f / 256.f) + 1e-6f);
        __syncthreads();
        int n2 = t >> 2, m0q = (t & 3) * 64;
        float mu2 = smean[n2], rs = srstd[n2];
        size_t rowb = ((size_t)b * HW + y * 128 + n2) * ostride + m0q;
#pragma unroll
        for (int blk = 0; blk < 64; blk += 8) {
            __align__(16) unsigned short h8[8];
#pragma unroll
            for (int j = 0; j < 8; j++) {
                int m = m0q + blk + j;
                __half h = __float2half(
                    gelu_f((Ds[m * 129 + n2] - mu2) * rs * sgam[m] + sbet[m]));
                h8[j] = *reinterpret_cast<unsigned short*>(&h);
            }
            *reinterpret_cast<uint4*>(btf + rowb + blk) = *reinterpret_cast<uint4*>(h8);
        }
    } else {
        int m = t >> 1, nh = (t & 1) * 64;
        float bias = sgam[m];
        size_t ob = ((size_t)b * CIN + m) * HW + y * 128 + nh;
#pragma unroll
        for (int blk = 0; blk < 64; blk += 4) {
            float4 v4;
            float* vp = &v4.x;
#pragma unroll
            for (int j = 0; j < 4; j++) vp[j] = Ds[m * 129 + nh + blk + j] + bias;
            *reinterpret_cast<float4*>(outF + ob + blk) = v4;
        }
    }
}

// ---------------- HMMA conv1 merged, fp16 2-pass: z=0 -> x1, z=1 -> xa --------------
__global__ void __launch_bounds__(512, 1) k_conv1(
    const __half* __restrict__ Whi, const __half* __restrict__ Wlo,
    const __half* __restrict__ I0, const __half* __restrict__ I1,
    const float* __restrict__ bias) {
    extern __shared__ __align__(16) char dsm[];
    __shared__ float sb2[128];
    const int zb = blockIdx.z, b = blockIdx.y, y = blockIdx.x;
    const int t = threadIdx.x, wid = t >> 5, lane = t & 31;
    const int mw = wid >> 2, nw = wid & 3;
    const uint32_t sbase = (uint32_t)__cvta_generic_to_shared(dsm);

    if (t < 128) sb2[t] = bias[t];
    __syncthreads();

    const __half* Ib = (zb ? I1 : I0) + (size_t)b * HW * CIN;

    float acc[2][4][4];
#pragma unroll
    for (int i = 0; i < 2; i++)
#pragma unroll
        for (int j = 0; j < 4; j++)
#pragma unroll
            for (int r = 0; r < 4; r++) acc[i][j][r] = 0.f;

    // per buf (30720B): Ah 0 (128x80), Al 10240, B 20480 (128x80)
    auto loadG = [&](int it, int buf) {
        int kc = it * 32;
        uint32_t base = sbase + buf * 30720;
        int r = t >> 2, q = t & 3;
        cp16(base + r * 80 + q * 16, Whi + (size_t)r * CIN + kc + q * 8, 16);
        cp16(base + 10240 + r * 80 + q * 16, Wlo + (size_t)r * CIN + kc + q * 8, 16);
        int hw = y * 128 + r;
        cp16(base + 20480 + r * 80 + q * 16, Ib + (size_t)hw * CIN + kc + q * 8, 16);
        CP_COMMIT();
    };

    loadG(0, 0);
    loadG(1, 1);

    const int lr = lane >> 2, lc = 2 * (lane & 3);
    const uint32_t a_loff = (uint32_t)(((lane & 7) + ((lane >> 3) & 1) * 8) * 80
                                       + (lane >> 4) * 16);
    const uint32_t b_loff4 = (uint32_t)(((lane & 7) + ((lane >> 4) & 1) * 8) * 80
                                        + ((lane >> 3) & 1) * 16);
    const uint32_t a_wbase = (uint32_t)(mw * 32 * 80) + a_loff;
    const uint32_t b_wbase = 20480u + (uint32_t)(nw * 32 * 80) + b_loff4;

    const int T = CIN / 32;
    int cur = 0;
    for (int it = 0; it < T; ++it) {
        if (it + 1 < T) CP_WAIT1(); else CP_WAIT0();
        __syncthreads();
        uint32_t sb = sbase + cur * 30720;
#pragma unroll
        for (int ks = 0; ks < 2; ks++) {
            uint32_t kboff = ks * 32;
            uint32_t bh[4][2];
#pragma unroll
            for (int jp = 0; jp < 2; jp++) {
                uint32_t ba = sb + b_wbase + jp * (16 * 80) + kboff;
                uint32_t r[4];
                ldsm_x4(r, ba);
                bh[2 * jp][0] = r[0]; bh[2 * jp][1] = r[1];
                bh[2 * jp + 1][0] = r[2]; bh[2 * jp + 1][1] = r[3];
            }
#pragma unroll
            for (int i = 0; i < 2; i++) {
                uint32_t aa = sb + a_wbase + i * (16 * 80) + kboff;
                uint32_t ah[4], al[4];
                ldsm_x4(ah, aa);
                ldsm_x4(al, aa + 10240);
#pragma unroll
                for (int j = 0; j < 4; j++) {
                    mma16816f(acc[i][j], ah, bh[j]);
                    mma16816f(acc[i][j], al, bh[j]);
                }
            }
        }
        if (it + 2 < T) loadG(it + 2, (cur + 2 >= 3) ? cur - 1 : cur + 2);
        cur = (cur + 1 == 3) ? 0 : cur + 1;
    }
    __syncthreads();

    float* Ds = reinterpret_cast<float*>(dsm);
#pragma unroll
    for (int i = 0; i < 2; i++) {
        int r0 = mw * 32 + i * 16 + lr;
#pragma unroll
        for (int j = 0; j < 4; j++) {
            int c = nw * 32 + j * 8 + lc;
            Ds[r0 * 129 + c] = acc[i][j][0] + sb2[r0];
            Ds[r0 * 129 + c + 1] = acc[i][j][1] + sb2[r0];
            Ds[(r0 + 8) * 129 + c] = acc[i][j][2] + sb2[r0 + 8];
            Ds[(r0 + 8) * 129 + c + 1] = acc[i][j][3] + sb2[r0 + 8];
        }
    }
    __syncthreads();
    // transposed single fp16
    {
        int n2 = t >> 2, m0 = (t & 3) * 32;
        __half* th = zb ? g_xatf : g_x1tf;
        size_t rowb = ((size_t)b * HW + y * 128 + n2) * COUT + m0;
#pragma unroll
        for (int blk = 0; blk < 32; blk += 8) {
            __align__(16) unsigned short h8[8];
#pragma unroll
            for (int j = 0; j < 8; j++) {
                __half h = __float2half(Ds[(m0 + blk + j) * 129 + n2]);
                h8[j] = *reinterpret_cast<unsigned short*>(&h);
            }
            *reinterpret_cast<uint4*>(th + rowb + blk) = *reinterpret_cast<uint4*>(h8);
        }
    }
    // straight
    {
        int m = t >> 2, nh = (t & 3) * 32;
        size_t ob = ((size_t)b * COUT + m) * HW + y * 128 + nh;
        if (zb) {
#pragma unroll
            for (int blk = 0; blk < 32; blk += 4) {
                float4 v4;
                float* vp = &v4.x;
#pragma unroll
                for (int j = 0; j < 4; j++) vp[j] = Ds[m * 129 + nh + blk + j];
                *reinterpret_cast<float4*>(g_xa + ob + blk) = v4;
            }
        } else {
#pragma unroll
            for (int blk = 0; blk < 32; blk += 8) {
                __align__(16) unsigned short h8[8], l8[8];
#pragma unroll
                for (int j = 0; j < 8; j++) {
                    __half h, l; splitf16(Ds[m * 129 + nh + blk + j], h, l);
                    h8[j] = *reinterpret_cast<unsigned short*>(&h);
                    l8[j] = *reinterpret_cast<unsigned short*>(&l);
                }
                *reinterpret_cast<uint4*>(g_x1fh + ob + blk) = *reinterpret_cast<uint4*>(h8);
                *reinterpret_cast<uint4*>(g_x1fl + ob + blk) = *reinterpret_cast<uint4*>(l8);
            }
        }
    }
}

// ---------------- HMMA S-GEMM fp16 1-pass: 256(q)x128(p), tri-buffer ----------
__global__ void __launch_bounds__(512, 1) k_sgemm2() {
    extern __shared__ __align__(16) char dsm[];
    const int b = blockIdx.z, q0 = blockIdx.y * 256, p0 = blockIdx.x * 128;
    const int t = threadIdx.x, wid = t >> 5, lane = t & 31;
    const int mw = wid >> 2, nw = wid & 3;
    const uint32_t sbase = (uint32_t)__cvta_generic_to_shared(dsm);
    const __half* Q = g_xatf + (size_t)b * HW * COUT;
    const __half* P = g_x1tf + (size_t)b * HW * COUT;

    float acc[4][4][4];
#pragma unroll
    for (int i = 0; i < 4; i++)
#pragma unroll
        for (int j = 0; j < 4; j++)
#pragma unroll
            for (int r = 0; r < 4; r++) acc[i][j][r] = 0.f;

    auto loadG = [&](int it, int buf) {
        int kc = it * 32;
        uint32_t base = sbase + buf * 30720;
        int arow = t >> 1, ak = (t & 1) * 16;
        const __half* ap = Q + (size_t)(q0 + arow) * COUT + kc + ak;
        uint32_t da = base + arow * 80 + ak * 2;
        cp16(da, ap, 16);
        cp16(da + 16, ap + 8, 16);
        int n = t >> 2, q = t & 3;
        cp16(base + 20480 + n * 80 + q * 16, P + (size_t)(p0 + n) * COUT + kc + q * 8, 16);
        CP_COMMIT();
    };

    loadG(0, 0);
    loadG(1, 1);

    const int lr = lane >> 2, lc = 2 * (lane & 3);
    const uint32_t a_loff = (uint32_t)(((lane & 7) + ((lane >> 3) & 1) * 8) * 80
                                       + (lane >> 4) * 16);
    const uint32_t b_loff4 = (uint32_t)(((lane & 7) + ((lane >> 4) & 1) * 8) * 80
                                        + ((lane >> 3) & 1) * 16);
    const uint32_t a_wbase = (uint32_t)(mw * 64 * 80) + a_loff;
    const uint32_t b_wbase = 20480u + (uint32_t)(nw * 32 * 80) + b_loff4;

    const int T = COUT / 32;
    int cur = 0;
    for (int it = 0; it < T; ++it) {
        if (it + 1 < T) CP_WAIT1(); else CP_WAIT0();
        __syncthreads();
        uint32_t sb = sbase + cur * 30720;
#pragma unroll
        for (int ks = 0; ks < 2; ks++) {
            uint32_t kboff = ks * 32;
            uint32_t bh[4][2];
#pragma unroll
            for (int jp = 0; jp < 2; jp++) {
                uint32_t ba = sb + b_wbase + jp * (16 * 80) + kboff;
                uint32_t r[4];
                ldsm_x4(r, ba);
                bh[2 * jp][0] = r[0]; bh[2 * jp][1] = r[1];
                bh[2 * jp + 1][0] = r[2]; bh[2 * jp + 1][1] = r[3];
            }
#pragma unroll
            for (int i = 0; i < 4; i++) {
                uint32_t aa = sb + a_wbase + i * (16 * 80) + kboff;
                uint32_t ah[4];
                ldsm_x4(ah, aa);
#pragma unroll
                for (int j = 0; j < 4; j++) mma16816f(acc[i][j], ah, bh[j]);
            }
        }
        if (it + 2 < T) loadG(it + 2, (cur + 2 >= 3) ? cur - 1 : cur + 2);
        cur = (cur + 1 == 3) ? 0 : cur + 1;
    }
    __syncthreads();

    float* Ds = reinterpret_cast<float*>(dsm);
#pragma unroll
    for (int i = 0; i < 4; i++) {
        int r0 = mw * 64 + i * 16 + lr;
#pragma unroll
        for (int j = 0; j < 4; j++) {
            int c = nw * 32 + j * 8 + lc;
            Ds[r0 * 129 + c] = acc[i][j][0];
            Ds[r0 * 129 + c + 1] = acc[i][j][1];
            Ds[(r0 + 8) * 129 + c] = acc[i][j][2];
            Ds[(r0 + 8) * 129 + c + 1] = acc[i][j][3];
        }
    }
    __syncthreads();
    {
        const float sc = 1.f / 64.f;
        int m = t >> 1, nh = (t & 1) * 64;
        float* So = g_S + (size_t)b * HW * HW + (size_t)(q0 + m) * HW + p0 + nh;
#pragma unroll
        for (int blk = 0; blk < 64; blk += 4) {
            float4 v4;
            float* vp = &v4.x;
#pragma unroll
            for (int j = 0; j < 4; j++) vp[j] = Ds[m * 129 + nh + blk + j] * sc;
            *reinterpret_cast<float4*>(So + blk) = v4;
        }
    }
}

// ---------------- row softmax; emits fp16 probs ----------------
__global__ void __launch_bounds__(256) k_softmax() {
    const size_t row = blockIdx.x;
    const float* r = g_S + row * (size_t)HW;
    __half* oa = g_Af + row * (size_t)HW;
    __shared__ float buf[HW];
    __shared__ float red[256];
    int t = threadIdx.x;
    float m = -1e30f;
    for (int i = t; i < HW; i += 256) { float v = r[i]; buf[i] = v; m = fmaxf(m, v); }
    red[t] = m; __syncthreads();
    for (int s = 128; s > 0; s >>= 1) { if (t < s) red[t] = fmaxf(red[t], red[t + s]); __syncthreads(); }
    float mx = red[0]; __syncthreads();
    float s = 0.f;
    for (int i = t; i < HW; i += 256) { float e = expf(buf[i] - mx); buf[i] = e; s += e; }
    red[t] = s; __syncthreads();
    for (int o = 128; o > 0; o >>= 1) { if (t < o) red[t] += red[t + o]; __syncthreads(); }
    float inv = 1.f / red[0];
    for (int i = t; i < HW; i += 256) oa[i] = __float2half(buf[i] * inv);
}

// ---------------- HMMA L-GEMM fp16 2-pass: 128(c)x128(j), tri-buffer, trans-B x4 ----
__global__ void __launch_bounds__(512, 1) k_lgemm2() {
    extern __shared__ __align__(16) char dsm[];
    const int b = blockIdx.y, j0g = blockIdx.x * 128;
    const int t = threadIdx.x, wid = t >> 5, lane = t & 31;
    const int mw = wid >> 2, nw = wid & 3;
    const uint32_t sbase = (uint32_t)__cvta_generic_to_shared(dsm);
    const __half* Xh = g_x1fh + (size_t)b * COUT * HW;
    const __half* Xl = g_x1fl + (size_t)b * COUT * HW;
    const __half* Ap = g_Af + (size_t)b * HW * HW;

    float acc[2][4][4];
#pragma unroll
    for (int i = 0; i < 2; i++)
#pragma unroll
        for (int j = 0; j < 4; j++)
#pragma unroll
            for (int r = 0; r < 4; r++) acc[i][j][r] = 0.f;

    auto loadG = [&](int it, int buf) {
        int kc = it * 32;
        uint32_t base = sbase + buf * 29184;
        int c = t >> 2, cq = t & 3;
        uint32_t da = base + c * 80 + cq * 16;
        cp16(da, Xh + (size_t)c * HW + kc + cq * 8, 16);
        cp16(da + 10240, Xl + (size_t)c * HW + kc + cq * 8, 16);
        int k = t >> 4, jt = t & 15;
        cp16(base + 20480 + k * 272 + jt * 16,
             Ap + (size_t)(kc + k) * HW + j0g + jt * 8, 16);
        CP_COMMIT();
    };

    loadG(0, 0);
    loadG(1, 1);

    const int lr = lane >> 2, lc = 2 * (lane & 3);
    const uint32_t a_loff = (uint32_t)(((lane & 7) + ((lane >> 3) & 1) * 8) * 80
                                       + (lane >> 4) * 16);
    const uint32_t a_wbase = (uint32_t)(mw * 32 * 80) + a_loff;
    const uint32_t bt_loff4 = (uint32_t)((lane & 15) * 272 + ((lane >> 4) & 1) * 16);

    const int T = HW / 32;
    int cur = 0;
    for (int it = 0; it < T; ++it) {
        if (it + 1 < T) CP_WAIT1(); else CP_WAIT0();
        __syncthreads();
        uint32_t sb = sbase + cur * 29184;
#pragma unroll
        for (int ks = 0; ks < 2; ks++) {
            uint32_t bh[4][2];
#pragma unroll
            for (int jp = 0; jp < 2; jp++) {
                uint32_t ba = sb + 20480 + bt_loff4 + ks * (16 * 272)
                              + (nw * 32 + jp * 16) * 2;
                uint32_t r[4];
                ldsm_x4t(r, ba);
                bh[2 * jp][0] = r[0]; bh[2 * jp][1] = r[1];
                bh[2 * jp + 1][0] = r[2]; bh[2 * jp + 1][1] = r[3];
            }
#pragma unroll
            for (int i = 0; i < 2; i++) {
                uint32_t aa = sb + a_wbase + i * (16 * 80) + ks * 32;
                uint32_t ah[4], al[4];
                ldsm_x4(ah, aa);
                ldsm_x4(al, aa + 10240);
#pragma unroll
                for (int j = 0; j < 4; j++) {
                    mma16816f(acc[i][j], ah, bh[j]);
                    mma16816f(acc[i][j], al, bh[j]);
                }
            }
        }
        if (it + 2 < T) loadG(it + 2, (cur + 2 >= 3) ? cur - 1 : cur + 2);
        cur = (cur + 1 == 3) ? 0 : cur + 1;
    }
    __syncthreads();

    const float* xab = g_xa + (size_t)b * COUT * HW;
    float* Ds = reinterpret_cast<float*>(dsm);
#pragma unroll
    for (int i = 0; i < 2; i++) {
#pragma unroll
        for (int j = 0; j < 4; j++) {
            int c = mw * 32 + i * 16 + lr;
            int col = nw * 32 + j * 8 + lc;
            size_t i0 = (size_t)c * HW + j0g + col;
            size_t i8 = (size_t)(c + 8) * HW + j0g + col;
            float2 x0 = *reinterpret_cast<const float2*>(xab + i0);
            float2 x8 = *reinterpret_cast<const float2*>(xab + i8);
            Ds[col * 129 + c] = acc[i][j][0] + x0.x;
            Ds[(col + 1) * 129 + c] = acc[i][j][1] + x0.y;
            Ds[col * 129 + c + 8] = acc[i][j][2] + x8.x;
            Ds[(col + 1) * 129 + c + 8] = acc[i][j][3] + x8.y;
        }
    }
    __syncthreads();
    {
        int jj = t >> 2, c0q = (t & 3) * 32;
        size_t rowb = ((size_t)b * HW + j0g + jj) * COUT + c0q;
#pragma unroll
        for (int blk = 0; blk < 32; blk += 8) {
            __align__(16) unsigned short h8[8];
#pragma unroll
            for (int j = 0; j < 8; j++) {
                __half h = __float2half(Ds[jj * 129 + c0q + blk + j]);
                h8[j] = *reinterpret_cast<unsigned short*>(&h);
            }
            *reinterpret_cast<uint4*>(g_otf + rowb + blk) = *reinterpret_cast<uint4*>(h8);
        }
    }
}

// ---------------- host launch ----------------
extern "C" void kernel_launch(void* const* d_in, const int* in_sizes, int n_in,
                              void* d_out, int out_size) {
    (void)in_sizes; (void)n_in; (void)out_size;
    const float* x       = (const float*)d_in[0];
    const float* conv1_w = (const float*)d_in[1];
    const float* conv1_b = (const float*)d_in[2];
    const float* conv2_w = (const float*)d_in[3];
    const float* conv2_b = (const float*)d_in[4];
    const float* cw_w1   = (const float*)d_in[5];
    const float* cw_b1   = (const float*)d_in[6];
    const float* cw_ln_g = (const float*)d_in[7];
    const float* cw_ln_b = (const float*)d_in[8];
    const float* cw_w2   = (const float*)d_in[9];
    const float* cw_b2   = (const float*)d_in[10];
    const float* aspp0_w = (const float*)d_in[11];
    const float* aspp0_g = (const float*)d_in[12];
    const float* aspp0_b = (const float*)d_in[13];
    const float* aspp1_w = (const float*)d_in[14];
    const float* aspp1_g = (const float*)d_in[15];
    const float* aspp1_b = (const float*)d_in[16];
    const float* aspp2_w = (const float*)d_in[17];
    const float* aspp2_g = (const float*)d_in[18];
    const float* aspp2_b = (const float*)d_in[19];
    const float* aspp3_w = (const float*)d_in[20];
    const float* aspp3_g = (const float*)d_in[21];
    const float* aspp3_b = (const float*)d_in[22];
    const float* asppp_w = (const float*)d_in[23];
    const float* asppp_g = (const float*)d_in[24];
    const float* asppp_b = (const float*)d_in[25];
    const float* proj_w  = (const float*)d_in[26];
    const float* proj_g  = (const float*)d_in[27];
    const float* proj_b  = (const float*)d_in[28];

    void* pv;
    __half *p_xtf, *p_xTf, *p_ctf, *p_ptf;
    __half *p_w3h, *p_w3l, *p_a0h, *p_a0l, *p_pjh, *p_pjl, *p_c2h, *p_c2l, *p_c1h, *p_c1l;
    __half *p_otf;
    cudaGetSymbolAddress(&pv, g_xtf);  p_xtf  = (__half*)pv;
    cudaGetSymbolAddress(&pv, g_xTf);  p_xTf  = (__half*)pv;
    cudaGetSymbolAddress(&pv, g_ctf);  p_ctf  = (__half*)pv;
    cudaGetSymbolAddress(&pv, g_ptf);  p_ptf  = (__half*)pv;
    cudaGetSymbolAddress(&pv, g_w3h);  p_w3h  = (__half*)pv;
    cudaGetSymbolAddress(&pv, g_w3l);  p_w3l  = (__half*)pv;
    cudaGetSymbolAddress(&pv, g_a0h);  p_a0h  = (__half*)pv;
    cudaGetSymbolAddress(&pv, g_a0l);  p_a0l  = (__half*)pv;
    cudaGetSymbolAddress(&pv, g_pjh);  p_pjh  = (__half*)pv;
    cudaGetSymbolAddress(&pv, g_pjl);  p_pjl  = (__half*)pv;
    cudaGetSymbolAddress(&pv, g_c2h);  p_c2h  = (__half*)pv;
    cudaGetSymbolAddress(&pv, g_c2l);  p_c2l  = (__half*)pv;
    cudaGetSymbolAddress(&pv, g_c1h);  p_c1h  = (__half*)pv;
    cudaGetSymbolAddress(&pv, g_c1l);  p_c1l  = (__half*)pv;
    cudaGetSymbolAddress(&pv, g_otf);  p_otf  = (__half*)pv;

    const int G_SMEM = 153600;    // 3 x 51200 (epilogue Ds 132096 aliases)
    const int C1_SMEM = 92160;    // 3 x 30720
    const int SG_SMEM = 132096;   // max(3x30720, Ds)
    const int LG_SMEM = 87552;    // 3 x 29184
    cudaFuncSetAttribute(k_aspp, cudaFuncAttributeMaxDynamicSharedMemorySize, G_SMEM);
    cudaFuncSetAttribute(k_hgemm<1>, cudaFuncAttributeMaxDynamicSharedMemorySize, G_SMEM);
    cudaFuncSetAttribute(k_hgemm<2>, cudaFuncAttributeMaxDynamicSharedMemorySize, G_SMEM);
    cudaFuncSetAttribute(k_conv1, cudaFuncAttributeMaxDynamicSharedMemorySize, C1_SMEM);
    cudaFuncSetAttribute(k_sgemm2, cudaFuncAttributeMaxDynamicSharedMemorySize, SG_SMEM);
    cudaFuncSetAttribute(k_lgemm2, cudaFuncAttributeMaxDynamicSharedMemorySize, LG_SMEM);

    dim3 gh(HW / 128, BATCH);

    AsppArgs aa;
    aa.wh[0] = p_a0h; aa.wl[0] = p_a0l; aa.g[0] = aspp0_g; aa.bt[0] = aspp0_b;
    aa.dil[0] = 0; aa.coff[0] = 0;
    aa.wh[1] = p_w3h; aa.wl[1] = p_w3l; aa.g[1] = aspp1_g; aa.bt[1] = aspp1_b;
    aa.dil[1] = 3; aa.coff[1] = 256;
    aa.wh[2] = p_w3h + 9 * 65536; aa.wl[2] = p_w3l + 9 * 65536;
    aa.g[2] = aspp2_g; aa.bt[2] = aspp2_b; aa.dil[2] = 6; aa.coff[2] = 512;
    aa.wh[3] = p_w3h + 18 * 65536; aa.wl[3] = p_w3l + 18 * 65536;
    aa.g[3] = aspp3_g; aa.bt[3] = aspp3_b; aa.dil[3] = 9; aa.coff[3] = 768;

    k_prep<<<3584, 256>>>(aspp1_w, aspp2_w, aspp3_w, aspp0_w, proj_w, conv2_w, conv1_w, x);
    k_cw<<<BATCH, 256>>>(cw_w1, cw_b1, cw_ln_g, cw_ln_b, cw_w2, cw_b2,
                         asppp_w, asppp_g, asppp_b);
    k_xcsplit<<<dim3(128, 8, BATCH), 256>>>(x);
    // merged ASPP branches (fp16 2-pass)
    k_aspp<<<dim3(HW / 128, BATCH, 4), 512, G_SMEM>>>(aa, p_xtf, p_ctf);
    k_bp_cat<<<dim3(128, BATCH), 256>>>();
    // proj (K=1280) -> projT fp16
    k_hgemm<1><<<gh, 512, G_SMEM>>>(p_pjh, p_pjl, p_ctf,
                                    proj_g, proj_b, nullptr, p_ptf, CIN, 5 * CIN);
    // conv1 x2 merged
    k_conv1<<<dim3(HW / 128, BATCH, 2), 512, C1_SMEM>>>(p_c1h, p_c1l,
                                                        p_xTf, p_ptf, conv1_b);
    // attention
    k_sgemm2<<<dim3(HW / 128, HW / 256, BATCH), 512, SG_SMEM>>>();
    k_softmax<<<BATCH * HW, 256>>>();
    k_lgemm2<<<dim3(HW / 128, BATCH), 512, LG_SMEM>>>();
    // conv2 (K=128)
    k_hgemm<2><<<gh, 512, G_SMEM>>>(p_c2h, p_c2l, p_otf,
                                    conv2_b, conv2_b, (float*)d_out, nullptr, 0, COUT);
}